// round 5
// baseline (speedup 1.0000x reference)
#include <cuda_runtime.h>

// ---------------- problem constants ----------------
#define BQ 8
#define DIMC 256
#define CDIMC 512
#define TT 8192
#define NH 8
#define DH 32
#define MLPD 640
#define EPSV 1e-5f

// ---------------- scratch (device globals; no allocation allowed) ----------------
__device__ float g_big [(size_t)BQ * 768 * TT];   // qkv(768) / ckv(512) / mlp-h(640) / o2(256)
__device__ float g_attn[(size_t)BQ * DIMC * TT];  // attn out / q2
__device__ float g_so  [(size_t)BQ * DIMC * TT];  // pre-norm conv outputs
__device__ float g_x   [(size_t)BQ * DIMC * TT];  // running residual x
__device__ float g_wt  [(size_t)BQ * 512 * 512];  // folded transposed weights (max M*K=262144)
__device__ float g_beff[BQ * 1024];
__device__ float g_mu  [BQ * 32];
__device__ float g_rs  [BQ * 32];
__device__ float g_affa[BQ * CDIMC];
__device__ float g_affb[BQ * CDIMC];
__device__ float g_kmax[BQ * 256];
__device__ float g_kinv[BQ * 256];
__device__ float g_ctx [BQ * NH * DH * DH];       // 65536
__device__ float g_ctxp[8 * BQ * NH * DH * DH];   // per-slice partials (deterministic reduce)

// ---------------- group-norm statistics ----------------
// grid = B*32 groups; each group is a CONTIGUOUS chunk of GC*T floats.
__global__ void gn_stats_kernel(const float* __restrict__ x, int GC,
                                float* __restrict__ mu, float* __restrict__ rs)
{
    const size_t n = (size_t)GC * TT;
    const float4* x4 = (const float4*)(x + (size_t)blockIdx.x * n);
    const int n4 = (int)(n >> 2);
    float s = 0.f, sq = 0.f;
    for (int i = threadIdx.x; i < n4; i += 256) {
        float4 v = x4[i];
        s  += (v.x + v.y) + (v.z + v.w);
        sq += v.x*v.x + v.y*v.y + v.z*v.z + v.w*v.w;
    }
    __shared__ float sh1[8], sh2[8];
    int lane = threadIdx.x & 31, w = threadIdx.x >> 5;
    #pragma unroll
    for (int o = 16; o > 0; o >>= 1) {
        s  += __shfl_xor_sync(0xffffffffu, s, o);
        sq += __shfl_xor_sync(0xffffffffu, sq, o);
    }
    if (lane == 0) { sh1[w] = s; sh2[w] = sq; }
    __syncthreads();
    if (threadIdx.x < 8) {
        s = sh1[threadIdx.x]; sq = sh2[threadIdx.x];
        #pragma unroll
        for (int o = 4; o > 0; o >>= 1) {
            s  += __shfl_xor_sync(0xffu, s, o);
            sq += __shfl_xor_sync(0xffu, sq, o);
        }
        if (threadIdx.x == 0) {
            float inv_n = 1.f / (float)n;
            float m = s * inv_n;
            float var = sq * inv_n - m * m;
            mu[blockIdx.x] = m;
            rs[blockIdx.x] = rsqrtf(fmaxf(var, 0.f) + EPSV);
        }
    }
}

// per-channel affine so gn(x) == a[c]*x + bb[c]
__global__ void affine_kernel(const float* __restrict__ g, const float* __restrict__ be,
                              const float* __restrict__ mu, const float* __restrict__ rs,
                              float* __restrict__ a, float* __restrict__ bb, int C)
{
    int b = blockIdx.x;
    int GC = C >> 5;
    for (int c = threadIdx.x; c < C; c += blockDim.x) {
        int grp = c / GC;
        float r = rs[b*32 + grp], m = mu[b*32 + grp];
        float av = g[c] * r;
        a [b*C + c] = av;
        bb[b*C + c] = be[c] - m * av;
    }
}

// ---------------- weight fold: Wt[b][k][m] = W[m][k] * a[b][k] ----------------
__global__ void foldT_kernel(const float* __restrict__ W, const float* __restrict__ a,
                             float* __restrict__ Wt, int M, int K)
{
    __shared__ float tile[32][33];
    int k0 = blockIdx.x * 32, m0 = blockIdx.y * 32, b = blockIdx.z;
    for (int i = threadIdx.y; i < 32; i += 8)
        tile[i][threadIdx.x] = W[(size_t)(m0 + i) * K + k0 + threadIdx.x];
    __syncthreads();
    float* Wo = Wt + (size_t)b * M * K;
    for (int i = threadIdx.y; i < 32; i += 8) {
        int k = k0 + i;
        float av = a ? a[b*K + k] : 1.f;
        Wo[(size_t)k * M + m0 + threadIdx.x] = tile[threadIdx.x][i] * av;
    }
}

// beff[b][m] = sum_k W[m][k]*bb[b][k] + bias[m]
__global__ void beff_kernel(const float* __restrict__ W, const float* __restrict__ bbv,
                            const float* __restrict__ bias, float* __restrict__ beff,
                            int M, int K)
{
    int m = blockIdx.x, b = blockIdx.y;
    float s = 0.f;
    for (int k = threadIdx.x; k < K; k += 128)
        s += W[(size_t)m*K + k] * bbv[b*K + k];
    __shared__ float sh[4];
    int lane = threadIdx.x & 31, w = threadIdx.x >> 5;
    #pragma unroll
    for (int o = 16; o > 0; o >>= 1) s += __shfl_xor_sync(0xffffffffu, s, o);
    if (lane == 0) sh[w] = s;
    __syncthreads();
    if (threadIdx.x == 0)
        beff[(size_t)b*M + m] = sh[0] + sh[1] + sh[2] + sh[3] + (bias ? bias[m] : 0.f);
}

// ---------------- SGEMM:  Y[b][m][n] = sum_k Wt[b][k][m] * X[b][k][n] + beff[b][m] ----------------
// BM=BN=128, BK=16, 256 threads, 8x8 per thread (4x4 quads at +0/+64).
__global__ __launch_bounds__(256, 2)
void gemm_kernel(const float* __restrict__ Wt, size_t wStrideB,
                 const float* __restrict__ beff, int beffStride,
                 const float* __restrict__ X, size_t xStrideB,
                 float* __restrict__ Y, size_t yStrideB,
                 const float* __restrict__ R, size_t rStrideB,
                 int M, int K, int ep)
{
    __shared__ float Ws[16][128];
    __shared__ float Xs[16][128];
    const int b = blockIdx.z;
    const int n0 = blockIdx.x * 128;
    const int m0 = blockIdx.y * 128;
    const float* Wb = Wt + (size_t)b * wStrideB;
    const float* Xb = X  + (size_t)b * xStrideB;
    float acc[8][8];
    #pragma unroll
    for (int i = 0; i < 8; i++)
        #pragma unroll
        for (int j = 0; j < 8; j++) acc[i][j] = 0.f;

    const int tid = threadIdx.x;
    const int tx = tid & 15, ty = tid >> 4;

    for (int k0 = 0; k0 < K; k0 += 16) {
        #pragma unroll
        for (int u = 0; u < 2; u++) {
            int f = tid + u * 256;         // 512 float4 per tile
            int k = f >> 5, c4 = f & 31;
            ((float4*)Ws[k])[c4] = ((const float4*)(Wb + (size_t)(k0 + k) * M + m0))[c4];
            ((float4*)Xs[k])[c4] = ((const float4*)(Xb + (size_t)(k0 + k) * TT + n0))[c4];
        }
        __syncthreads();
        #pragma unroll
        for (int k = 0; k < 16; k++) {
            float ar[8], br[8];
            *(float4*)&ar[0] = *(const float4*)&Ws[k][ty * 4];
            *(float4*)&ar[4] = *(const float4*)&Ws[k][64 + ty * 4];
            *(float4*)&br[0] = *(const float4*)&Xs[k][tx * 4];
            *(float4*)&br[4] = *(const float4*)&Xs[k][64 + tx * 4];
            #pragma unroll
            for (int i = 0; i < 8; i++)
                #pragma unroll
                for (int j = 0; j < 8; j++)
                    acc[i][j] += ar[i] * br[j];
        }
        __syncthreads();
    }

    #pragma unroll
    for (int i = 0; i < 8; i++) {
        int m = m0 + ty * 4 + (i & 3) + ((i >> 2) << 6);
        float bv = beff[(size_t)b * beffStride + m];
        #pragma unroll
        for (int jh = 0; jh < 2; jh++) {
            int n = n0 + tx * 4 + (jh << 6);
            float4 v;
            v.x = acc[i][jh*4+0] + bv;
            v.y = acc[i][jh*4+1] + bv;
            v.z = acc[i][jh*4+2] + bv;
            v.w = acc[i][jh*4+3] + bv;
            if (ep == 1) {                       // SiLU
                v.x = v.x / (1.f + expf(-v.x));
                v.y = v.y / (1.f + expf(-v.y));
                v.z = v.z / (1.f + expf(-v.z));
                v.w = v.w / (1.f + expf(-v.w));
            } else if (ep == 2) {                // + residual
                float4 rv = *(const float4*)(R + (size_t)b * rStrideB + (size_t)m * TT + n);
                v.x += rv.x; v.y += rv.y; v.z += rv.z; v.w += rv.w;
            }
            *(float4*)(Y + (size_t)b * yStrideB + (size_t)m * TT + n) = v;
        }
    }
}

// ---------------- k softmax row stats (max + 1/sum over T) ----------------
__global__ void ksm_stats_kernel(const float* __restrict__ kbase, size_t strideB,
                                 float* __restrict__ kmax, float* __restrict__ kinv)
{
    int r = blockIdx.x, b = blockIdx.y;
    const float4* p4 = (const float4*)(kbase + (size_t)b * strideB + (size_t)r * TT);
    float mx = -1e30f;
    for (int i = threadIdx.x; i < TT/4; i += 256) {
        float4 v = p4[i];
        mx = fmaxf(mx, fmaxf(fmaxf(v.x, v.y), fmaxf(v.z, v.w)));
    }
    __shared__ float sh[8];
    __shared__ float bmax, bsum;
    int lane = threadIdx.x & 31, w = threadIdx.x >> 5;
    #pragma unroll
    for (int o = 16; o > 0; o >>= 1) mx = fmaxf(mx, __shfl_xor_sync(0xffffffffu, mx, o));
    if (lane == 0) sh[w] = mx;
    __syncthreads();
    if (threadIdx.x < 8) {
        mx = sh[threadIdx.x];
        #pragma unroll
        for (int o = 4; o > 0; o >>= 1) mx = fmaxf(mx, __shfl_xor_sync(0xffu, mx, o));
        if (threadIdx.x == 0) bmax = mx;
    }
    __syncthreads();
    float m = bmax;
    float s = 0.f;
    for (int i = threadIdx.x; i < TT/4; i += 256) {
        float4 v = p4[i];
        s += expf(v.x - m) + expf(v.y - m) + expf(v.z - m) + expf(v.w - m);
    }
    #pragma unroll
    for (int o = 16; o > 0; o >>= 1) s += __shfl_xor_sync(0xffffffffu, s, o);
    if (lane == 0) sh[w] = s;
    __syncthreads();
    if (threadIdx.x < 8) {
        s = sh[threadIdx.x];
        #pragma unroll
        for (int o = 4; o > 0; o >>= 1) s += __shfl_xor_sync(0xffu, s, o);
        if (threadIdx.x == 0) bsum = s;
    }
    __syncthreads();
    if (threadIdx.x == 0) {
        kmax[b*256 + r] = m;
        kinv[b*256 + r] = 1.f / bsum;
    }
}

// ---------------- ctx partials: ctx[b,h,d,e] += sum_t ksm[d,t]*v[e,t] over one t-slice ----------------
__global__ void ctx_kernel(const float* __restrict__ kv, size_t strideB, int koff, int voff,
                           const float* __restrict__ kmax, const float* __restrict__ kinv,
                           float* __restrict__ cpart)
{
    int bh = blockIdx.x;             // 0..63
    int slice = blockIdx.y;          // 0..7
    int b = bh / NH, h = bh % NH;
    __shared__ float ks[32][65], vs[32][65];
    __shared__ float km[32], ki[32];
    int tid = threadIdx.x;
    if (tid < 32) {
        km[tid] = kmax[b*256 + h*32 + tid];
        ki[tid] = kinv[b*256 + h*32 + tid];
    }
    const float* kp = kv + (size_t)b*strideB + (size_t)(koff + h*32)*TT + slice*1024;
    const float* vp = kv + (size_t)b*strideB + (size_t)(voff + h*32)*TT + slice*1024;
    int d = tid >> 3, e0 = (tid & 7) * 4;
    float c0 = 0.f, c1 = 0.f, c2 = 0.f, c3 = 0.f;
    for (int tc = 0; tc < 1024; tc += 64) {
        __syncthreads();
        for (int i = tid; i < 32*64; i += 256) {
            int r = i >> 6, t = i & 63;
            ks[r][t] = expf(kp[(size_t)r*TT + tc + t] - km[r]) * ki[r];
            vs[r][t] = vp[(size_t)r*TT + tc + t];
        }
        __syncthreads();
        #pragma unroll 8
        for (int t = 0; t < 64; t++) {
            float kd = ks[d][t];
            c0 += kd * vs[e0+0][t];
            c1 += kd * vs[e0+1][t];
            c2 += kd * vs[e0+2][t];
            c3 += kd * vs[e0+3][t];
        }
    }
    float* cp = cpart + (size_t)slice*65536 + (size_t)bh*1024 + d*32 + e0;
    cp[0] = c0; cp[1] = c1; cp[2] = c2; cp[3] = c3;
}

__global__ void ctx_reduce_kernel(const float* __restrict__ cpart, float* __restrict__ ctx)
{
    int i = blockIdx.x * 256 + threadIdx.x;   // 65536 total
    float s = 0.f;
    #pragma unroll
    for (int sl = 0; sl < 8; sl++) s += cpart[(size_t)sl*65536 + i];
    ctx[i] = s;
}

// ---------------- attn out: o[e,t] = sum_d ctx[d,e] * softmax_d(q[:,t]) * scale ----------------
__global__ void attn_out_kernel(const float* __restrict__ q, size_t strideB, int qoff,
                                const float* __restrict__ ctx,
                                float* __restrict__ o, size_t oStrideB)
{
    int bh = blockIdx.x;
    int b = bh / NH, h = bh % NH;
    int t = blockIdx.y * 256 + threadIdx.x;
    __shared__ float cs[32][32];
    for (int i = threadIdx.x; i < 1024; i += 256)
        cs[i >> 5][i & 31] = ctx[(size_t)bh*1024 + i];
    __syncthreads();
    const float* qp = q + (size_t)b*strideB + (size_t)(qoff + h*32)*TT + t;
    float p[32];
    float mx = -1e30f;
    #pragma unroll
    for (int d = 0; d < 32; d++) { p[d] = qp[(size_t)d*TT]; mx = fmaxf(mx, p[d]); }
    float s = 0.f;
    #pragma unroll
    for (int d = 0; d < 32; d++) { p[d] = expf(p[d] - mx); s += p[d]; }
    float inv = 0.17677669529663687f / s;   // (1/sqrt(32)) / sum
    #pragma unroll
    for (int d = 0; d < 32; d++) p[d] *= inv;
    float accv[32];
    #pragma unroll
    for (int e = 0; e < 32; e++) accv[e] = 0.f;
    #pragma unroll
    for (int d = 0; d < 32; d++) {
        float pd = p[d];
        #pragma unroll
        for (int e4 = 0; e4 < 8; e4++) {
            float4 cv = *(const float4*)&cs[d][e4*4];
            accv[e4*4+0] += cv.x * pd;
            accv[e4*4+1] += cv.y * pd;
            accv[e4*4+2] += cv.z * pd;
            accv[e4*4+3] += cv.w * pd;
        }
    }
    float* op = o + (size_t)b*oStrideB + (size_t)(h*32)*TT + t;
    #pragma unroll
    for (int e = 0; e < 32; e++) op[(size_t)e*TT] = accv[e];
}

// ---------------- y = gn(v)*g + b + r  (elementwise, float4) ----------------
__global__ void gn_add_kernel(const float* __restrict__ v,
                              const float* __restrict__ gamma, const float* __restrict__ beta,
                              const float* __restrict__ mu, const float* __restrict__ rs,
                              const float* __restrict__ r, float* __restrict__ y)
{
    size_t i = ((size_t)blockIdx.x * 256 + threadIdx.x) * 4;
    int c = (int)((i / TT) % DIMC);
    int b = (int)(i / ((size_t)DIMC * TT));
    int grp = c >> 3;  // GC = 8
    float rr = rs[b*32 + grp], m = mu[b*32 + grp];
    float sc = gamma[c] * rr;
    float sh = beta[c] - m * sc;
    float4 vv = *(const float4*)(v + i);
    float4 rv = *(const float4*)(r + i);
    float4 o;
    o.x = vv.x * sc + sh + rv.x;
    o.y = vv.y * sc + sh + rv.y;
    o.z = vv.z * sc + sh + rv.z;
    o.w = vv.w * sc + sh + rv.w;
    *(float4*)(y + i) = o;
}

// ---------------- host orchestration ----------------
extern "C" void kernel_launch(void* const* d_in, const int* in_sizes, int n_in,
                              void* d_out, int out_size)
{
    const float* x     = (const float*)d_in[0];
    const float* c     = (const float*)d_in[1];
    const float* W_qkv = (const float*)d_in[2];
    const float* W_so  = (const float*)d_in[3];
    const float* b_so  = (const float*)d_in[4];
    const float* sa_g  = (const float*)d_in[5];
    const float* sa_b  = (const float*)d_in[6];
    const float* W_cq  = (const float*)d_in[7];
    const float* W_ckv = (const float*)d_in[8];
    const float* W_co  = (const float*)d_in[9];
    const float* b_co  = (const float*)d_in[10];
    const float* ca_g  = (const float*)d_in[11];
    const float* ca_b  = (const float*)d_in[12];
    const float* W_m1  = (const float*)d_in[13];
    const float* b_m1  = (const float*)d_in[14];
    const float* W_m2  = (const float*)d_in[15];
    const float* b_m2  = (const float*)d_in[16];
    const float* nm_g  = (const float*)d_in[17];
    const float* nm_b  = (const float*)d_in[18];
    const float* nm1_g = (const float*)d_in[19];
    const float* nm1_b = (const float*)d_in[20];
    const float* nm2_g = (const float*)d_in[21];
    const float* nm2_b = (const float*)d_in[22];
    const float* nm3_g = (const float*)d_in[23];
    const float* nm3_b = (const float*)d_in[24];
    float* out = (float*)d_out;

    float *big, *attn, *so, *xb, *wt, *beff, *mu, *rs, *aa, *ab, *kmax, *kinv, *ctx, *ctxp;
    cudaGetSymbolAddress((void**)&big,  g_big);
    cudaGetSymbolAddress((void**)&attn, g_attn);
    cudaGetSymbolAddress((void**)&so,   g_so);
    cudaGetSymbolAddress((void**)&xb,   g_x);
    cudaGetSymbolAddress((void**)&wt,   g_wt);
    cudaGetSymbolAddress((void**)&beff, g_beff);
    cudaGetSymbolAddress((void**)&mu,   g_mu);
    cudaGetSymbolAddress((void**)&rs,   g_rs);
    cudaGetSymbolAddress((void**)&aa,   g_affa);
    cudaGetSymbolAddress((void**)&ab,   g_affb);
    cudaGetSymbolAddress((void**)&kmax, g_kmax);
    cudaGetSymbolAddress((void**)&kinv, g_kinv);
    cudaGetSymbolAddress((void**)&ctx,  g_ctx);
    cudaGetSymbolAddress((void**)&ctxp, g_ctxp);

    const dim3 tb8(32, 8);
    const size_t XT = (size_t)DIMC * TT;   // 256*T

    // ================= Phase 1: self linear attention =================
    gn_stats_kernel<<<BQ*32, 256>>>(x, 8, mu, rs);
    affine_kernel<<<BQ, 256>>>(nm_g, nm_b, mu, rs, aa, ab, 256);
    foldT_kernel<<<dim3(8, 24, BQ), tb8>>>(W_qkv, aa, wt, 768, 256);
    beff_kernel<<<dim3(768, BQ), 128>>>(W_qkv, ab, nullptr, beff, 768, 256);
    gemm_kernel<<<dim3(64, 6, BQ), 256>>>(wt, (size_t)768*256, beff, 768,
                                          x, XT, big, (size_t)768*TT,
                                          nullptr, 0, 768, 256, 0);
    ksm_stats_kernel<<<dim3(256, BQ), 256>>>(big + (size_t)256*TT, (size_t)768*TT, kmax, kinv);
    ctx_kernel<<<dim3(64, 8), 256>>>(big, (size_t)768*TT, 256, 512, kmax, kinv, ctxp);
    ctx_reduce_kernel<<<256, 256>>>(ctxp, ctx);
    attn_out_kernel<<<dim3(64, 32), 256>>>(big, (size_t)768*TT, 0, ctx, attn, XT);
    foldT_kernel<<<dim3(8, 8, 1), tb8>>>(W_so, nullptr, wt, 256, 256);
    gemm_kernel<<<dim3(64, 2, BQ), 256>>>(wt, 0, b_so, 0,
                                          attn, XT, so, XT,
                                          nullptr, 0, 256, 256, 0);
    gn_stats_kernel<<<BQ*32, 256>>>(so, 8, mu, rs);
    gn_add_kernel<<<16384, 256>>>(so, sa_g, sa_b, mu, rs, x, xb);

    // ================= Phase 2: cross linear attention =================
    gn_stats_kernel<<<BQ*32, 256>>>(xb, 8, mu, rs);
    affine_kernel<<<BQ, 256>>>(nm1_g, nm1_b, mu, rs, aa, ab, 256);
    foldT_kernel<<<dim3(8, 8, BQ), tb8>>>(W_cq, aa, wt, 256, 256);
    beff_kernel<<<dim3(256, BQ), 128>>>(W_cq, ab, nullptr, beff, 256, 256);
    gemm_kernel<<<dim3(64, 2, BQ), 256>>>(wt, (size_t)256*256, beff, 256,
                                          xb, XT, attn, XT,
                                          nullptr, 0, 256, 256, 0);
    gn_stats_kernel<<<BQ*32, 256>>>(c, 16, mu, rs);
    affine_kernel<<<BQ, 256>>>(nm3_g, nm3_b, mu, rs, aa, ab, 512);
    foldT_kernel<<<dim3(16, 16, BQ), tb8>>>(W_ckv, aa, wt, 512, 512);
    beff_kernel<<<dim3(512, BQ), 128>>>(W_ckv, ab, nullptr, beff, 512, 512);
    gemm_kernel<<<dim3(64, 4, BQ), 256>>>(wt, (size_t)512*512, beff, 512,
                                          c, (size_t)512*TT, big, (size_t)512*TT,
                                          nullptr, 0, 512, 512, 0);
    ksm_stats_kernel<<<dim3(256, BQ), 256>>>(big, (size_t)512*TT, kmax, kinv);
    ctx_kernel<<<dim3(64, 8), 256>>>(big, (size_t)512*TT, 0, 256, kmax, kinv, ctxp);
    ctx_reduce_kernel<<<256, 256>>>(ctxp, ctx);
    attn_out_kernel<<<dim3(64, 32), 256>>>(attn, XT, 0, ctx, big, XT);
    foldT_kernel<<<dim3(8, 8, 1), tb8>>>(W_co, nullptr, wt, 256, 256);
    gemm_kernel<<<dim3(64, 2, BQ), 256>>>(wt, 0, b_co, 0,
                                          big, XT, so, XT,
                                          nullptr, 0, 256, 256, 0);
    gn_stats_kernel<<<BQ*32, 256>>>(so, 8, mu, rs);
    gn_add_kernel<<<16384, 256>>>(so, ca_g, ca_b, mu, rs, xb, xb);

    // ================= Phase 3: SiLU MLP =================
    gn_stats_kernel<<<BQ*32, 256>>>(xb, 8, mu, rs);
    affine_kernel<<<BQ, 256>>>(nm2_g, nm2_b, mu, rs, aa, ab, 256);
    foldT_kernel<<<dim3(8, 20, BQ), tb8>>>(W_m1, aa, wt, 640, 256);
    beff_kernel<<<dim3(640, BQ), 128>>>(W_m1, ab, b_m1, beff, 640, 256);
    gemm_kernel<<<dim3(64, 5, BQ), 256>>>(wt, (size_t)640*256, beff, 640,
                                          xb, XT, big, (size_t)640*TT,
                                          nullptr, 0, 640, 256, 1 /*silu*/);
    foldT_kernel<<<dim3(20, 8, 1), tb8>>>(W_m2, nullptr, wt, 256, 640);
    gemm_kernel<<<dim3(64, 2, BQ), 256>>>(wt, 0, b_m2, 0,
                                          big, (size_t)640*TT, out, XT,
                                          xb, XT, 256, 640, 2 /*residual*/);
}

// round 7
// speedup vs baseline: 1.5135x; 1.5135x over previous
#include <cuda_runtime.h>
#include <cuda_bf16.h>
#include <cstdint>

#define BQ 8
#define DIMC 256
#define TT 8192
#define NH 8
#define EPSV 1e-5f

// SMEM layout per stage: Ahi[128x40bf16]=10240B, Alo=10240B, Bhi[32x136bf16]=8704B, Blo=8704B
#define STG_BYTES 37888
#define SMEM_MM (2 * STG_BYTES)

// ---------------- scratch (device globals) ----------------
__device__ float g_big [(size_t)BQ * 768 * TT];
__device__ float g_attn[(size_t)BQ * DIMC * TT];
__device__ float g_so  [(size_t)BQ * DIMC * TT];
__device__ float g_x   [(size_t)BQ * DIMC * TT];
__device__ float g_beff[BQ * 1024];
__device__ float g_mu  [BQ * 32];
__device__ float g_rs  [BQ * 32];
__device__ float g_affa[BQ * 512];
__device__ float g_affb[BQ * 512];
__device__ float g_kmax[BQ * 256];
__device__ float g_kinv[BQ * 256];
__device__ float g_ctx [BQ * NH * 32 * 32];
__device__ float g_ctxp[8 * BQ * NH * 32 * 32];

// ==================== PTX helpers (plain sm_80+ instructions only) ====================
__device__ __forceinline__ unsigned s2u(const void* p) {
    unsigned a;
    asm("{ .reg .u64 t; cvta.to.shared.u64 t, %1; cvt.u32.u64 %0, t; }" : "=r"(a) : "l"(p));
    return a;
}
#define LDSM4(r, addr) \
    asm volatile("ldmatrix.sync.aligned.m8n8.x4.shared.b16 {%0,%1,%2,%3}, [%4];" \
        : "=r"((r)[0]), "=r"((r)[1]), "=r"((r)[2]), "=r"((r)[3]) : "r"(addr))
#define LDSM4T(r, addr) \
    asm volatile("ldmatrix.sync.aligned.m8n8.x4.trans.shared.b16 {%0,%1,%2,%3}, [%4];" \
        : "=r"((r)[0]), "=r"((r)[1]), "=r"((r)[2]), "=r"((r)[3]) : "r"(addr))
__device__ __forceinline__ void mma_bf16(float* c, const unsigned* a, const unsigned* b) {
    asm volatile("mma.sync.aligned.m16n8k16.row.col.f32.bf16.bf16.f32 "
        "{%0,%1,%2,%3}, {%4,%5,%6,%7}, {%8,%9}, {%0,%1,%2,%3};"
        : "+f"(c[0]), "+f"(c[1]), "+f"(c[2]), "+f"(c[3])
        : "r"(a[0]), "r"(a[1]), "r"(a[2]), "r"(a[3]), "r"(b[0]), "r"(b[1]));
}
__device__ __forceinline__ unsigned pack2(__nv_bfloat16 lo, __nv_bfloat16 hi) {
    __nv_bfloat162 t = __halves2bfloat162(lo, hi);   // .x = lo halfword
    return *(unsigned*)&t;
}

// ==================== tensor-core GEMM (mma.sync bf16 hi/lo split) ====================
// Y[b][m][n] = sum_k (W[m][k]*aS[b][k]) * X[b][k][n] + bias[m] [silu | +R]
__global__ __launch_bounds__(256, 1)
void mm_kernel(const float* __restrict__ W, const float* __restrict__ aS,
               const float* __restrict__ bias, int perB,
               const float* __restrict__ X, size_t xStrideB,
               float* __restrict__ Y, size_t yStrideB,
               const float* __restrict__ R, size_t rStrideB,
               int M, int K, int ep)
{
    extern __shared__ char smem[];
    const unsigned sb = s2u(smem);
    const int tid = threadIdx.x, lane = tid & 31, wid = tid >> 5;
    const int wr = wid >> 2, wc = wid & 3;           // warp grid 2(m) x 4(n)
    const int mt = blockIdx.x, nt = blockIdx.y, b = blockIdx.z;
    const int m0 = mt * 128, n0 = nt * 128;
    const float* Xb = X + (size_t)b * xStrideB;
    const float* aSb = aS ? aS + b * K : nullptr;

    float acc[4][4][4];
    #pragma unroll
    for (int i = 0; i < 4; i++)
        #pragma unroll
        for (int j = 0; j < 4; j++)
            #pragma unroll
            for (int r = 0; r < 4; r++) acc[i][j][r] = 0.f;

    const unsigned aoff = (lane & 15) * 80  + (lane >> 4) * 16;
    const unsigned boff = (lane & 15) * 272 + (lane >> 4) * 16;
    const int nk = K >> 5;

    float4 rA[4], rB[4];

    auto gload = [&](int kc) {
        #pragma unroll
        for (int u = 0; u < 4; u++) {
            int f = tid + u * 256;
            int ra = f >> 3, ca = (f & 7) * 4;
            float4 v = *(const float4*)&W[(size_t)(m0 + ra) * K + kc * 32 + ca];
            if (aSb) {
                v.x *= aSb[kc*32 + ca];   v.y *= aSb[kc*32 + ca+1];
                v.z *= aSb[kc*32 + ca+2]; v.w *= aSb[kc*32 + ca+3];
            }
            rA[u] = v;
            int rb = f >> 5, cb = (f & 31) * 4;
            rB[u] = *(const float4*)&Xb[(size_t)(kc*32 + rb) * TT + n0 + cb];
        }
    };
    auto sstore = [&](int st) {
        size_t base = (size_t)st * STG_BYTES;
        #pragma unroll
        for (int u = 0; u < 4; u++) {
            int f = tid + u * 256;
            {   // A
                float4 v = rA[u];
                __nv_bfloat16 hx = __float2bfloat16(v.x), hy = __float2bfloat16(v.y);
                __nv_bfloat16 hz = __float2bfloat16(v.z), hw = __float2bfloat16(v.w);
                float lx = v.x - __bfloat162float(hx), ly = v.y - __bfloat162float(hy);
                float lz = v.z - __bfloat162float(hz), lw = v.w - __bfloat162float(hw);
                int ra = f >> 3, ca = f & 7;
                size_t off = base + ra * 80 + ca * 8;
                *(uint2*)(smem + off) = make_uint2(pack2(hx, hy), pack2(hz, hw));
                *(uint2*)(smem + off + 10240) = make_uint2(
                    pack2(__float2bfloat16(lx), __float2bfloat16(ly)),
                    pack2(__float2bfloat16(lz), __float2bfloat16(lw)));
            }
            {   // B
                float4 v = rB[u];
                __nv_bfloat16 hx = __float2bfloat16(v.x), hy = __float2bfloat16(v.y);
                __nv_bfloat16 hz = __float2bfloat16(v.z), hw = __float2bfloat16(v.w);
                float lx = v.x - __bfloat162float(hx), ly = v.y - __bfloat162float(hy);
                float lz = v.z - __bfloat162float(hz), lw = v.w - __bfloat162float(hw);
                int rb = f >> 5, cb = f & 31;
                size_t off = base + 20480 + rb * 272 + cb * 8;
                *(uint2*)(smem + off) = make_uint2(pack2(hx, hy), pack2(hz, hw));
                *(uint2*)(smem + off + 8704) = make_uint2(
                    pack2(__float2bfloat16(lx), __float2bfloat16(ly)),
                    pack2(__float2bfloat16(lz), __float2bfloat16(lw)));
            }
        }
    };
    auto compute = [&](int st) {
        unsigned stb = sb + st * STG_BYTES;
        #pragma unroll
        for (int ks = 0; ks < 2; ks++) {
            unsigned ah[4][4], al[4][4], bh[2][4], bl[2][4];
            #pragma unroll
            for (int mf = 0; mf < 4; mf++) {
                unsigned adr = stb + wr * 5120 + mf * 1280 + ks * 32 + aoff;
                LDSM4(ah[mf], adr);
                LDSM4(al[mf], adr + 10240);
            }
            #pragma unroll
            for (int np = 0; np < 2; np++) {
                unsigned adr = stb + 20480 + ks * 4352 + wc * 64 + np * 32 + boff;
                LDSM4T(bh[np], adr);
                LDSM4T(bl[np], adr + 8704);
            }
            #pragma unroll
            for (int mf = 0; mf < 4; mf++)
                #pragma unroll
                for (int nf = 0; nf < 4; nf++) {
                    const unsigned* bp = &bh[nf >> 1][(nf & 1) * 2];
                    const unsigned* lp = &bl[nf >> 1][(nf & 1) * 2];
                    mma_bf16(acc[mf][nf], ah[mf], bp);
                    mma_bf16(acc[mf][nf], al[mf], bp);
                    mma_bf16(acc[mf][nf], ah[mf], lp);
                }
        }
    };

    gload(0);
    sstore(0);
    __syncthreads();
    for (int i = 0; i < nk; i++) {
        if (i + 1 < nk) gload(i + 1);
        compute(i & 1);
        __syncthreads();
        if (i + 1 < nk) { sstore((i + 1) & 1); __syncthreads(); }
    }

    // epilogue: direct v2 stores (each lane-quad fills one 32B sector)
    const float* biasB = bias + (perB ? (size_t)b * M : 0);
    float* Yb = Y + (size_t)b * yStrideB;
    const float* Rb = R ? R + (size_t)b * rStrideB : nullptr;
    #pragma unroll
    for (int mf = 0; mf < 4; mf++) {
        int gm = m0 + wr * 64 + mf * 16 + (lane >> 2);
        float bv0 = biasB[gm], bv1 = biasB[gm + 8];
        #pragma unroll
        for (int nf = 0; nf < 4; nf++) {
            int gn = n0 + wc * 32 + nf * 8 + (lane & 3) * 2;
            float* a4 = acc[mf][nf];
            float2 v0 = make_float2(a4[0] + bv0, a4[1] + bv0);
            float2 v1 = make_float2(a4[2] + bv1, a4[3] + bv1);
            if (ep == 1) {
                v0.x /= (1.f + expf(-v0.x)); v0.y /= (1.f + expf(-v0.y));
                v1.x /= (1.f + expf(-v1.x)); v1.y /= (1.f + expf(-v1.y));
            } else if (ep == 2) {
                float2 r0 = *(const float2*)&Rb[(size_t)gm * TT + gn];
                float2 r1 = *(const float2*)&Rb[(size_t)(gm + 8) * TT + gn];
                v0.x += r0.x; v0.y += r0.y; v1.x += r1.x; v1.y += r1.y;
            }
            *(float2*)&Yb[(size_t)gm * TT + gn] = v0;
            *(float2*)&Yb[(size_t)(gm + 8) * TT + gn] = v1;
        }
    }
}

// ==================== group-norm / attention kernels (R3, proven) ====================
__global__ void gn_stats_kernel(const float* __restrict__ x, int GC,
                                float* __restrict__ mu, float* __restrict__ rs)
{
    const size_t n = (size_t)GC * TT;
    const float4* x4 = (const float4*)(x + (size_t)blockIdx.x * n);
    const int n4 = (int)(n >> 2);
    float s = 0.f, sq = 0.f;
    for (int i = threadIdx.x; i < n4; i += 256) {
        float4 v = x4[i];
        s += (v.x + v.y) + (v.z + v.w);
        sq += v.x*v.x + v.y*v.y + v.z*v.z + v.w*v.w;
    }
    __shared__ float sh1[8], sh2[8];
    int lane = threadIdx.x & 31, w = threadIdx.x >> 5;
    #pragma unroll
    for (int o = 16; o > 0; o >>= 1) {
        s += __shfl_xor_sync(0xffffffffu, s, o);
        sq += __shfl_xor_sync(0xffffffffu, sq, o);
    }
    if (lane == 0) { sh1[w] = s; sh2[w] = sq; }
    __syncthreads();
    if (threadIdx.x < 8) {
        s = sh1[threadIdx.x]; sq = sh2[threadIdx.x];
        #pragma unroll
        for (int o = 4; o > 0; o >>= 1) {
            s += __shfl_xor_sync(0xffu, s, o);
            sq += __shfl_xor_sync(0xffu, sq, o);
        }
        if (threadIdx.x == 0) {
            float inv_n = 1.f / (float)n;
            float m = s * inv_n;
            float var = sq * inv_n - m * m;
            mu[blockIdx.x] = m;
            rs[blockIdx.x] = rsqrtf(fmaxf(var, 0.f) + EPSV);
        }
    }
}

__global__ void affine_kernel(const float* __restrict__ g, const float* __restrict__ be,
                              const float* __restrict__ mu, const float* __restrict__ rs,
                              float* __restrict__ a, float* __restrict__ bb, int C)
{
    int b = blockIdx.x;
    int GC = C >> 5;
    for (int c = threadIdx.x; c < C; c += blockDim.x) {
        int grp = c / GC;
        float r = rs[b*32 + grp], m = mu[b*32 + grp];
        float av = g[c] * r;
        a [b*C + c] = av;
        bb[b*C + c] = be[c] - m * av;
    }
}

__global__ void beff_kernel(const float* __restrict__ W, const float* __restrict__ bbv,
                            const float* __restrict__ bias, float* __restrict__ beff,
                            int M, int K)
{
    int m = blockIdx.x, b = blockIdx.y;
    float s = 0.f;
    for (int k = threadIdx.x; k < K; k += 128)
        s += W[(size_t)m*K + k] * bbv[b*K + k];
    __shared__ float sh[4];
    int lane = threadIdx.x & 31, w = threadIdx.x >> 5;
    #pragma unroll
    for (int o = 16; o > 0; o >>= 1) s += __shfl_xor_sync(0xffffffffu, s, o);
    if (lane == 0) sh[w] = s;
    __syncthreads();
    if (threadIdx.x == 0)
        beff[(size_t)b*M + m] = sh[0] + sh[1] + sh[2] + sh[3] + (bias ? bias[m] : 0.f);
}

__global__ void ksm_stats_kernel(const float* __restrict__ kbase, size_t strideB,
                                 float* __restrict__ kmax, float* __restrict__ kinv)
{
    int r = blockIdx.x, b = blockIdx.y;
    const float4* p4 = (const float4*)(kbase + (size_t)b * strideB + (size_t)r * TT);
    float mx = -1e30f;
    for (int i = threadIdx.x; i < TT/4; i += 256) {
        float4 v = p4[i];
        mx = fmaxf(mx, fmaxf(fmaxf(v.x, v.y), fmaxf(v.z, v.w)));
    }
    __shared__ float sh[8];
    __shared__ float bmax, bsum;
    int lane = threadIdx.x & 31, w = threadIdx.x >> 5;
    #pragma unroll
    for (int o = 16; o > 0; o >>= 1) mx = fmaxf(mx, __shfl_xor_sync(0xffffffffu, mx, o));
    if (lane == 0) sh[w] = mx;
    __syncthreads();
    if (threadIdx.x < 8) {
        mx = sh[threadIdx.x];
        #pragma unroll
        for (int o = 4; o > 0; o >>= 1) mx = fmaxf(mx, __shfl_xor_sync(0xffu, mx, o));
        if (threadIdx.x == 0) bmax = mx;
    }
    __syncthreads();
    float m = bmax;
    float s = 0.f;
    for (int i = threadIdx.x; i < TT/4; i += 256) {
        float4 v = p4[i];
        s += expf(v.x - m) + expf(v.y - m) + expf(v.z - m) + expf(v.w - m);
    }
    #pragma unroll
    for (int o = 16; o > 0; o >>= 1) s += __shfl_xor_sync(0xffffffffu, s, o);
    if (lane == 0) sh[w] = s;
    __syncthreads();
    if (threadIdx.x < 8) {
        s = sh[threadIdx.x];
        #pragma unroll
        for (int o = 4; o > 0; o >>= 1) s += __shfl_xor_sync(0xffu, s, o);
        if (threadIdx.x == 0) bsum = s;
    }
    __syncthreads();
    if (threadIdx.x == 0) { kmax[b*256 + r] = m; kinv[b*256 + r] = 1.f / bsum; }
}

__global__ void ctx_kernel(const float* __restrict__ kv, size_t strideB, int koff, int voff,
                           const float* __restrict__ kmax, const float* __restrict__ kinv,
                           float* __restrict__ cpart)
{
    int bh = blockIdx.x;
    int slice = blockIdx.y;
    int b = bh / NH, h = bh % NH;
    __shared__ float ks[32][65], vs[32][65];
    __shared__ float km[32], ki[32];
    int tid = threadIdx.x;
    if (tid < 32) {
        km[tid] = kmax[b*256 + h*32 + tid];
        ki[tid] = kinv[b*256 + h*32 + tid];
    }
    const float* kp = kv + (size_t)b*strideB + (size_t)(koff + h*32)*TT + slice*1024;
    const float* vp = kv + (size_t)b*strideB + (size_t)(voff + h*32)*TT + slice*1024;
    int d = tid >> 3, e0 = (tid & 7) * 4;
    float c0 = 0.f, c1 = 0.f, c2 = 0.f, c3 = 0.f;
    for (int tc = 0; tc < 1024; tc += 64) {
        __syncthreads();
        for (int i = tid; i < 32*64; i += 256) {
            int r = i >> 6, t = i & 63;
            ks[r][t] = expf(kp[(size_t)r*TT + tc + t] - km[r]) * ki[r];
            vs[r][t] = vp[(size_t)r*TT + tc + t];
        }
        __syncthreads();
        #pragma unroll 8
        for (int t = 0; t < 64; t++) {
            float kd = ks[d][t];
            c0 += kd * vs[e0+0][t];
            c1 += kd * vs[e0+1][t];
            c2 += kd * vs[e0+2][t];
            c3 += kd * vs[e0+3][t];
        }
    }
    float* cp = cpart + (size_t)slice*65536 + (size_t)bh*1024 + d*32 + e0;
    cp[0] = c0; cp[1] = c1; cp[2] = c2; cp[3] = c3;
}

__global__ void ctx_reduce_kernel(const float* __restrict__ cpart, float* __restrict__ ctx)
{
    int i = blockIdx.x * 256 + threadIdx.x;
    float s = 0.f;
    #pragma unroll
    for (int sl = 0; sl < 8; sl++) s += cpart[(size_t)sl*65536 + i];
    ctx[i] = s;
}

__global__ void attn_out_kernel(const float* __restrict__ q, size_t strideB, int qoff,
                                const float* __restrict__ ctx,
                                float* __restrict__ o, size_t oStrideB)
{
    int bh = blockIdx.x;
    int b = bh / NH, h = bh % NH;
    int t = blockIdx.y * 256 + threadIdx.x;
    __shared__ float cs[32][32];
    for (int i = threadIdx.x; i < 1024; i += 256)
        cs[i >> 5][i & 31] = ctx[(size_t)bh*1024 + i];
    __syncthreads();
    const float* qp = q + (size_t)b*strideB + (size_t)(qoff + h*32)*TT + t;
    float p[32];
    float mx = -1e30f;
    #pragma unroll
    for (int d = 0; d < 32; d++) { p[d] = qp[(size_t)d*TT]; mx = fmaxf(mx, p[d]); }
    float s = 0.f;
    #pragma unroll
    for (int d = 0; d < 32; d++) { p[d] = expf(p[d] - mx); s += p[d]; }
    float inv = 0.17677669529663687f / s;
    #pragma unroll
    for (int d = 0; d < 32; d++) p[d] *= inv;
    float accv[32];
    #pragma unroll
    for (int e = 0; e < 32; e++) accv[e] = 0.f;
    #pragma unroll
    for (int d = 0; d < 32; d++) {
        float pd = p[d];
        #pragma unroll
        for (int e4 = 0; e4 < 8; e4++) {
            float4 cv = *(const float4*)&cs[d][e4*4];
            accv[e4*4+0] += cv.x * pd;
            accv[e4*4+1] += cv.y * pd;
            accv[e4*4+2] += cv.z * pd;
            accv[e4*4+3] += cv.w * pd;
        }
    }
    float* op = o + (size_t)b*oStrideB + (size_t)(h*32)*TT + t;
    #pragma unroll
    for (int e = 0; e < 32; e++) op[(size_t)e*TT] = accv[e];
}

__global__ void gn_add_kernel(const float* __restrict__ v,
                              const float* __restrict__ gamma, const float* __restrict__ beta,
                              const float* __restrict__ mu, const float* __restrict__ rs,
                              const float* __restrict__ r, float* __restrict__ y)
{
    size_t i = ((size_t)blockIdx.x * 256 + threadIdx.x) * 4;
    int c = (int)((i / TT) % DIMC);
    int b = (int)(i / ((size_t)DIMC * TT));
    int grp = c >> 3;
    float rr = rs[b*32 + grp], m = mu[b*32 + grp];
    float sc = gamma[c] * rr;
    float sh = beta[c] - m * sc;
    float4 vv = *(const float4*)(v + i);
    float4 rv = *(const float4*)(r + i);
    float4 o;
    o.x = vv.x * sc + sh + rv.x;
    o.y = vv.y * sc + sh + rv.y;
    o.z = vv.z * sc + sh + rv.z;
    o.w = vv.w * sc + sh + rv.w;
    *(float4*)(y + i) = o;
}

// ==================== host orchestration ====================
extern "C" void kernel_launch(void* const* d_in, const int* in_sizes, int n_in,
                              void* d_out, int out_size)
{
    const float* x     = (const float*)d_in[0];
    const float* c     = (const float*)d_in[1];
    const float* W_qkv = (const float*)d_in[2];
    const float* W_so  = (const float*)d_in[3];
    const float* b_so  = (const float*)d_in[4];
    const float* sa_g  = (const float*)d_in[5];
    const float* sa_b  = (const float*)d_in[6];
    const float* W_cq  = (const float*)d_in[7];
    const float* W_ckv = (const float*)d_in[8];
    const float* W_co  = (const float*)d_in[9];
    const float* b_co  = (const float*)d_in[10];
    const float* ca_g  = (const float*)d_in[11];
    const float* ca_b  = (const float*)d_in[12];
    const float* W_m1  = (const float*)d_in[13];
    const float* b_m1  = (const float*)d_in[14];
    const float* W_m2  = (const float*)d_in[15];
    const float* b_m2  = (const float*)d_in[16];
    const float* nm_g  = (const float*)d_in[17];
    const float* nm_b  = (const float*)d_in[18];
    const float* nm1_g = (const float*)d_in[19];
    const float* nm1_b = (const float*)d_in[20];
    const float* nm2_g = (const float*)d_in[21];
    const float* nm2_b = (const float*)d_in[22];
    const float* nm3_g = (const float*)d_in[23];
    const float* nm3_b = (const float*)d_in[24];
    float* out = (float*)d_out;

    float *big, *attn, *so, *xb, *beff, *mu, *rs, *aa, *ab, *kmax, *kinv, *ctx, *ctxp;
    cudaGetSymbolAddress((void**)&big,  g_big);
    cudaGetSymbolAddress((void**)&attn, g_attn);
    cudaGetSymbolAddress((void**)&so,   g_so);
    cudaGetSymbolAddress((void**)&xb,   g_x);
    cudaGetSymbolAddress((void**)&beff, g_beff);
    cudaGetSymbolAddress((void**)&mu,   g_mu);
    cudaGetSymbolAddress((void**)&rs,   g_rs);
    cudaGetSymbolAddress((void**)&aa,   g_affa);
    cudaGetSymbolAddress((void**)&ab,   g_affb);
    cudaGetSymbolAddress((void**)&kmax, g_kmax);
    cudaGetSymbolAddress((void**)&kinv, g_kinv);
    cudaGetSymbolAddress((void**)&ctx,  g_ctx);
    cudaGetSymbolAddress((void**)&ctxp, g_ctxp);

    static bool attr_set = false;
    if (!attr_set) {
        cudaFuncSetAttribute(mm_kernel, cudaFuncAttributeMaxDynamicSharedMemorySize, SMEM_MM);
        attr_set = true;
    }

    const size_t XT = (size_t)DIMC * TT;

    // ================= Phase 1: self linear attention =================
    gn_stats_kernel<<<BQ*32, 256>>>(x, 8, mu, rs);
    affine_kernel<<<BQ, 256>>>(nm_g, nm_b, mu, rs, aa, ab, 256);
    beff_kernel<<<dim3(768, BQ), 128>>>(W_qkv, ab, nullptr, beff, 768, 256);
    mm_kernel<<<dim3(6, 64, BQ), 256, SMEM_MM>>>(W_qkv, aa, beff, 1,
                                                 x, XT, big, (size_t)768*TT,
                                                 nullptr, 0, 768, 256, 0);
    ksm_stats_kernel<<<dim3(256, BQ), 256>>>(big + (size_t)256*TT, (size_t)768*TT, kmax, kinv);
    ctx_kernel<<<dim3(64, 8), 256>>>(big, (size_t)768*TT, 256, 512, kmax, kinv, ctxp);
    ctx_reduce_kernel<<<256, 256>>>(ctxp, ctx);
    attn_out_kernel<<<dim3(64, 32), 256>>>(big, (size_t)768*TT, 0, ctx, attn, XT);
    mm_kernel<<<dim3(2, 64, BQ), 256, SMEM_MM>>>(W_so, nullptr, b_so, 0,
                                                 attn, XT, so, XT,
                                                 nullptr, 0, 256, 256, 0);
    gn_stats_kernel<<<BQ*32, 256>>>(so, 8, mu, rs);
    gn_add_kernel<<<16384, 256>>>(so, sa_g, sa_b, mu, rs, x, xb);

    // ================= Phase 2: cross linear attention =================
    gn_stats_kernel<<<BQ*32, 256>>>(xb, 8, mu, rs);
    affine_kernel<<<BQ, 256>>>(nm1_g, nm1_b, mu, rs, aa, ab, 256);
    beff_kernel<<<dim3(256, BQ), 128>>>(W_cq, ab, nullptr, beff, 256, 256);
    mm_kernel<<<dim3(2, 64, BQ), 256, SMEM_MM>>>(W_cq, aa, beff, 1,
                                                 xb, XT, attn, XT,
                                                 nullptr, 0, 256, 256, 0);
    gn_stats_kernel<<<BQ*32, 256>>>(c, 16, mu, rs);
    affine_kernel<<<BQ, 256>>>(nm3_g, nm3_b, mu, rs, aa, ab, 512);
    beff_kernel<<<dim3(512, BQ), 128>>>(W_ckv, ab, nullptr, beff, 512, 512);
    mm_kernel<<<dim3(4, 64, BQ), 256, SMEM_MM>>>(W_ckv, aa, beff, 1,
                                                 c, (size_t)512*TT, big, (size_t)512*TT,
                                                 nullptr, 0, 512, 512, 0);
    ksm_stats_kernel<<<dim3(256, BQ), 256>>>(big, (size_t)512*TT, kmax, kinv);
    ctx_kernel<<<dim3(64, 8), 256>>>(big, (size_t)512*TT, 0, 256, kmax, kinv, ctxp);
    ctx_reduce_kernel<<<256, 256>>>(ctxp, ctx);
    attn_out_kernel<<<dim3(64, 32), 256>>>(attn, XT, 0, ctx, big, XT);
    mm_kernel<<<dim3(2, 64, BQ), 256, SMEM_MM>>>(W_co, nullptr, b_co, 0,
                                                 big, XT, so, XT,
                                                 nullptr, 0, 256, 256, 0);
    gn_stats_kernel<<<BQ*32, 256>>>(so, 8, mu, rs);
    gn_add_kernel<<<16384, 256>>>(so, ca_g, ca_b, mu, rs, xb, xb);

    // ================= Phase 3: SiLU MLP =================
    gn_stats_kernel<<<BQ*32, 256>>>(xb, 8, mu, rs);
    affine_kernel<<<BQ, 256>>>(nm2_g, nm2_b, mu, rs, aa, ab, 256);
    beff_kernel<<<dim3(640, BQ), 128>>>(W_m1, ab, b_m1, beff, 640, 256);
    mm_kernel<<<dim3(5, 64, BQ), 256, SMEM_MM>>>(W_m1, aa, beff, 1,
                                                 xb, XT, big, (size_t)640*TT,
                                                 nullptr, 0, 640, 256, 1 /*silu*/);
    mm_kernel<<<dim3(2, 64, BQ), 256, SMEM_MM>>>(W_m2, nullptr, b_m2, 0,
                                                 big, (size_t)640*TT, out, XT,
                                                 xb, XT, 256, 640, 2 /*residual*/);
}

// round 8
// speedup vs baseline: 1.7721x; 1.1709x over previous
#include <cuda_runtime.h>
#include <cuda_bf16.h>
#include <cstdint>

#define BQ 8
#define DIMC 256
#define TT 8192
#define NH 8
#define EPSV 1e-5f

// SMEM layout per stage: Ahi[128x40bf16]=10240B, Alo=10240B, Bhi[32x136bf16]=8704B, Blo=8704B
#define STG_BYTES 37888
#define SMEM_MM (2 * STG_BYTES)

// ---------------- scratch (device globals) ----------------
__device__ float g_big [(size_t)BQ * 768 * TT];
__device__ float g_attn[(size_t)BQ * DIMC * TT];
__device__ float g_so  [(size_t)BQ * DIMC * TT];
__device__ float g_x   [(size_t)BQ * DIMC * TT];
__device__ float g_beff[BQ * 1024];
__device__ float g_mu  [BQ * 32];
__device__ float g_rs  [BQ * 32];
__device__ float g_affa[BQ * 512];
__device__ float g_affb[BQ * 512];
__device__ float g_kmax[BQ * 256];
__device__ float g_kinv[BQ * 256];
__device__ float g_ctx [BQ * NH * 32 * 32];
__device__ float g_ctxp[8 * BQ * NH * 32 * 32];

// ==================== PTX helpers (plain sm_80+ instructions only) ====================
__device__ __forceinline__ unsigned s2u(const void* p) {
    unsigned a;
    asm("{ .reg .u64 t; cvta.to.shared.u64 t, %1; cvt.u32.u64 %0, t; }" : "=r"(a) : "l"(p));
    return a;
}
#define LDSM4(r, addr) \
    asm volatile("ldmatrix.sync.aligned.m8n8.x4.shared.b16 {%0,%1,%2,%3}, [%4];" \
        : "=r"((r)[0]), "=r"((r)[1]), "=r"((r)[2]), "=r"((r)[3]) : "r"(addr))
#define LDSM4T(r, addr) \
    asm volatile("ldmatrix.sync.aligned.m8n8.x4.trans.shared.b16 {%0,%1,%2,%3}, [%4];" \
        : "=r"((r)[0]), "=r"((r)[1]), "=r"((r)[2]), "=r"((r)[3]) : "r"(addr))
__device__ __forceinline__ void mma_bf16(float* c, const unsigned* a, const unsigned* b) {
    asm volatile("mma.sync.aligned.m16n8k16.row.col.f32.bf16.bf16.f32 "
        "{%0,%1,%2,%3}, {%4,%5,%6,%7}, {%8,%9}, {%0,%1,%2,%3};"
        : "+f"(c[0]), "+f"(c[1]), "+f"(c[2]), "+f"(c[3])
        : "r"(a[0]), "r"(a[1]), "r"(a[2]), "r"(a[3]), "r"(b[0]), "r"(b[1]));
}
__device__ __forceinline__ unsigned pack2(__nv_bfloat16 lo, __nv_bfloat16 hi) {
    __nv_bfloat162 t = __halves2bfloat162(lo, hi);   // .x = lo halfword
    return *(unsigned*)&t;
}

// ==================== tensor-core GEMM (mma.sync bf16 hi/lo split) ====================
// Y[b][m][n] = sum_k (W[m][k]*aS[b][k]) * X[b][k][n] + bias[m] [silu | +R]
// Changes vs R7: 1 sync/iter, fused load+convert+store, per-mf fragment loads,
// launch_bounds(256,2) to get 2 CTAs/SM.
__global__ __launch_bounds__(256, 2)
void mm_kernel(const float* __restrict__ W, const float* __restrict__ aS,
               const float* __restrict__ bias, int perB,
               const float* __restrict__ X, size_t xStrideB,
               float* __restrict__ Y, size_t yStrideB,
               const float* __restrict__ R, size_t rStrideB,
               int M, int K, int ep)
{
    extern __shared__ char smem[];
    const unsigned sb = s2u(smem);
    const int tid = threadIdx.x, lane = tid & 31, wid = tid >> 5;
    const int wr = wid >> 2, wc = wid & 3;           // warp grid 2(m) x 4(n)
    const int mt = blockIdx.x, nt = blockIdx.y, b = blockIdx.z;
    const int m0 = mt * 128, n0 = nt * 128;
    const float* Xb = X + (size_t)b * xStrideB;
    const float* aSb = aS ? aS + b * K : nullptr;

    float acc[4][4][4];
    #pragma unroll
    for (int i = 0; i < 4; i++)
        #pragma unroll
        for (int j = 0; j < 4; j++)
            #pragma unroll
            for (int r = 0; r < 4; r++) acc[i][j][r] = 0.f;

    const unsigned aoff = (lane & 15) * 80  + (lane >> 4) * 16;
    const unsigned boff = (lane & 15) * 272 + (lane >> 4) * 16;
    const int nk = K >> 5;

    // fused: gmem load -> affine -> bf16 hi/lo split -> smem store
    auto gls = [&](int kc, int st) {
        size_t base = (size_t)st * STG_BYTES;
        #pragma unroll
        for (int u = 0; u < 4; u++) {
            int f = tid + u * 256;
            int ra = f >> 3, ca = (f & 7) * 4;
            float4 va = *(const float4*)&W[(size_t)(m0 + ra) * K + kc * 32 + ca];
            int rb = f >> 5, cb = (f & 31) * 4;
            float4 vb = *(const float4*)&Xb[(size_t)(kc*32 + rb) * TT + n0 + cb];
            if (aSb) {
                va.x *= aSb[kc*32 + ca];   va.y *= aSb[kc*32 + ca+1];
                va.z *= aSb[kc*32 + ca+2]; va.w *= aSb[kc*32 + ca+3];
            }
            {   // A
                __nv_bfloat16 hx = __float2bfloat16(va.x), hy = __float2bfloat16(va.y);
                __nv_bfloat16 hz = __float2bfloat16(va.z), hw = __float2bfloat16(va.w);
                float lx = va.x - __bfloat162float(hx), ly = va.y - __bfloat162float(hy);
                float lz = va.z - __bfloat162float(hz), lw = va.w - __bfloat162float(hw);
                size_t off = base + ra * 80 + (f & 7) * 8;
                *(uint2*)(smem + off) = make_uint2(pack2(hx, hy), pack2(hz, hw));
                *(uint2*)(smem + off + 10240) = make_uint2(
                    pack2(__float2bfloat16(lx), __float2bfloat16(ly)),
                    pack2(__float2bfloat16(lz), __float2bfloat16(lw)));
            }
            {   // B
                __nv_bfloat16 hx = __float2bfloat16(vb.x), hy = __float2bfloat16(vb.y);
                __nv_bfloat16 hz = __float2bfloat16(vb.z), hw = __float2bfloat16(vb.w);
                float lx = vb.x - __bfloat162float(hx), ly = vb.y - __bfloat162float(hy);
                float lz = vb.z - __bfloat162float(hz), lw = vb.w - __bfloat162float(hw);
                size_t off = base + 20480 + rb * 272 + (f & 31) * 8;
                *(uint2*)(smem + off) = make_uint2(pack2(hx, hy), pack2(hz, hw));
                *(uint2*)(smem + off + 8704) = make_uint2(
                    pack2(__float2bfloat16(lx), __float2bfloat16(ly)),
                    pack2(__float2bfloat16(lz), __float2bfloat16(lw)));
            }
        }
    };

    auto compute = [&](int st) {
        unsigned stb = sb + st * STG_BYTES;
        #pragma unroll
        for (int ks = 0; ks < 2; ks++) {
            unsigned bh[2][4], bl[2][4];
            #pragma unroll
            for (int np = 0; np < 2; np++) {
                unsigned adr = stb + 20480 + ks * 4352 + wc * 64 + np * 32 + boff;
                LDSM4T(bh[np], adr);
                LDSM4T(bl[np], adr + 8704);
            }
            #pragma unroll
            for (int mf = 0; mf < 4; mf++) {
                unsigned ah[4], al[4];
                unsigned adr = stb + wr * 5120 + mf * 1280 + ks * 32 + aoff;
                LDSM4(ah, adr);
                LDSM4(al, adr + 10240);
                #pragma unroll
                for (int nf = 0; nf < 4; nf++) {
                    const unsigned* bp = &bh[nf >> 1][(nf & 1) * 2];
                    const unsigned* lp = &bl[nf >> 1][(nf & 1) * 2];
                    mma_bf16(acc[mf][nf], ah, bp);
                    mma_bf16(acc[mf][nf], al, bp);
                    mma_bf16(acc[mf][nf], ah, lp);
                }
            }
        }
    };

    gls(0, 0);
    __syncthreads();
    for (int i = 0; i < nk; i++) {
        compute(i & 1);
        if (i + 1 < nk) gls(i + 1, (i + 1) & 1);   // writes the OTHER stage: no hazard
        __syncthreads();
    }

    // epilogue: direct v2 stores (each lane-quad fills one 32B sector)
    const float* biasB = bias + (perB ? (size_t)b * M : 0);
    float* Yb = Y + (size_t)b * yStrideB;
    const float* Rb = R ? R + (size_t)b * rStrideB : nullptr;
    #pragma unroll
    for (int mf = 0; mf < 4; mf++) {
        int gm = m0 + wr * 64 + mf * 16 + (lane >> 2);
        float bv0 = biasB[gm], bv1 = biasB[gm + 8];
        #pragma unroll
        for (int nf = 0; nf < 4; nf++) {
            int gn = n0 + wc * 32 + nf * 8 + (lane & 3) * 2;
            float* a4 = acc[mf][nf];
            float2 v0 = make_float2(a4[0] + bv0, a4[1] + bv0);
            float2 v1 = make_float2(a4[2] + bv1, a4[3] + bv1);
            if (ep == 1) {
                v0.x /= (1.f + expf(-v0.x)); v0.y /= (1.f + expf(-v0.y));
                v1.x /= (1.f + expf(-v1.x)); v1.y /= (1.f + expf(-v1.y));
            } else if (ep == 2) {
                float2 r0 = *(const float2*)&Rb[(size_t)gm * TT + gn];
                float2 r1 = *(const float2*)&Rb[(size_t)(gm + 8) * TT + gn];
                v0.x += r0.x; v0.y += r0.y; v1.x += r1.x; v1.y += r1.y;
            }
            *(float2*)&Yb[(size_t)gm * TT + gn] = v0;
            *(float2*)&Yb[(size_t)(gm + 8) * TT + gn] = v1;
        }
    }
}

// ==================== group-norm / attention kernels (proven) ====================
__global__ void gn_stats_kernel(const float* __restrict__ x, int GC,
                                float* __restrict__ mu, float* __restrict__ rs)
{
    const size_t n = (size_t)GC * TT;
    const float4* x4 = (const float4*)(x + (size_t)blockIdx.x * n);
    const int n4 = (int)(n >> 2);
    float s = 0.f, sq = 0.f;
    for (int i = threadIdx.x; i < n4; i += 256) {
        float4 v = x4[i];
        s += (v.x + v.y) + (v.z + v.w);
        sq += v.x*v.x + v.y*v.y + v.z*v.z + v.w*v.w;
    }
    __shared__ float sh1[8], sh2[8];
    int lane = threadIdx.x & 31, w = threadIdx.x >> 5;
    #pragma unroll
    for (int o = 16; o > 0; o >>= 1) {
        s += __shfl_xor_sync(0xffffffffu, s, o);
        sq += __shfl_xor_sync(0xffffffffu, sq, o);
    }
    if (lane == 0) { sh1[w] = s; sh2[w] = sq; }
    __syncthreads();
    if (threadIdx.x < 8) {
        s = sh1[threadIdx.x]; sq = sh2[threadIdx.x];
        #pragma unroll
        for (int o = 4; o > 0; o >>= 1) {
            s += __shfl_xor_sync(0xffu, s, o);
            sq += __shfl_xor_sync(0xffu, sq, o);
        }
        if (threadIdx.x == 0) {
            float inv_n = 1.f / (float)n;
            float m = s * inv_n;
            float var = sq * inv_n - m * m;
            mu[blockIdx.x] = m;
            rs[blockIdx.x] = rsqrtf(fmaxf(var, 0.f) + EPSV);
        }
    }
}

__global__ void affine_kernel(const float* __restrict__ g, const float* __restrict__ be,
                              const float* __restrict__ mu, const float* __restrict__ rs,
                              float* __restrict__ a, float* __restrict__ bb, int C)
{
    int b = blockIdx.x;
    int GC = C >> 5;
    for (int c = threadIdx.x; c < C; c += blockDim.x) {
        int grp = c / GC;
        float r = rs[b*32 + grp], m = mu[b*32 + grp];
        float av = g[c] * r;
        a [b*C + c] = av;
        bb[b*C + c] = be[c] - m * av;
    }
}

__global__ void beff_kernel(const float* __restrict__ W, const float* __restrict__ bbv,
                            const float* __restrict__ bias, float* __restrict__ beff,
                            int M, int K)
{
    int m = blockIdx.x, b = blockIdx.y;
    float s = 0.f;
    for (int k = threadIdx.x; k < K; k += 128)
        s += W[(size_t)m*K + k] * bbv[b*K + k];
    __shared__ float sh[4];
    int lane = threadIdx.x & 31, w = threadIdx.x >> 5;
    #pragma unroll
    for (int o = 16; o > 0; o >>= 1) s += __shfl_xor_sync(0xffffffffu, s, o);
    if (lane == 0) sh[w] = s;
    __syncthreads();
    if (threadIdx.x == 0)
        beff[(size_t)b*M + m] = sh[0] + sh[1] + sh[2] + sh[3] + (bias ? bias[m] : 0.f);
}

__global__ void ksm_stats_kernel(const float* __restrict__ kbase, size_t strideB,
                                 float* __restrict__ kmax, float* __restrict__ kinv)
{
    int r = blockIdx.x, b = blockIdx.y;
    const float4* p4 = (const float4*)(kbase + (size_t)b * strideB + (size_t)r * TT);
    float mx = -1e30f;
    for (int i = threadIdx.x; i < TT/4; i += 256) {
        float4 v = p4[i];
        mx = fmaxf(mx, fmaxf(fmaxf(v.x, v.y), fmaxf(v.z, v.w)));
    }
    __shared__ float sh[8];
    __shared__ float bmax, bsum;
    int lane = threadIdx.x & 31, w = threadIdx.x >> 5;
    #pragma unroll
    for (int o = 16; o > 0; o >>= 1) mx = fmaxf(mx, __shfl_xor_sync(0xffffffffu, mx, o));
    if (lane == 0) sh[w] = mx;
    __syncthreads();
    if (threadIdx.x < 8) {
        mx = sh[threadIdx.x];
        #pragma unroll
        for (int o = 4; o > 0; o >>= 1) mx = fmaxf(mx, __shfl_xor_sync(0xffu, mx, o));
        if (threadIdx.x == 0) bmax = mx;
    }
    __syncthreads();
    float m = bmax;
    float s = 0.f;
    for (int i = threadIdx.x; i < TT/4; i += 256) {
        float4 v = p4[i];
        s += expf(v.x - m) + expf(v.y - m) + expf(v.z - m) + expf(v.w - m);
    }
    #pragma unroll
    for (int o = 16; o > 0; o >>= 1) s += __shfl_xor_sync(0xffffffffu, s, o);
    if (lane == 0) sh[w] = s;
    __syncthreads();
    if (threadIdx.x < 8) {
        s = sh[threadIdx.x];
        #pragma unroll
        for (int o = 4; o > 0; o >>= 1) s += __shfl_xor_sync(0xffu, s, o);
        if (threadIdx.x == 0) bsum = s;
    }
    __syncthreads();
    if (threadIdx.x == 0) { kmax[b*256 + r] = m; kinv[b*256 + r] = 1.f / bsum; }
}

__global__ void ctx_kernel(const float* __restrict__ kv, size_t strideB, int koff, int voff,
                           const float* __restrict__ kmax, const float* __restrict__ kinv,
                           float* __restrict__ cpart)
{
    int bh = blockIdx.x;
    int slice = blockIdx.y;
    int b = bh / NH, h = bh % NH;
    __shared__ float ks[32][65], vs[32][65];
    __shared__ float km[32], ki[32];
    int tid = threadIdx.x;
    if (tid < 32) {
        km[tid] = kmax[b*256 + h*32 + tid];
        ki[tid] = kinv[b*256 + h*32 + tid];
    }
    const float* kp = kv + (size_t)b*strideB + (size_t)(koff + h*32)*TT + slice*1024;
    const float* vp = kv + (size_t)b*strideB + (size_t)(voff + h*32)*TT + slice*1024;
    int d = tid >> 3, e0 = (tid & 7) * 4;
    float c0 = 0.f, c1 = 0.f, c2 = 0.f, c3 = 0.f;
    for (int tc = 0; tc < 1024; tc += 64) {
        __syncthreads();
        for (int i = tid; i < 32*64; i += 256) {
            int r = i >> 6, t = i & 63;
            ks[r][t] = expf(kp[(size_t)r*TT + tc + t] - km[r]) * ki[r];
            vs[r][t] = vp[(size_t)r*TT + tc + t];
        }
        __syncthreads();
        #pragma unroll 8
        for (int t = 0; t < 64; t++) {
            float kd = ks[d][t];
            c0 += kd * vs[e0+0][t];
            c1 += kd * vs[e0+1][t];
            c2 += kd * vs[e0+2][t];
            c3 += kd * vs[e0+3][t];
        }
    }
    float* cp = cpart + (size_t)slice*65536 + (size_t)bh*1024 + d*32 + e0;
    cp[0] = c0; cp[1] = c1; cp[2] = c2; cp[3] = c3;
}

__global__ void ctx_reduce_kernel(const float* __restrict__ cpart, float* __restrict__ ctx)
{
    int i = blockIdx.x * 256 + threadIdx.x;
    float s = 0.f;
    #pragma unroll
    for (int sl = 0; sl < 8; sl++) s += cpart[(size_t)sl*65536 + i];
    ctx[i] = s;
}

__global__ void attn_out_kernel(const float* __restrict__ q, size_t strideB, int qoff,
                                const float* __restrict__ ctx,
                                float* __restrict__ o, size_t oStrideB)
{
    int bh = blockIdx.x;
    int b = bh / NH, h = bh % NH;
    int t = blockIdx.y * 256 + threadIdx.x;
    __shared__ float cs[32][32];
    for (int i = threadIdx.x; i < 1024; i += 256)
        cs[i >> 5][i & 31] = ctx[(size_t)bh*1024 + i];
    __syncthreads();
    const float* qp = q + (size_t)b*strideB + (size_t)(qoff + h*32)*TT + t;
    float p[32];
    float mx = -1e30f;
    #pragma unroll
    for (int d = 0; d < 32; d++) { p[d] = qp[(size_t)d*TT]; mx = fmaxf(mx, p[d]); }
    float s = 0.f;
    #pragma unroll
    for (int d = 0; d < 32; d++) { p[d] = expf(p[d] - mx); s += p[d]; }
    float inv = 0.17677669529663687f / s;
    #pragma unroll
    for (int d = 0; d < 32; d++) p[d] *= inv;
    float accv[32];
    #pragma unroll
    for (int e = 0; e < 32; e++) accv[e] = 0.f;
    #pragma unroll
    for (int d = 0; d < 32; d++) {
        float pd = p[d];
        #pragma unroll
        for (int e4 = 0; e4 < 8; e4++) {
            float4 cv = *(const float4*)&cs[d][e4*4];
            accv[e4*4+0] += cv.x * pd;
            accv[e4*4+1] += cv.y * pd;
            accv[e4*4+2] += cv.z * pd;
            accv[e4*4+3] += cv.w * pd;
        }
    }
    float* op = o + (size_t)b*oStrideB + (size_t)(h*32)*TT + t;
    #pragma unroll
    for (int e = 0; e < 32; e++) op[(size_t)e*TT] = accv[e];
}

__global__ void gn_add_kernel(const float* __restrict__ v,
                              const float* __restrict__ gamma, const float* __restrict__ beta,
                              const float* __restrict__ mu, const float* __restrict__ rs,
                              const float* __restrict__ r, float* __restrict__ y)
{
    size_t i = ((size_t)blockIdx.x * 256 + threadIdx.x) * 4;
    int c = (int)((i / TT) % DIMC);
    int b = (int)(i / ((size_t)DIMC * TT));
    int grp = c >> 3;
    float rr = rs[b*32 + grp], m = mu[b*32 + grp];
    float sc = gamma[c] * rr;
    float sh = beta[c] - m * sc;
    float4 vv = *(const float4*)(v + i);
    float4 rv = *(const float4*)(r + i);
    float4 o;
    o.x = vv.x * sc + sh + rv.x;
    o.y = vv.y * sc + sh + rv.y;
    o.z = vv.z * sc + sh + rv.z;
    o.w = vv.w * sc + sh + rv.w;
    *(float4*)(y + i) = o;
}

// ==================== host orchestration ====================
extern "C" void kernel_launch(void* const* d_in, const int* in_sizes, int n_in,
                              void* d_out, int out_size)
{
    const float* x     = (const float*)d_in[0];
    const float* c     = (const float*)d_in[1];
    const float* W_qkv = (const float*)d_in[2];
    const float* W_so  = (const float*)d_in[3];
    const float* b_so  = (const float*)d_in[4];
    const float* sa_g  = (const float*)d_in[5];
    const float* sa_b  = (const float*)d_in[6];
    const float* W_cq  = (const float*)d_in[7];
    const float* W_ckv = (const float*)d_in[8];
    const float* W_co  = (const float*)d_in[9];
    const float* b_co  = (const float*)d_in[10];
    const float* ca_g  = (const float*)d_in[11];
    const float* ca_b  = (const float*)d_in[12];
    const float* W_m1  = (const float*)d_in[13];
    const float* b_m1  = (const float*)d_in[14];
    const float* W_m2  = (const float*)d_in[15];
    const float* b_m2  = (const float*)d_in[16];
    const float* nm_g  = (const float*)d_in[17];
    const float* nm_b  = (const float*)d_in[18];
    const float* nm1_g = (const float*)d_in[19];
    const float* nm1_b = (const float*)d_in[20];
    const float* nm2_g = (const float*)d_in[21];
    const float* nm2_b = (const float*)d_in[22];
    const float* nm3_g = (const float*)d_in[23];
    const float* nm3_b = (const float*)d_in[24];
    float* out = (float*)d_out;

    float *big, *attn, *so, *xb, *beff, *mu, *rs, *aa, *ab, *kmax, *kinv, *ctx, *ctxp;
    cudaGetSymbolAddress((void**)&big,  g_big);
    cudaGetSymbolAddress((void**)&attn, g_attn);
    cudaGetSymbolAddress((void**)&so,   g_so);
    cudaGetSymbolAddress((void**)&xb,   g_x);
    cudaGetSymbolAddress((void**)&beff, g_beff);
    cudaGetSymbolAddress((void**)&mu,   g_mu);
    cudaGetSymbolAddress((void**)&rs,   g_rs);
    cudaGetSymbolAddress((void**)&aa,   g_affa);
    cudaGetSymbolAddress((void**)&ab,   g_affb);
    cudaGetSymbolAddress((void**)&kmax, g_kmax);
    cudaGetSymbolAddress((void**)&kinv, g_kinv);
    cudaGetSymbolAddress((void**)&ctx,  g_ctx);
    cudaGetSymbolAddress((void**)&ctxp, g_ctxp);

    static bool attr_set = false;
    if (!attr_set) {
        cudaFuncSetAttribute(mm_kernel, cudaFuncAttributeMaxDynamicSharedMemorySize, SMEM_MM);
        attr_set = true;
    }

    const size_t XT = (size_t)DIMC * TT;

    // ================= Phase 1: self linear attention =================
    gn_stats_kernel<<<BQ*32, 256>>>(x, 8, mu, rs);
    affine_kernel<<<BQ, 256>>>(nm_g, nm_b, mu, rs, aa, ab, 256);
    beff_kernel<<<dim3(768, BQ), 128>>>(W_qkv, ab, nullptr, beff, 768, 256);
    mm_kernel<<<dim3(6, 64, BQ), 256, SMEM_MM>>>(W_qkv, aa, beff, 1,
                                                 x, XT, big, (size_t)768*TT,
                                                 nullptr, 0, 768, 256, 0);
    ksm_stats_kernel<<<dim3(256, BQ), 256>>>(big + (size_t)256*TT, (size_t)768*TT, kmax, kinv);
    ctx_kernel<<<dim3(64, 8), 256>>>(big, (size_t)768*TT, 256, 512, kmax, kinv, ctxp);
    ctx_reduce_kernel<<<256, 256>>>(ctxp, ctx);
    attn_out_kernel<<<dim3(64, 32), 256>>>(big, (size_t)768*TT, 0, ctx, attn, XT);
    mm_kernel<<<dim3(2, 64, BQ), 256, SMEM_MM>>>(W_so, nullptr, b_so, 0,
                                                 attn, XT, so, XT,
                                                 nullptr, 0, 256, 256, 0);
    gn_stats_kernel<<<BQ*32, 256>>>(so, 8, mu, rs);
    gn_add_kernel<<<16384, 256>>>(so, sa_g, sa_b, mu, rs, x, xb);

    // ================= Phase 2: cross linear attention =================
    gn_stats_kernel<<<BQ*32, 256>>>(xb, 8, mu, rs);
    affine_kernel<<<BQ, 256>>>(nm1_g, nm1_b, mu, rs, aa, ab, 256);
    beff_kernel<<<dim3(256, BQ), 128>>>(W_cq, ab, nullptr, beff, 256, 256);
    mm_kernel<<<dim3(2, 64, BQ), 256, SMEM_MM>>>(W_cq, aa, beff, 1,
                                                 xb, XT, attn, XT,
                                                 nullptr, 0, 256, 256, 0);
    gn_stats_kernel<<<BQ*32, 256>>>(c, 16, mu, rs);
    affine_kernel<<<BQ, 256>>>(nm3_g, nm3_b, mu, rs, aa, ab, 512);
    beff_kernel<<<dim3(512, BQ), 128>>>(W_ckv, ab, nullptr, beff, 512, 512);
    mm_kernel<<<dim3(4, 64, BQ), 256, SMEM_MM>>>(W_ckv, aa, beff, 1,
                                                 c, (size_t)512*TT, big, (size_t)512*TT,
                                                 nullptr, 0, 512, 512, 0);
    ksm_stats_kernel<<<dim3(256, BQ), 256>>>(big, (size_t)512*TT, kmax, kinv);
    ctx_kernel<<<dim3(64, 8), 256>>>(big, (size_t)512*TT, 0, 256, kmax, kinv, ctxp);
    ctx_reduce_kernel<<<256, 256>>>(ctxp, ctx);
    attn_out_kernel<<<dim3(64, 32), 256>>>(attn, XT, 0, ctx, big, XT);
    mm_kernel<<<dim3(2, 64, BQ), 256, SMEM_MM>>>(W_co, nullptr, b_co, 0,
                                                 big, XT, so, XT,
                                                 nullptr, 0, 256, 256, 0);
    gn_stats_kernel<<<BQ*32, 256>>>(so, 8, mu, rs);
    gn_add_kernel<<<16384, 256>>>(so, ca_g, ca_b, mu, rs, xb, xb);

    // ================= Phase 3: SiLU MLP =================
    gn_stats_kernel<<<BQ*32, 256>>>(xb, 8, mu, rs);
    affine_kernel<<<BQ, 256>>>(nm2_g, nm2_b, mu, rs, aa, ab, 256);
    beff_kernel<<<dim3(640, BQ), 128>>>(W_m1, ab, b_m1, beff, 640, 256);
    mm_kernel<<<dim3(5, 64, BQ), 256, SMEM_MM>>>(W_m1, aa, beff, 1,
                                                 xb, XT, big, (size_t)640*TT,
                                                 nullptr, 0, 640, 256, 1 /*silu*/);
    mm_kernel<<<dim3(2, 64, BQ), 256, SMEM_MM>>>(W_m2, nullptr, b_m2, 0,
                                                 big, (size_t)640*TT, out, XT,
                                                 xb, XT, 256, 640, 2 /*residual*/);
}

// round 9
// speedup vs baseline: 1.8066x; 1.0195x over previous
#include <cuda_runtime.h>
#include <cuda_bf16.h>
#include <cstdint>

#define BQ 8
#define DIMC 256
#define TT 8192
#define NH 8
#define EPSV 1e-5f

// bf16 stage: Ahi[128x40bf16]=10240B, Alo=10240B, Bhi[32x136bf16]=8704B, Blo=8704B
#define STG_BYTES 37888
// fp32 B ring: 2 slots x 16KB behind the two bf16 stages
#define RING_OFF  (2 * STG_BYTES)
#define SMEM_MM   (2 * STG_BYTES + 2 * 16384)

// ---------------- scratch (device globals) ----------------
__device__ float g_big [(size_t)BQ * 768 * TT];
__device__ float g_attn[(size_t)BQ * DIMC * TT];
__device__ float g_so  [(size_t)BQ * DIMC * TT];
__device__ float g_x   [(size_t)BQ * DIMC * TT];
__device__ float g_beff[BQ * 1024];
__device__ float g_mu  [BQ * 32];
__device__ float g_rs  [BQ * 32];
__device__ float g_affa[BQ * 512];
__device__ float g_affb[BQ * 512];
__device__ float g_kmax[BQ * 256];
__device__ float g_kinv[BQ * 256];
__device__ float g_ctx [BQ * NH * 32 * 32];
__device__ float g_ctxp[8 * BQ * NH * 32 * 32];

// ==================== PTX helpers (plain sm_80+ instructions only) ====================
__device__ __forceinline__ unsigned s2u(const void* p) {
    unsigned a;
    asm("{ .reg .u64 t; cvta.to.shared.u64 t, %1; cvt.u32.u64 %0, t; }" : "=r"(a) : "l"(p));
    return a;
}
#define LDSM4(r, addr) \
    asm volatile("ldmatrix.sync.aligned.m8n8.x4.shared.b16 {%0,%1,%2,%3}, [%4];" \
        : "=r"((r)[0]), "=r"((r)[1]), "=r"((r)[2]), "=r"((r)[3]) : "r"(addr))
#define LDSM4T(r, addr) \
    asm volatile("ldmatrix.sync.aligned.m8n8.x4.trans.shared.b16 {%0,%1,%2,%3}, [%4];" \
        : "=r"((r)[0]), "=r"((r)[1]), "=r"((r)[2]), "=r"((r)[3]) : "r"(addr))
__device__ __forceinline__ void mma_bf16(float* c, const unsigned* a, const unsigned* b) {
    asm volatile("mma.sync.aligned.m16n8k16.row.col.f32.bf16.bf16.f32 "
        "{%0,%1,%2,%3}, {%4,%5,%6,%7}, {%8,%9}, {%0,%1,%2,%3};"
        : "+f"(c[0]), "+f"(c[1]), "+f"(c[2]), "+f"(c[3])
        : "r"(a[0]), "r"(a[1]), "r"(a[2]), "r"(a[3]), "r"(b[0]), "r"(b[1]));
}
__device__ __forceinline__ unsigned pack2(__nv_bfloat16 lo, __nv_bfloat16 hi) {
    __nv_bfloat162 t = __halves2bfloat162(lo, hi);   // .x = lo halfword
    return *(unsigned*)&t;
}
__device__ __forceinline__ void cp16(unsigned saddr, const void* gaddr) {
    asm volatile("cp.async.cg.shared.global [%0], [%1], 16;" :: "r"(saddr), "l"(gaddr));
}
__device__ __forceinline__ void cp_commit() {
    asm volatile("cp.async.commit_group;");
}
template <int N>
__device__ __forceinline__ void cp_wait() {
    asm volatile("cp.async.wait_group %0;" :: "n"(N));
}

// ==================== tensor-core GEMM (mma.sync bf16 hi/lo split) ====================
// Y[b][m][n] = sum_k (W[m][k]*aS[b][k]) * X[b][k][n] + bias[m] [silu | +R]
// R9: B operand staged through cp.async fp32 ring (2-chunk lookahead);
//     A operand prefetched into 16 regs one chunk ahead. Barrier path is smem-only.
__global__ __launch_bounds__(256, 2)
void mm_kernel(const float* __restrict__ W, const float* __restrict__ aS,
               const float* __restrict__ bias, int perB,
               const float* __restrict__ X, size_t xStrideB,
               float* __restrict__ Y, size_t yStrideB,
               const float* __restrict__ R, size_t rStrideB,
               int M, int K, int ep)
{
    extern __shared__ char smem[];
    const unsigned sb = s2u(smem);
    const int tid = threadIdx.x, lane = tid & 31, wid = tid >> 5;
    const int wr = wid >> 2, wc = wid & 3;           // warp grid 2(m) x 4(n)
    const int mt = blockIdx.x, nt = blockIdx.y, b = blockIdx.z;
    const int m0 = mt * 128, n0 = nt * 128;
    const float* Xb = X + (size_t)b * xStrideB;
    const float* aSb = aS ? aS + b * K : nullptr;

    float acc[4][4][4];
    #pragma unroll
    for (int i = 0; i < 4; i++)
        #pragma unroll
        for (int j = 0; j < 4; j++)
            #pragma unroll
            for (int r = 0; r < 4; r++) acc[i][j][r] = 0.f;

    const unsigned aoff = (lane & 15) * 80  + (lane >> 4) * 16;
    const unsigned boff = (lane & 15) * 272 + (lane >> 4) * 16;
    const int nk = K >> 5;

    float4 rA[4];                       // A staging (one chunk ahead)

    // async-copy one fp32 B chunk (32k x 128n = 16KB) into ring slot kc&1
    auto cpB = [&](int kc) {
        unsigned slot = sb + RING_OFF + (kc & 1) * 16384;
        const float* src = Xb + (size_t)(kc * 32 + (tid >> 5)) * TT + n0 + (tid & 31) * 4;
        unsigned dst = slot + (tid >> 5) * 512 + (tid & 31) * 16;
        #pragma unroll
        for (int u = 0; u < 4; u++)
            cp16(dst + u * 4096, src + (size_t)(u * 8) * TT);
        cp_commit();
    };
    // load A chunk into rA
    auto gloadA = [&](int kc) {
        #pragma unroll
        for (int u = 0; u < 4; u++) {
            int f = tid + u * 256;
            int ra = f >> 3, ca = (f & 7) * 4;
            float4 v = *(const float4*)&W[(size_t)(m0 + ra) * K + kc * 32 + ca];
            if (aSb) {
                v.x *= aSb[kc*32 + ca];   v.y *= aSb[kc*32 + ca+1];
                v.z *= aSb[kc*32 + ca+2]; v.w *= aSb[kc*32 + ca+3];
            }
            rA[u] = v;
        }
    };
    // convert staged data into bf16 stage st: A from rA, B from ring slot kc&1
    auto cvt_store = [&](int kc, int st) {
        size_t base = (size_t)st * STG_BYTES;
        unsigned slot = sb + RING_OFF + (kc & 1) * 16384;
        #pragma unroll
        for (int u = 0; u < 4; u++) {
            int f = tid + u * 256;
            {   // A from registers
                float4 v = rA[u];
                __nv_bfloat16 hx = __float2bfloat16(v.x), hy = __float2bfloat16(v.y);
                __nv_bfloat16 hz = __float2bfloat16(v.z), hw = __float2bfloat16(v.w);
                float lx = v.x - __bfloat162float(hx), ly = v.y - __bfloat162float(hy);
                float lz = v.z - __bfloat162float(hz), lw = v.w - __bfloat162float(hw);
                size_t off = base + (f >> 3) * 80 + (f & 7) * 8;
                *(uint2*)(smem + off) = make_uint2(pack2(hx, hy), pack2(hz, hw));
                *(uint2*)(smem + off + 10240) = make_uint2(
                    pack2(__float2bfloat16(lx), __float2bfloat16(ly)),
                    pack2(__float2bfloat16(lz), __float2bfloat16(lw)));
            }
            {   // B from fp32 ring (smem)
                float4 v;
                unsigned sa = slot + (f >> 5) * 512 + (f & 31) * 16;
                asm volatile("ld.shared.v4.f32 {%0,%1,%2,%3}, [%4];"
                    : "=f"(v.x), "=f"(v.y), "=f"(v.z), "=f"(v.w) : "r"(sa));
                __nv_bfloat16 hx = __float2bfloat16(v.x), hy = __float2bfloat16(v.y);
                __nv_bfloat16 hz = __float2bfloat16(v.z), hw = __float2bfloat16(v.w);
                float lx = v.x - __bfloat162float(hx), ly = v.y - __bfloat162float(hy);
                float lz = v.z - __bfloat162float(hz), lw = v.w - __bfloat162float(hw);
                size_t off = base + 20480 + (f >> 5) * 272 + (f & 31) * 8;
                *(uint2*)(smem + off) = make_uint2(pack2(hx, hy), pack2(hz, hw));
                *(uint2*)(smem + off + 8704) = make_uint2(
                    pack2(__float2bfloat16(lx), __float2bfloat16(ly)),
                    pack2(__float2bfloat16(lz), __float2bfloat16(lw)));
            }
        }
    };

    auto compute = [&](int st) {
        unsigned stb = sb + st * STG_BYTES;
        #pragma unroll
        for (int ks = 0; ks < 2; ks++) {
            unsigned bh[2][4], bl[2][4];
            #pragma unroll
            for (int np = 0; np < 2; np++) {
                unsigned adr = stb + 20480 + ks * 4352 + wc * 64 + np * 32 + boff;
                LDSM4T(bh[np], adr);
                LDSM4T(bl[np], adr + 8704);
            }
            #pragma unroll
            for (int mf = 0; mf < 4; mf++) {
                unsigned ah[4], al[4];
                unsigned adr = stb + wr * 5120 + mf * 1280 + ks * 32 + aoff;
                LDSM4(ah, adr);
                LDSM4(al, adr + 10240);
                #pragma unroll
                for (int nf = 0; nf < 4; nf++) {
                    const unsigned* bp = &bh[nf >> 1][(nf & 1) * 2];
                    const unsigned* lp = &bl[nf >> 1][(nf & 1) * 2];
                    mma_bf16(acc[mf][nf], ah, bp);
                    mma_bf16(acc[mf][nf], al, bp);
                    mma_bf16(acc[mf][nf], ah, lp);
                }
            }
        }
    };

    // ---------------- prologue ----------------
    cpB(0);                       // group: chunk0
    cpB(1);                       // group: chunk1
    gloadA(0);
    cp_wait<1>();                 // chunk0 B resident
    __syncthreads();              // ring visible to all warps
    cvt_store(0, 0);
    gloadA(1);
    __syncthreads();              // stage0 built

    // ---------------- mainloop ----------------
    for (int i = 0; i < nk; i++) {
        if (i + 2 < nk) cpB(i + 2);            // fire-and-forget
        compute(i & 1);
        if (i + 1 < nk) {
            if (i + 2 < nk) cp_wait<1>(); else cp_wait<0>();   // chunk i+1 resident
            __syncthreads();                    // compute(i) reads done; ring slot safe
            cvt_store(i + 1, (i + 1) & 1);
            if (i + 2 < nk) gloadA(i + 2);
        }
        __syncthreads();                        // stage (i+1)&1 built
    }

    // ---------------- epilogue ----------------
    const float* biasB = bias + (perB ? (size_t)b * M : 0);
    float* Yb = Y + (size_t)b * yStrideB;
    const float* Rb = R ? R + (size_t)b * rStrideB : nullptr;
    #pragma unroll
    for (int mf = 0; mf < 4; mf++) {
        int gm = m0 + wr * 64 + mf * 16 + (lane >> 2);
        float bv0 = biasB[gm], bv1 = biasB[gm + 8];
        #pragma unroll
        for (int nf = 0; nf < 4; nf++) {
            int gn = n0 + wc * 32 + nf * 8 + (lane & 3) * 2;
            float* a4 = acc[mf][nf];
            float2 v0 = make_float2(a4[0] + bv0, a4[1] + bv0);
            float2 v1 = make_float2(a4[2] + bv1, a4[3] + bv1);
            if (ep == 1) {
                v0.x /= (1.f + expf(-v0.x)); v0.y /= (1.f + expf(-v0.y));
                v1.x /= (1.f + expf(-v1.x)); v1.y /= (1.f + expf(-v1.y));
            } else if (ep == 2) {
                float2 r0 = *(const float2*)&Rb[(size_t)gm * TT + gn];
                float2 r1 = *(const float2*)&Rb[(size_t)(gm + 8) * TT + gn];
                v0.x += r0.x; v0.y += r0.y; v1.x += r1.x; v1.y += r1.y;
            }
            *(float2*)&Yb[(size_t)gm * TT + gn] = v0;
            *(float2*)&Yb[(size_t)(gm + 8) * TT + gn] = v1;
        }
    }
}

// ==================== group-norm / attention kernels (proven) ====================
__global__ void gn_stats_kernel(const float* __restrict__ x, int GC,
                                float* __restrict__ mu, float* __restrict__ rs)
{
    const size_t n = (size_t)GC * TT;
    const float4* x4 = (const float4*)(x + (size_t)blockIdx.x * n);
    const int n4 = (int)(n >> 2);
    float s = 0.f, sq = 0.f;
    for (int i = threadIdx.x; i < n4; i += 256) {
        float4 v = x4[i];
        s += (v.x + v.y) + (v.z + v.w);
        sq += v.x*v.x + v.y*v.y + v.z*v.z + v.w*v.w;
    }
    __shared__ float sh1[8], sh2[8];
    int lane = threadIdx.x & 31, w = threadIdx.x >> 5;
    #pragma unroll
    for (int o = 16; o > 0; o >>= 1) {
        s += __shfl_xor_sync(0xffffffffu, s, o);
        sq += __shfl_xor_sync(0xffffffffu, sq, o);
    }
    if (lane == 0) { sh1[w] = s; sh2[w] = sq; }
    __syncthreads();
    if (threadIdx.x < 8) {
        s = sh1[threadIdx.x]; sq = sh2[threadIdx.x];
        #pragma unroll
        for (int o = 4; o > 0; o >>= 1) {
            s += __shfl_xor_sync(0xffu, s, o);
            sq += __shfl_xor_sync(0xffu, sq, o);
        }
        if (threadIdx.x == 0) {
            float inv_n = 1.f / (float)n;
            float m = s * inv_n;
            float var = sq * inv_n - m * m;
            mu[blockIdx.x] = m;
            rs[blockIdx.x] = rsqrtf(fmaxf(var, 0.f) + EPSV);
        }
    }
}

__global__ void affine_kernel(const float* __restrict__ g, const float* __restrict__ be,
                              const float* __restrict__ mu, const float* __restrict__ rs,
                              float* __restrict__ a, float* __restrict__ bb, int C)
{
    int b = blockIdx.x;
    int GC = C >> 5;
    for (int c = threadIdx.x; c < C; c += blockDim.x) {
        int grp = c / GC;
        float r = rs[b*32 + grp], m = mu[b*32 + grp];
        float av = g[c] * r;
        a [b*C + c] = av;
        bb[b*C + c] = be[c] - m * av;
    }
}

__global__ void beff_kernel(const float* __restrict__ W, const float* __restrict__ bbv,
                            const float* __restrict__ bias, float* __restrict__ beff,
                            int M, int K)
{
    int m = blockIdx.x, b = blockIdx.y;
    float s = 0.f;
    for (int k = threadIdx.x; k < K; k += 128)
        s += W[(size_t)m*K + k] * bbv[b*K + k];
    __shared__ float sh[4];
    int lane = threadIdx.x & 31, w = threadIdx.x >> 5;
    #pragma unroll
    for (int o = 16; o > 0; o >>= 1) s += __shfl_xor_sync(0xffffffffu, s, o);
    if (lane == 0) sh[w] = s;
    __syncthreads();
    if (threadIdx.x == 0)
        beff[(size_t)b*M + m] = sh[0] + sh[1] + sh[2] + sh[3] + (bias ? bias[m] : 0.f);
}

__global__ void ksm_stats_kernel(const float* __restrict__ kbase, size_t strideB,
                                 float* __restrict__ kmax, float* __restrict__ kinv)
{
    int r = blockIdx.x, b = blockIdx.y;
    const float4* p4 = (const float4*)(kbase + (size_t)b * strideB + (size_t)r * TT);
    float mx = -1e30f;
    for (int i = threadIdx.x; i < TT/4; i += 256) {
        float4 v = p4[i];
        mx = fmaxf(mx, fmaxf(fmaxf(v.x, v.y), fmaxf(v.z, v.w)));
    }
    __shared__ float sh[8];
    __shared__ float bmax, bsum;
    int lane = threadIdx.x & 31, w = threadIdx.x >> 5;
    #pragma unroll
    for (int o = 16; o > 0; o >>= 1) mx = fmaxf(mx, __shfl_xor_sync(0xffffffffu, mx, o));
    if (lane == 0) sh[w] = mx;
    __syncthreads();
    if (threadIdx.x < 8) {
        mx = sh[threadIdx.x];
        #pragma unroll
        for (int o = 4; o > 0; o >>= 1) mx = fmaxf(mx, __shfl_xor_sync(0xffu, mx, o));
        if (threadIdx.x == 0) bmax = mx;
    }
    __syncthreads();
    float m = bmax;
    float s = 0.f;
    for (int i = threadIdx.x; i < TT/4; i += 256) {
        float4 v = p4[i];
        s += expf(v.x - m) + expf(v.y - m) + expf(v.z - m) + expf(v.w - m);
    }
    #pragma unroll
    for (int o = 16; o > 0; o >>= 1) s += __shfl_xor_sync(0xffffffffu, s, o);
    if (lane == 0) sh[w] = s;
    __syncthreads();
    if (threadIdx.x < 8) {
        s = sh[threadIdx.x];
        #pragma unroll
        for (int o = 4; o > 0; o >>= 1) s += __shfl_xor_sync(0xffu, s, o);
        if (threadIdx.x == 0) bsum = s;
    }
    __syncthreads();
    if (threadIdx.x == 0) { kmax[b*256 + r] = m; kinv[b*256 + r] = 1.f / bsum; }
}

__global__ void ctx_kernel(const float* __restrict__ kv, size_t strideB, int koff, int voff,
                           const float* __restrict__ kmax, const float* __restrict__ kinv,
                           float* __restrict__ cpart)
{
    int bh = blockIdx.x;
    int slice = blockIdx.y;
    int b = bh / NH, h = bh % NH;
    __shared__ float ks[32][65], vs[32][65];
    __shared__ float km[32], ki[32];
    int tid = threadIdx.x;
    if (tid < 32) {
        km[tid] = kmax[b*256 + h*32 + tid];
        ki[tid] = kinv[b*256 + h*32 + tid];
    }
    const float* kp = kv + (size_t)b*strideB + (size_t)(koff + h*32)*TT + slice*1024;
    const float* vp = kv + (size_t)b*strideB + (size_t)(voff + h*32)*TT + slice*1024;
    int d = tid >> 3, e0 = (tid & 7) * 4;
    float c0 = 0.f, c1 = 0.f, c2 = 0.f, c3 = 0.f;
    for (int tc = 0; tc < 1024; tc += 64) {
        __syncthreads();
        for (int i = tid; i < 32*64; i += 256) {
            int r = i >> 6, t = i & 63;
            ks[r][t] = expf(kp[(size_t)r*TT + tc + t] - km[r]) * ki[r];
            vs[r][t] = vp[(size_t)r*TT + tc + t];
        }
        __syncthreads();
        #pragma unroll 8
        for (int t = 0; t < 64; t++) {
            float kd = ks[d][t];
            c0 += kd * vs[e0+0][t];
            c1 += kd * vs[e0+1][t];
            c2 += kd * vs[e0+2][t];
            c3 += kd * vs[e0+3][t];
        }
    }
    float* cp = cpart + (size_t)slice*65536 + (size_t)bh*1024 + d*32 + e0;
    cp[0] = c0; cp[1] = c1; cp[2] = c2; cp[3] = c3;
}

__global__ void ctx_reduce_kernel(const float* __restrict__ cpart, float* __restrict__ ctx)
{
    int i = blockIdx.x * 256 + threadIdx.x;
    float s = 0.f;
    #pragma unroll
    for (int sl = 0; sl < 8; sl++) s += cpart[(size_t)sl*65536 + i];
    ctx[i] = s;
}

__global__ void attn_out_kernel(const float* __restrict__ q, size_t strideB, int qoff,
                                const float* __restrict__ ctx,
                                float* __restrict__ o, size_t oStrideB)
{
    int bh = blockIdx.x;
    int b = bh / NH, h = bh % NH;
    int t = blockIdx.y * 256 + threadIdx.x;
    __shared__ float cs[32][32];
    for (int i = threadIdx.x; i < 1024; i += 256)
        cs[i >> 5][i & 31] = ctx[(size_t)bh*1024 + i];
    __syncthreads();
    const float* qp = q + (size_t)b*strideB + (size_t)(qoff + h*32)*TT + t;
    float p[32];
    float mx = -1e30f;
    #pragma unroll
    for (int d = 0; d < 32; d++) { p[d] = qp[(size_t)d*TT]; mx = fmaxf(mx, p[d]); }
    float s = 0.f;
    #pragma unroll
    for (int d = 0; d < 32; d++) { p[d] = expf(p[d] - mx); s += p[d]; }
    float inv = 0.17677669529663687f / s;
    #pragma unroll
    for (int d = 0; d < 32; d++) p[d] *= inv;
    float accv[32];
    #pragma unroll
    for (int e = 0; e < 32; e++) accv[e] = 0.f;
    #pragma unroll
    for (int d = 0; d < 32; d++) {
        float pd = p[d];
        #pragma unroll
        for (int e4 = 0; e4 < 8; e4++) {
            float4 cv = *(const float4*)&cs[d][e4*4];
            accv[e4*4+0] += cv.x * pd;
            accv[e4*4+1] += cv.y * pd;
            accv[e4*4+2] += cv.z * pd;
            accv[e4*4+3] += cv.w * pd;
        }
    }
    float* op = o + (size_t)b*oStrideB + (size_t)(h*32)*TT + t;
    #pragma unroll
    for (int e = 0; e < 32; e++) op[(size_t)e*TT] = accv[e];
}

__global__ void gn_add_kernel(const float* __restrict__ v,
                              const float* __restrict__ gamma, const float* __restrict__ beta,
                              const float* __restrict__ mu, const float* __restrict__ rs,
                              const float* __restrict__ r, float* __restrict__ y)
{
    size_t i = ((size_t)blockIdx.x * 256 + threadIdx.x) * 4;
    int c = (int)((i / TT) % DIMC);
    int b = (int)(i / ((size_t)DIMC * TT));
    int grp = c >> 3;
    float rr = rs[b*32 + grp], m = mu[b*32 + grp];
    float sc = gamma[c] * rr;
    float sh = beta[c] - m * sc;
    float4 vv = *(const float4*)(v + i);
    float4 rv = *(const float4*)(r + i);
    float4 o;
    o.x = vv.x * sc + sh + rv.x;
    o.y = vv.y * sc + sh + rv.y;
    o.z = vv.z * sc + sh + rv.z;
    o.w = vv.w * sc + sh + rv.w;
    *(float4*)(y + i) = o;
}

// ==================== host orchestration ====================
extern "C" void kernel_launch(void* const* d_in, const int* in_sizes, int n_in,
                              void* d_out, int out_size)
{
    const float* x     = (const float*)d_in[0];
    const float* c     = (const float*)d_in[1];
    const float* W_qkv = (const float*)d_in[2];
    const float* W_so  = (const float*)d_in[3];
    const float* b_so  = (const float*)d_in[4];
    const float* sa_g  = (const float*)d_in[5];
    const float* sa_b  = (const float*)d_in[6];
    const float* W_cq  = (const float*)d_in[7];
    const float* W_ckv = (const float*)d_in[8];
    const float* W_co  = (const float*)d_in[9];
    const float* b_co  = (const float*)d_in[10];
    const float* ca_g  = (const float*)d_in[11];
    const float* ca_b  = (const float*)d_in[12];
    const float* W_m1  = (const float*)d_in[13];
    const float* b_m1  = (const float*)d_in[14];
    const float* W_m2  = (const float*)d_in[15];
    const float* b_m2  = (const float*)d_in[16];
    const float* nm_g  = (const float*)d_in[17];
    const float* nm_b  = (const float*)d_in[18];
    const float* nm1_g = (const float*)d_in[19];
    const float* nm1_b = (const float*)d_in[20];
    const float* nm2_g = (const float*)d_in[21];
    const float* nm2_b = (const float*)d_in[22];
    const float* nm3_g = (const float*)d_in[23];
    const float* nm3_b = (const float*)d_in[24];
    float* out = (float*)d_out;

    float *big, *attn, *so, *xb, *beff, *mu, *rs, *aa, *ab, *kmax, *kinv, *ctx, *ctxp;
    cudaGetSymbolAddress((void**)&big,  g_big);
    cudaGetSymbolAddress((void**)&attn, g_attn);
    cudaGetSymbolAddress((void**)&so,   g_so);
    cudaGetSymbolAddress((void**)&xb,   g_x);
    cudaGetSymbolAddress((void**)&beff, g_beff);
    cudaGetSymbolAddress((void**)&mu,   g_mu);
    cudaGetSymbolAddress((void**)&rs,   g_rs);
    cudaGetSymbolAddress((void**)&aa,   g_affa);
    cudaGetSymbolAddress((void**)&ab,   g_affb);
    cudaGetSymbolAddress((void**)&kmax, g_kmax);
    cudaGetSymbolAddress((void**)&kinv, g_kinv);
    cudaGetSymbolAddress((void**)&ctx,  g_ctx);
    cudaGetSymbolAddress((void**)&ctxp, g_ctxp);

    static bool attr_set = false;
    if (!attr_set) {
        cudaFuncSetAttribute(mm_kernel, cudaFuncAttributeMaxDynamicSharedMemorySize, SMEM_MM);
        attr_set = true;
    }

    const size_t XT = (size_t)DIMC * TT;

    // ================= Phase 1: self linear attention =================
    gn_stats_kernel<<<BQ*32, 256>>>(x, 8, mu, rs);
    affine_kernel<<<BQ, 256>>>(nm_g, nm_b, mu, rs, aa, ab, 256);
    beff_kernel<<<dim3(768, BQ), 128>>>(W_qkv, ab, nullptr, beff, 768, 256);
    mm_kernel<<<dim3(6, 64, BQ), 256, SMEM_MM>>>(W_qkv, aa, beff, 1,
                                                 x, XT, big, (size_t)768*TT,
                                                 nullptr, 0, 768, 256, 0);
    ksm_stats_kernel<<<dim3(256, BQ), 256>>>(big + (size_t)256*TT, (size_t)768*TT, kmax, kinv);
    ctx_kernel<<<dim3(64, 8), 256>>>(big, (size_t)768*TT, 256, 512, kmax, kinv, ctxp);
    ctx_reduce_kernel<<<256, 256>>>(ctxp, ctx);
    attn_out_kernel<<<dim3(64, 32), 256>>>(big, (size_t)768*TT, 0, ctx, attn, XT);
    mm_kernel<<<dim3(2, 64, BQ), 256, SMEM_MM>>>(W_so, nullptr, b_so, 0,
                                                 attn, XT, so, XT,
                                                 nullptr, 0, 256, 256, 0);
    gn_stats_kernel<<<BQ*32, 256>>>(so, 8, mu, rs);
    gn_add_kernel<<<16384, 256>>>(so, sa_g, sa_b, mu, rs, x, xb);

    // ================= Phase 2: cross linear attention =================
    gn_stats_kernel<<<BQ*32, 256>>>(xb, 8, mu, rs);
    affine_kernel<<<BQ, 256>>>(nm1_g, nm1_b, mu, rs, aa, ab, 256);
    beff_kernel<<<dim3(256, BQ), 128>>>(W_cq, ab, nullptr, beff, 256, 256);
    mm_kernel<<<dim3(2, 64, BQ), 256, SMEM_MM>>>(W_cq, aa, beff, 1,
                                                 xb, XT, attn, XT,
                                                 nullptr, 0, 256, 256, 0);
    gn_stats_kernel<<<BQ*32, 256>>>(c, 16, mu, rs);
    affine_kernel<<<BQ, 256>>>(nm3_g, nm3_b, mu, rs, aa, ab, 512);
    beff_kernel<<<dim3(512, BQ), 128>>>(W_ckv, ab, nullptr, beff, 512, 512);
    mm_kernel<<<dim3(4, 64, BQ), 256, SMEM_MM>>>(W_ckv, aa, beff, 1,
                                                 c, (size_t)512*TT, big, (size_t)512*TT,
                                                 nullptr, 0, 512, 512, 0);
    ksm_stats_kernel<<<dim3(256, BQ), 256>>>(big, (size_t)512*TT, kmax, kinv);
    ctx_kernel<<<dim3(64, 8), 256>>>(big, (size_t)512*TT, 0, 256, kmax, kinv, ctxp);
    ctx_reduce_kernel<<<256, 256>>>(ctxp, ctx);
    attn_out_kernel<<<dim3(64, 32), 256>>>(attn, XT, 0, ctx, big, XT);
    mm_kernel<<<dim3(2, 64, BQ), 256, SMEM_MM>>>(W_co, nullptr, b_co, 0,
                                                 big, XT, so, XT,
                                                 nullptr, 0, 256, 256, 0);
    gn_stats_kernel<<<BQ*32, 256>>>(so, 8, mu, rs);
    gn_add_kernel<<<16384, 256>>>(so, ca_g, ca_b, mu, rs, xb, xb);

    // ================= Phase 3: SiLU MLP =================
    gn_stats_kernel<<<BQ*32, 256>>>(xb, 8, mu, rs);
    affine_kernel<<<BQ, 256>>>(nm2_g, nm2_b, mu, rs, aa, ab, 256);
    beff_kernel<<<dim3(640, BQ), 128>>>(W_m1, ab, b_m1, beff, 640, 256);
    mm_kernel<<<dim3(5, 64, BQ), 256, SMEM_MM>>>(W_m1, aa, beff, 1,
                                                 xb, XT, big, (size_t)640*TT,
                                                 nullptr, 0, 640, 256, 1 /*silu*/);
    mm_kernel<<<dim3(2, 64, BQ), 256, SMEM_MM>>>(W_m2, nullptr, b_m2, 0,
                                                 big, (size_t)640*TT, out, XT,
                                                 xb, XT, 256, 640, 2 /*residual*/);
}

// round 10
// speedup vs baseline: 2.1473x; 1.1886x over previous
#include <cuda_runtime.h>
#include <cuda_fp16.h>
#include <cstdint>

#define BQ 8
#define DIMC 256
#define TT 8192
#define NH 8
#define EPSV 1e-5f

// fp16 stage: A[128x40h]=10240B, Bhi[32x136h]=8704B, Blo=8704B
#define A_BYTES   10240
#define STG_BYTES 27648
// fp32 B ring: 2 slots x 16KB behind the two fp16 stages
#define RING_OFF  (2 * STG_BYTES)
#define SMEM_MM   (2 * STG_BYTES + 2 * 16384)

// ---------------- scratch (device globals) ----------------
__device__ float g_big [(size_t)BQ * 768 * TT];
__device__ float g_attn[(size_t)BQ * DIMC * TT];
__device__ float g_so  [(size_t)BQ * DIMC * TT];
__device__ float g_x   [(size_t)BQ * DIMC * TT];
__device__ float g_beff[BQ * 1024];
__device__ float g_mu  [BQ * 32];
__device__ float g_rs  [BQ * 32];
__device__ float g_affa[BQ * 512];
__device__ float g_affb[BQ * 512];
__device__ float g_kmax[BQ * 256];
__device__ float g_kinv[BQ * 256];
__device__ float g_ctx [BQ * NH * 32 * 32];
__device__ float g_ctxp[8 * BQ * NH * 32 * 32];

// ==================== PTX helpers (plain sm_80+ instructions only) ====================
__device__ __forceinline__ unsigned s2u(const void* p) {
    unsigned a;
    asm("{ .reg .u64 t; cvta.to.shared.u64 t, %1; cvt.u32.u64 %0, t; }" : "=r"(a) : "l"(p));
    return a;
}
#define LDSM4(r, addr) \
    asm volatile("ldmatrix.sync.aligned.m8n8.x4.shared.b16 {%0,%1,%2,%3}, [%4];" \
        : "=r"((r)[0]), "=r"((r)[1]), "=r"((r)[2]), "=r"((r)[3]) : "r"(addr))
#define LDSM4T(r, addr) \
    asm volatile("ldmatrix.sync.aligned.m8n8.x4.trans.shared.b16 {%0,%1,%2,%3}, [%4];" \
        : "=r"((r)[0]), "=r"((r)[1]), "=r"((r)[2]), "=r"((r)[3]) : "r"(addr))
__device__ __forceinline__ void mma_f16(float* c, const unsigned* a, const unsigned* b) {
    asm volatile("mma.sync.aligned.m16n8k16.row.col.f32.f16.f16.f32 "
        "{%0,%1,%2,%3}, {%4,%5,%6,%7}, {%8,%9}, {%0,%1,%2,%3};"
        : "+f"(c[0]), "+f"(c[1]), "+f"(c[2]), "+f"(c[3])
        : "r"(a[0]), "r"(a[1]), "r"(a[2]), "r"(a[3]), "r"(b[0]), "r"(b[1]));
}
__device__ __forceinline__ unsigned pack2h(__half lo, __half hi) {
    __half2 t = __halves2half2(lo, hi);   // .x = lo halfword
    return *(unsigned*)&t;
}
__device__ __forceinline__ void cp16(unsigned saddr, const void* gaddr) {
    asm volatile("cp.async.cg.shared.global [%0], [%1], 16;" :: "r"(saddr), "l"(gaddr));
}
__device__ __forceinline__ void cp_commit() {
    asm volatile("cp.async.commit_group;");
}
template <int N>
__device__ __forceinline__ void cp_wait() {
    asm volatile("cp.async.wait_group %0;" :: "n"(N));
}

// ==================== tensor-core GEMM (mma.sync fp16, B hi/lo split) ====================
// Y[b][m][n] = sum_k (W[m][k]*aS[b][k]) * X[k][n] + bias[m] [silu | +R]
// R10: fp16x2 — A single fp16, B split hi/lo; 2 MMA passes; 33% fewer MMAs,
//      33% less ldmatrix traffic vs bf16x3 (kernel was smem-crossbar bound).
__global__ __launch_bounds__(256, 2)
void mm_kernel(const float* __restrict__ W, const float* __restrict__ aS,
               const float* __restrict__ bias, int perB,
               const float* __restrict__ X, size_t xStrideB,
               float* __restrict__ Y, size_t yStrideB,
               const float* __restrict__ R, size_t rStrideB,
               int M, int K, int ep)
{
    extern __shared__ char smem[];
    const unsigned sb = s2u(smem);
    const int tid = threadIdx.x, lane = tid & 31, wid = tid >> 5;
    const int wr = wid >> 2, wc = wid & 3;           // warp grid 2(m) x 4(n)
    const int mt = blockIdx.x, nt = blockIdx.y, b = blockIdx.z;
    const int m0 = mt * 128, n0 = nt * 128;
    const float* Xb = X + (size_t)b * xStrideB;
    const float* aSb = aS ? aS + b * K : nullptr;

    float acc[4][4][4];
    #pragma unroll
    for (int i = 0; i < 4; i++)
        #pragma unroll
        for (int j = 0; j < 4; j++)
            #pragma unroll
            for (int r = 0; r < 4; r++) acc[i][j][r] = 0.f;

    const unsigned aoff = (lane & 15) * 80  + (lane >> 4) * 16;
    const unsigned boff = (lane & 15) * 272 + (lane >> 4) * 16;
    const int nk = K >> 5;

    float4 rA[4];                       // A staging (one chunk ahead)

    // async-copy one fp32 B chunk (32k x 128n = 16KB) into ring slot kc&1
    auto cpB = [&](int kc) {
        unsigned slot = sb + RING_OFF + (kc & 1) * 16384;
        const float* src = Xb + (size_t)(kc * 32 + (tid >> 5)) * TT + n0 + (tid & 31) * 4;
        unsigned dst = slot + (tid >> 5) * 512 + (tid & 31) * 16;
        #pragma unroll
        for (int u = 0; u < 4; u++)
            cp16(dst + u * 4096, src + (size_t)(u * 8) * TT);
        cp_commit();
    };
    // load A chunk into rA
    auto gloadA = [&](int kc) {
        #pragma unroll
        for (int u = 0; u < 4; u++) {
            int f = tid + u * 256;
            int ra = f >> 3, ca = (f & 7) * 4;
            float4 v = *(const float4*)&W[(size_t)(m0 + ra) * K + kc * 32 + ca];
            if (aSb) {
                v.x *= aSb[kc*32 + ca];   v.y *= aSb[kc*32 + ca+1];
                v.z *= aSb[kc*32 + ca+2]; v.w *= aSb[kc*32 + ca+3];
            }
            rA[u] = v;
        }
    };
    // convert staged data into fp16 stage st: A (single) from rA, B (hi/lo) from ring slot
    auto cvt_store = [&](int kc, int st) {
        size_t base = (size_t)st * STG_BYTES;
        unsigned slot = sb + RING_OFF + (kc & 1) * 16384;
        #pragma unroll
        for (int u = 0; u < 4; u++) {
            int f = tid + u * 256;
            {   // A from registers (single fp16)
                float4 v = rA[u];
                size_t off = base + (f >> 3) * 80 + (f & 7) * 8;
                *(uint2*)(smem + off) = make_uint2(
                    pack2h(__float2half(v.x), __float2half(v.y)),
                    pack2h(__float2half(v.z), __float2half(v.w)));
            }
            {   // B from fp32 ring (smem): hi + lo
                float4 v;
                unsigned sa = slot + (f >> 5) * 512 + (f & 31) * 16;
                asm volatile("ld.shared.v4.f32 {%0,%1,%2,%3}, [%4];"
                    : "=f"(v.x), "=f"(v.y), "=f"(v.z), "=f"(v.w) : "r"(sa));
                __half hx = __float2half(v.x), hy = __float2half(v.y);
                __half hz = __float2half(v.z), hw = __float2half(v.w);
                float lx = v.x - __half2float(hx), ly = v.y - __half2float(hy);
                float lz = v.z - __half2float(hz), lw = v.w - __half2float(hw);
                size_t off = base + A_BYTES + (f >> 5) * 272 + (f & 31) * 8;
                *(uint2*)(smem + off) = make_uint2(pack2h(hx, hy), pack2h(hz, hw));
                *(uint2*)(smem + off + 8704) = make_uint2(
                    pack2h(__float2half(lx), __float2half(ly)),
                    pack2h(__float2half(lz), __float2half(lw)));
            }
        }
    };

    auto compute = [&](int st) {
        unsigned stb = sb + st * STG_BYTES;
        #pragma unroll
        for (int ks = 0; ks < 2; ks++) {
            unsigned bh[2][4], bl[2][4];
            #pragma unroll
            for (int np = 0; np < 2; np++) {
                unsigned adr = stb + A_BYTES + ks * 4352 + wc * 64 + np * 32 + boff;
                LDSM4T(bh[np], adr);
                LDSM4T(bl[np], adr + 8704);
            }
            #pragma unroll
            for (int mf = 0; mf < 4; mf++) {
                unsigned ah[4];
                unsigned adr = stb + wr * 5120 + mf * 1280 + ks * 32 + aoff;
                LDSM4(ah, adr);
                #pragma unroll
                for (int nf = 0; nf < 4; nf++) {
                    const unsigned* bp = &bh[nf >> 1][(nf & 1) * 2];
                    const unsigned* lp = &bl[nf >> 1][(nf & 1) * 2];
                    mma_f16(acc[mf][nf], ah, bp);
                    mma_f16(acc[mf][nf], ah, lp);
                }
            }
        }
    };

    // ---------------- prologue ----------------
    cpB(0);                       // group: chunk0
    cpB(1);                       // group: chunk1
    gloadA(0);
    cp_wait<1>();                 // chunk0 B resident
    __syncthreads();              // ring visible to all warps
    cvt_store(0, 0);
    gloadA(1);
    __syncthreads();              // stage0 built

    // ---------------- mainloop ----------------
    for (int i = 0; i < nk; i++) {
        if (i + 2 < nk) cpB(i + 2);            // fire-and-forget
        compute(i & 1);
        if (i + 1 < nk) {
            if (i + 2 < nk) cp_wait<1>(); else cp_wait<0>();   // chunk i+1 resident
            __syncthreads();                    // compute(i) reads done; ring slot safe
            cvt_store(i + 1, (i + 1) & 1);
            if (i + 2 < nk) gloadA(i + 2);
        }
        __syncthreads();                        // stage (i+1)&1 built
    }

    // ---------------- epilogue ----------------
    const float* biasB = bias + (perB ? (size_t)b * M : 0);
    float* Yb = Y + (size_t)b * yStrideB;
    const float* Rb = R ? R + (size_t)b * rStrideB : nullptr;
    #pragma unroll
    for (int mf = 0; mf < 4; mf++) {
        int gm = m0 + wr * 64 + mf * 16 + (lane >> 2);
        float bv0 = biasB[gm], bv1 = biasB[gm + 8];
        #pragma unroll
        for (int nf = 0; nf < 4; nf++) {
            int gn = n0 + wc * 32 + nf * 8 + (lane & 3) * 2;
            float* a4 = acc[mf][nf];
            float2 v0 = make_float2(a4[0] + bv0, a4[1] + bv0);
            float2 v1 = make_float2(a4[2] + bv1, a4[3] + bv1);
            if (ep == 1) {
                v0.x /= (1.f + expf(-v0.x)); v0.y /= (1.f + expf(-v0.y));
                v1.x /= (1.f + expf(-v1.x)); v1.y /= (1.f + expf(-v1.y));
            } else if (ep == 2) {
                float2 r0 = *(const float2*)&Rb[(size_t)gm * TT + gn];
                float2 r1 = *(const float2*)&Rb[(size_t)(gm + 8) * TT + gn];
                v0.x += r0.x; v0.y += r0.y; v1.x += r1.x; v1.y += r1.y;
            }
            *(float2*)&Yb[(size_t)gm * TT + gn] = v0;
            *(float2*)&Yb[(size_t)(gm + 8) * TT + gn] = v1;
        }
    }
}

// ==================== group-norm / attention kernels (proven) ====================
__global__ void gn_stats_kernel(const float* __restrict__ x, int GC,
                                float* __restrict__ mu, float* __restrict__ rs)
{
    const size_t n = (size_t)GC * TT;
    const float4* x4 = (const float4*)(x + (size_t)blockIdx.x * n);
    const int n4 = (int)(n >> 2);
    float s = 0.f, sq = 0.f;
    for (int i = threadIdx.x; i < n4; i += 256) {
        float4 v = x4[i];
        s += (v.x + v.y) + (v.z + v.w);
        sq += v.x*v.x + v.y*v.y + v.z*v.z + v.w*v.w;
    }
    __shared__ float sh1[8], sh2[8];
    int lane = threadIdx.x & 31, w = threadIdx.x >> 5;
    #pragma unroll
    for (int o = 16; o > 0; o >>= 1) {
        s += __shfl_xor_sync(0xffffffffu, s, o);
        sq += __shfl_xor_sync(0xffffffffu, sq, o);
    }
    if (lane == 0) { sh1[w] = s; sh2[w] = sq; }
    __syncthreads();
    if (threadIdx.x < 8) {
        s = sh1[threadIdx.x]; sq = sh2[threadIdx.x];
        #pragma unroll
        for (int o = 4; o > 0; o >>= 1) {
            s += __shfl_xor_sync(0xffu, s, o);
            sq += __shfl_xor_sync(0xffu, sq, o);
        }
        if (threadIdx.x == 0) {
            float inv_n = 1.f / (float)n;
            float m = s * inv_n;
            float var = sq * inv_n - m * m;
            mu[blockIdx.x] = m;
            rs[blockIdx.x] = rsqrtf(fmaxf(var, 0.f) + EPSV);
        }
    }
}

__global__ void affine_kernel(const float* __restrict__ g, const float* __restrict__ be,
                              const float* __restrict__ mu, const float* __restrict__ rs,
                              float* __restrict__ a, float* __restrict__ bb, int C)
{
    int b = blockIdx.x;
    int GC = C >> 5;
    for (int c = threadIdx.x; c < C; c += blockDim.x) {
        int grp = c / GC;
        float r = rs[b*32 + grp], m = mu[b*32 + grp];
        float av = g[c] * r;
        a [b*C + c] = av;
        bb[b*C + c] = be[c] - m * av;
    }
}

__global__ void beff_kernel(const float* __restrict__ W, const float* __restrict__ bbv,
                            const float* __restrict__ bias, float* __restrict__ beff,
                            int M, int K)
{
    int m = blockIdx.x, b = blockIdx.y;
    float s = 0.f;
    for (int k = threadIdx.x; k < K; k += 128)
        s += W[(size_t)m*K + k] * bbv[b*K + k];
    __shared__ float sh[4];
    int lane = threadIdx.x & 31, w = threadIdx.x >> 5;
    #pragma unroll
    for (int o = 16; o > 0; o >>= 1) s += __shfl_xor_sync(0xffffffffu, s, o);
    if (lane == 0) sh[w] = s;
    __syncthreads();
    if (threadIdx.x == 0)
        beff[(size_t)b*M + m] = sh[0] + sh[1] + sh[2] + sh[3] + (bias ? bias[m] : 0.f);
}

__global__ void ksm_stats_kernel(const float* __restrict__ kbase, size_t strideB,
                                 float* __restrict__ kmax, float* __restrict__ kinv)
{
    int r = blockIdx.x, b = blockIdx.y;
    const float4* p4 = (const float4*)(kbase + (size_t)b * strideB + (size_t)r * TT);
    float mx = -1e30f;
    for (int i = threadIdx.x; i < TT/4; i += 256) {
        float4 v = p4[i];
        mx = fmaxf(mx, fmaxf(fmaxf(v.x, v.y), fmaxf(v.z, v.w)));
    }
    __shared__ float sh[8];
    __shared__ float bmax, bsum;
    int lane = threadIdx.x & 31, w = threadIdx.x >> 5;
    #pragma unroll
    for (int o = 16; o > 0; o >>= 1) mx = fmaxf(mx, __shfl_xor_sync(0xffffffffu, mx, o));
    if (lane == 0) sh[w] = mx;
    __syncthreads();
    if (threadIdx.x < 8) {
        mx = sh[threadIdx.x];
        #pragma unroll
        for (int o = 4; o > 0; o >>= 1) mx = fmaxf(mx, __shfl_xor_sync(0xffu, mx, o));
        if (threadIdx.x == 0) bmax = mx;
    }
    __syncthreads();
    float m = bmax;
    float s = 0.f;
    for (int i = threadIdx.x; i < TT/4; i += 256) {
        float4 v = p4[i];
        s += expf(v.x - m) + expf(v.y - m) + expf(v.z - m) + expf(v.w - m);
    }
    #pragma unroll
    for (int o = 16; o > 0; o >>= 1) s += __shfl_xor_sync(0xffffffffu, s, o);
    if (lane == 0) sh[w] = s;
    __syncthreads();
    if (threadIdx.x < 8) {
        s = sh[threadIdx.x];
        #pragma unroll
        for (int o = 4; o > 0; o >>= 1) s += __shfl_xor_sync(0xffu, s, o);
        if (threadIdx.x == 0) bsum = s;
    }
    __syncthreads();
    if (threadIdx.x == 0) { kmax[b*256 + r] = m; kinv[b*256 + r] = 1.f / bsum; }
}

__global__ void ctx_kernel(const float* __restrict__ kv, size_t strideB, int koff, int voff,
                           const float* __restrict__ kmax, const float* __restrict__ kinv,
                           float* __restrict__ cpart)
{
    int bh = blockIdx.x;
    int slice = blockIdx.y;
    int b = bh / NH, h = bh % NH;
    __shared__ float ks[32][65], vs[32][65];
    __shared__ float km[32], ki[32];
    int tid = threadIdx.x;
    if (tid < 32) {
        km[tid] = kmax[b*256 + h*32 + tid];
        ki[tid] = kinv[b*256 + h*32 + tid];
    }
    const float* kp = kv + (size_t)b*strideB + (size_t)(koff + h*32)*TT + slice*1024;
    const float* vp = kv + (size_t)b*strideB + (size_t)(voff + h*32)*TT + slice*1024;
    int d = tid >> 3, e0 = (tid & 7) * 4;
    float c0 = 0.f, c1 = 0.f, c2 = 0.f, c3 = 0.f;
    for (int tc = 0; tc < 1024; tc += 64) {
        __syncthreads();
        for (int i = tid; i < 32*64; i += 256) {
            int r = i >> 6, t = i & 63;
            ks[r][t] = expf(kp[(size_t)r*TT + tc + t] - km[r]) * ki[r];
            vs[r][t] = vp[(size_t)r*TT + tc + t];
        }
        __syncthreads();
        #pragma unroll 8
        for (int t = 0; t < 64; t++) {
            float kd = ks[d][t];
            c0 += kd * vs[e0+0][t];
            c1 += kd * vs[e0+1][t];
            c2 += kd * vs[e0+2][t];
            c3 += kd * vs[e0+3][t];
        }
    }
    float* cp = cpart + (size_t)slice*65536 + (size_t)bh*1024 + d*32 + e0;
    cp[0] = c0; cp[1] = c1; cp[2] = c2; cp[3] = c3;
}

__global__ void ctx_reduce_kernel(const float* __restrict__ cpart, float* __restrict__ ctx)
{
    int i = blockIdx.x * 256 + threadIdx.x;
    float s = 0.f;
    #pragma unroll
    for (int sl = 0; sl < 8; sl++) s += cpart[(size_t)sl*65536 + i];
    ctx[i] = s;
}

__global__ void attn_out_kernel(const float* __restrict__ q, size_t strideB, int qoff,
                                const float* __restrict__ ctx,
                                float* __restrict__ o, size_t oStrideB)
{
    int bh = blockIdx.x;
    int b = bh / NH, h = bh % NH;
    int t = blockIdx.y * 256 + threadIdx.x;
    __shared__ float cs[32][32];
    for (int i = threadIdx.x; i < 1024; i += 256)
        cs[i >> 5][i & 31] = ctx[(size_t)bh*1024 + i];
    __syncthreads();
    const float* qp = q + (size_t)b*strideB + (size_t)(qoff + h*32)*TT + t;
    float p[32];
    float mx = -1e30f;
    #pragma unroll
    for (int d = 0; d < 32; d++) { p[d] = qp[(size_t)d*TT]; mx = fmaxf(mx, p[d]); }
    float s = 0.f;
    #pragma unroll
    for (int d = 0; d < 32; d++) { p[d] = expf(p[d] - mx); s += p[d]; }
    float inv = 0.17677669529663687f / s;
    #pragma unroll
    for (int d = 0; d < 32; d++) p[d] *= inv;
    float accv[32];
    #pragma unroll
    for (int e = 0; e < 32; e++) accv[e] = 0.f;
    #pragma unroll
    for (int d = 0; d < 32; d++) {
        float pd = p[d];
        #pragma unroll
        for (int e4 = 0; e4 < 8; e4++) {
            float4 cv = *(const float4*)&cs[d][e4*4];
            accv[e4*4+0] += cv.x * pd;
            accv[e4*4+1] += cv.y * pd;
            accv[e4*4+2] += cv.z * pd;
            accv[e4*4+3] += cv.w * pd;
        }
    }
    float* op = o + (size_t)b*oStrideB + (size_t)(h*32)*TT + t;
    #pragma unroll
    for (int e = 0; e < 32; e++) op[(size_t)e*TT] = accv[e];
}

__global__ void gn_add_kernel(const float* __restrict__ v,
                              const float* __restrict__ gamma, const float* __restrict__ beta,
                              const float* __restrict__ mu, const float* __restrict__ rs,
                              const float* __restrict__ r, float* __restrict__ y)
{
    size_t i = ((size_t)blockIdx.x * 256 + threadIdx.x) * 4;
    int c = (int)((i / TT) % DIMC);
    int b = (int)(i / ((size_t)DIMC * TT));
    int grp = c >> 3;
    float rr = rs[b*32 + grp], m = mu[b*32 + grp];
    float sc = gamma[c] * rr;
    float sh = beta[c] - m * sc;
    float4 vv = *(const float4*)(v + i);
    float4 rv = *(const float4*)(r + i);
    float4 o;
    o.x = vv.x * sc + sh + rv.x;
    o.y = vv.y * sc + sh + rv.y;
    o.z = vv.z * sc + sh + rv.z;
    o.w = vv.w * sc + sh + rv.w;
    *(float4*)(y + i) = o;
}

// ==================== host orchestration ====================
extern "C" void kernel_launch(void* const* d_in, const int* in_sizes, int n_in,
                              void* d_out, int out_size)
{
    const float* x     = (const float*)d_in[0];
    const float* c     = (const float*)d_in[1];
    const float* W_qkv = (const float*)d_in[2];
    const float* W_so  = (const float*)d_in[3];
    const float* b_so  = (const float*)d_in[4];
    const float* sa_g  = (const float*)d_in[5];
    const float* sa_b  = (const float*)d_in[6];
    const float* W_cq  = (const float*)d_in[7];
    const float* W_ckv = (const float*)d_in[8];
    const float* W_co  = (const float*)d_in[9];
    const float* b_co  = (const float*)d_in[10];
    const float* ca_g  = (const float*)d_in[11];
    const float* ca_b  = (const float*)d_in[12];
    const float* W_m1  = (const float*)d_in[13];
    const float* b_m1  = (const float*)d_in[14];
    const float* W_m2  = (const float*)d_in[15];
    const float* b_m2  = (const float*)d_in[16];
    const float* nm_g  = (const float*)d_in[17];
    const float* nm_b  = (const float*)d_in[18];
    const float* nm1_g = (const float*)d_in[19];
    const float* nm1_b = (const float*)d_in[20];
    const float* nm2_g = (const float*)d_in[21];
    const float* nm2_b = (const float*)d_in[22];
    const float* nm3_g = (const float*)d_in[23];
    const float* nm3_b = (const float*)d_in[24];
    float* out = (float*)d_out;

    float *big, *attn, *so, *xb, *beff, *mu, *rs, *aa, *ab, *kmax, *kinv, *ctx, *ctxp;
    cudaGetSymbolAddress((void**)&big,  g_big);
    cudaGetSymbolAddress((void**)&attn, g_attn);
    cudaGetSymbolAddress((void**)&so,   g_so);
    cudaGetSymbolAddress((void**)&xb,   g_x);
    cudaGetSymbolAddress((void**)&beff, g_beff);
    cudaGetSymbolAddress((void**)&mu,   g_mu);
    cudaGetSymbolAddress((void**)&rs,   g_rs);
    cudaGetSymbolAddress((void**)&aa,   g_affa);
    cudaGetSymbolAddress((void**)&ab,   g_affb);
    cudaGetSymbolAddress((void**)&kmax, g_kmax);
    cudaGetSymbolAddress((void**)&kinv, g_kinv);
    cudaGetSymbolAddress((void**)&ctx,  g_ctx);
    cudaGetSymbolAddress((void**)&ctxp, g_ctxp);

    static bool attr_set = false;
    if (!attr_set) {
        cudaFuncSetAttribute(mm_kernel, cudaFuncAttributeMaxDynamicSharedMemorySize, SMEM_MM);
        attr_set = true;
    }

    const size_t XT = (size_t)DIMC * TT;

    // ================= Phase 1: self linear attention =================
    gn_stats_kernel<<<BQ*32, 256>>>(x, 8, mu, rs);
    affine_kernel<<<BQ, 256>>>(nm_g, nm_b, mu, rs, aa, ab, 256);
    beff_kernel<<<dim3(768, BQ), 128>>>(W_qkv, ab, nullptr, beff, 768, 256);
    mm_kernel<<<dim3(6, 64, BQ), 256, SMEM_MM>>>(W_qkv, aa, beff, 1,
                                                 x, XT, big, (size_t)768*TT,
                                                 nullptr, 0, 768, 256, 0);
    ksm_stats_kernel<<<dim3(256, BQ), 256>>>(big + (size_t)256*TT, (size_t)768*TT, kmax, kinv);
    ctx_kernel<<<dim3(64, 8), 256>>>(big, (size_t)768*TT, 256, 512, kmax, kinv, ctxp);
    ctx_reduce_kernel<<<256, 256>>>(ctxp, ctx);
    attn_out_kernel<<<dim3(64, 32), 256>>>(big, (size_t)768*TT, 0, ctx, attn, XT);
    mm_kernel<<<dim3(2, 64, BQ), 256, SMEM_MM>>>(W_so, nullptr, b_so, 0,
                                                 attn, XT, so, XT,
                                                 nullptr, 0, 256, 256, 0);
    gn_stats_kernel<<<BQ*32, 256>>>(so, 8, mu, rs);
    gn_add_kernel<<<16384, 256>>>(so, sa_g, sa_b, mu, rs, x, xb);

    // ================= Phase 2: cross linear attention =================
    gn_stats_kernel<<<BQ*32, 256>>>(xb, 8, mu, rs);
    affine_kernel<<<BQ, 256>>>(nm1_g, nm1_b, mu, rs, aa, ab, 256);
    beff_kernel<<<dim3(256, BQ), 128>>>(W_cq, ab, nullptr, beff, 256, 256);
    mm_kernel<<<dim3(2, 64, BQ), 256, SMEM_MM>>>(W_cq, aa, beff, 1,
                                                 xb, XT, attn, XT,
                                                 nullptr, 0, 256, 256, 0);
    gn_stats_kernel<<<BQ*32, 256>>>(c, 16, mu, rs);
    affine_kernel<<<BQ, 256>>>(nm3_g, nm3_b, mu, rs, aa, ab, 512);
    beff_kernel<<<dim3(512, BQ), 128>>>(W_ckv, ab, nullptr, beff, 512, 512);
    mm_kernel<<<dim3(4, 64, BQ), 256, SMEM_MM>>>(W_ckv, aa, beff, 1,
                                                 c, (size_t)512*TT, big, (size_t)512*TT,
                                                 nullptr, 0, 512, 512, 0);
    ksm_stats_kernel<<<dim3(256, BQ), 256>>>(big, (size_t)512*TT, kmax, kinv);
    ctx_kernel<<<dim3(64, 8), 256>>>(big, (size_t)512*TT, 0, 256, kmax, kinv, ctxp);
    ctx_reduce_kernel<<<256, 256>>>(ctxp, ctx);
    attn_out_kernel<<<dim3(64, 32), 256>>>(attn, XT, 0, ctx, big, XT);
    mm_kernel<<<dim3(2, 64, BQ), 256, SMEM_MM>>>(W_co, nullptr, b_co, 0,
                                                 big, XT, so, XT,
                                                 nullptr, 0, 256, 256, 0);
    gn_stats_kernel<<<BQ*32, 256>>>(so, 8, mu, rs);
    gn_add_kernel<<<16384, 256>>>(so, ca_g, ca_b, mu, rs, xb, xb);

    // ================= Phase 3: SiLU MLP =================
    gn_stats_kernel<<<BQ*32, 256>>>(xb, 8, mu, rs);
    affine_kernel<<<BQ, 256>>>(nm2_g, nm2_b, mu, rs, aa, ab, 256);
    beff_kernel<<<dim3(640, BQ), 128>>>(W_m1, ab, b_m1, beff, 640, 256);
    mm_kernel<<<dim3(5, 64, BQ), 256, SMEM_MM>>>(W_m1, aa, beff, 1,
                                                 xb, XT, big, (size_t)640*TT,
                                                 nullptr, 0, 640, 256, 1 /*silu*/);
    mm_kernel<<<dim3(2, 64, BQ), 256, SMEM_MM>>>(W_m2, nullptr, b_m2, 0,
                                                 big, (size_t)640*TT, out, XT,
                                                 xb, XT, 256, 640, 2 /*residual*/);
}

// round 11
// speedup vs baseline: 2.7451x; 1.2784x over previous
#include <cuda_runtime.h>
#include <cuda_fp16.h>
#include <cstdint>

#define BQ 8
#define DIMC 256
#define TT 8192
#define NH 8
#define EPSV 1e-5f

// fp16 stage: A[128 rows x 32k, pad 40h]=10240B, B[32k x 128n, pad 136h]=8704B
#define A_BYTES   10240
#define STG_BYTES 18944
#define NSTG      3
#define SMEM_MM   (NSTG * STG_BYTES)

// ---------------- scratch (device globals) ----------------
__device__ float g_big [(size_t)BQ * 768 * TT];
__device__ float g_attn[(size_t)BQ * DIMC * TT];
__device__ float g_so  [(size_t)BQ * DIMC * TT];
__device__ float g_x   [(size_t)BQ * DIMC * TT];
__device__ float g_beff[BQ * 1024];
__device__ float g_mu  [BQ * 32];
__device__ float g_rs  [BQ * 32];
__device__ float g_affa[BQ * 512];
__device__ float g_affb[BQ * 512];
__device__ float g_kmax[BQ * 256];
__device__ float g_kinv[BQ * 256];
__device__ float g_ctx [BQ * NH * 32 * 32];
__device__ float g_ctxp[8 * BQ * NH * 32 * 32];
// fp16 operand planes
__device__ __align__(256) __half g_w16[(size_t)BQ * 512 * 512];        // folded weights
__device__ __align__(256) __half g_h1 [(size_t)BQ * 512 * TT];         // activation plane (reused)
__device__ __align__(256) __half g_h2 [(size_t)BQ * 640 * TT];         // m1 output -> m2 input

// ==================== PTX helpers (plain sm_80+ only) ====================
__device__ __forceinline__ unsigned s2u(const void* p) {
    unsigned a;
    asm("{ .reg .u64 t; cvta.to.shared.u64 t, %1; cvt.u32.u64 %0, t; }" : "=r"(a) : "l"(p));
    return a;
}
#define LDSM4(r, addr) \
    asm volatile("ldmatrix.sync.aligned.m8n8.x4.shared.b16 {%0,%1,%2,%3}, [%4];" \
        : "=r"((r)[0]), "=r"((r)[1]), "=r"((r)[2]), "=r"((r)[3]) : "r"(addr))
#define LDSM4T(r, addr) \
    asm volatile("ldmatrix.sync.aligned.m8n8.x4.trans.shared.b16 {%0,%1,%2,%3}, [%4];" \
        : "=r"((r)[0]), "=r"((r)[1]), "=r"((r)[2]), "=r"((r)[3]) : "r"(addr))
__device__ __forceinline__ void mma_f16(float* c, const unsigned* a, const unsigned* b) {
    asm volatile("mma.sync.aligned.m16n8k16.row.col.f32.f16.f16.f32 "
        "{%0,%1,%2,%3}, {%4,%5,%6,%7}, {%8,%9}, {%0,%1,%2,%3};"
        : "+f"(c[0]), "+f"(c[1]), "+f"(c[2]), "+f"(c[3])
        : "r"(a[0]), "r"(a[1]), "r"(a[2]), "r"(a[3]), "r"(b[0]), "r"(b[1]));
}
__device__ __forceinline__ void cp16(unsigned saddr, const void* gaddr) {
    asm volatile("cp.async.cg.shared.global [%0], [%1], 16;" :: "r"(saddr), "l"(gaddr));
}
__device__ __forceinline__ void cp_commit() {
    asm volatile("cp.async.commit_group;");
}
template <int N>
__device__ __forceinline__ void cp_wait() {
    asm volatile("cp.async.wait_group %0;" :: "n"(N));
}

// ==================== tensor-core GEMM (pure fp16 operands, fp32 accum) ====================
// Y[b][m][n] = sum_k A16[m][k] * B16[k][n] + bias[m]  [ep1: silu (fp16 out) | ep2: +R]
__global__ __launch_bounds__(256, 2)
void mm_kernel(const __half* __restrict__ A16, size_t aStrB,
               const float* __restrict__ bias, int perB,
               const __half* __restrict__ B16, size_t bStrB,
               float* __restrict__ Y, __half* __restrict__ Yh, size_t yStrB,
               const float* __restrict__ R, size_t rStrB,
               int M, int K, int ep)
{
    extern __shared__ char smem[];
    const unsigned sb = s2u(smem);
    const int tid = threadIdx.x, lane = tid & 31, wid = tid >> 5;
    const int wr = wid >> 2, wc = wid & 3;           // warp grid 2(m) x 4(n)
    const int mt = blockIdx.x, nt = blockIdx.y, b = blockIdx.z;
    const int m0 = mt * 128, n0 = nt * 128;
    const __half* Ab = A16 + (size_t)b * aStrB;
    const __half* Bb = B16 + (size_t)b * bStrB;

    float acc[4][4][4];
    #pragma unroll
    for (int i = 0; i < 4; i++)
        #pragma unroll
        for (int j = 0; j < 4; j++)
            #pragma unroll
            for (int r = 0; r < 4; r++) acc[i][j][r] = 0.f;

    const unsigned aoff = (lane & 15) * 80  + (lane >> 4) * 16;
    const unsigned boff = (lane & 15) * 272 + (lane >> 4) * 16;
    const int nk = K >> 5;

    // async-copy one fp16 chunk (A 8KB + B 8KB) into stage st
    auto cpChunk = [&](int kc, int st) {
        unsigned base = sb + st * STG_BYTES;
        #pragma unroll
        for (int u = 0; u < 2; u++) {            // A: 512 cp16
            int f = tid + u * 256;
            int row = f >> 2, c16 = f & 3;
            cp16(base + row * 80 + c16 * 16,
                 Ab + (size_t)(m0 + row) * K + kc * 32 + c16 * 8);
        }
        #pragma unroll
        for (int u = 0; u < 2; u++) {            // B: 512 cp16
            int f = tid + u * 256;
            int r = f >> 4, c16 = f & 15;
            cp16(base + A_BYTES + r * 272 + c16 * 16,
                 Bb + (size_t)(kc * 32 + r) * TT + n0 + c16 * 8);
        }
        cp_commit();
    };

    auto compute = [&](int st) {
        unsigned stb = sb + st * STG_BYTES;
        #pragma unroll
        for (int ks = 0; ks < 2; ks++) {
            unsigned bh[2][4];
            #pragma unroll
            for (int np = 0; np < 2; np++)
                LDSM4T(bh[np], stb + A_BYTES + ks * 4352 + wc * 64 + np * 32 + boff);
            #pragma unroll
            for (int mf = 0; mf < 4; mf++) {
                unsigned ah[4];
                LDSM4(ah, stb + wr * 5120 + mf * 1280 + ks * 32 + aoff);
                #pragma unroll
                for (int nf = 0; nf < 4; nf++)
                    mma_f16(acc[mf][nf], ah, &bh[nf >> 1][(nf & 1) * 2]);
            }
        }
    };

    // prologue: fill up to NSTG stages
    const int pre = nk < NSTG ? nk : NSTG;
    for (int i = 0; i < pre; i++) cpChunk(i, i);

    for (int i = 0; i < nk; i++) {
        if (i + 2 < nk)      cp_wait<2>();
        else if (i + 1 < nk) cp_wait<1>();
        else                 cp_wait<0>();
        __syncthreads();
        compute(i % NSTG);
        __syncthreads();
        if (i + NSTG < nk) cpChunk(i + NSTG, i % NSTG);
    }

    // epilogue
    const float* biasB = bias + (perB ? (size_t)b * M : 0);
    #pragma unroll
    for (int mf = 0; mf < 4; mf++) {
        int gm = m0 + wr * 64 + mf * 16 + (lane >> 2);
        float bv0 = biasB[gm], bv1 = biasB[gm + 8];
        #pragma unroll
        for (int nf = 0; nf < 4; nf++) {
            int gn = n0 + wc * 32 + nf * 8 + (lane & 3) * 2;
            float* a4 = acc[mf][nf];
            float2 v0 = make_float2(a4[0] + bv0, a4[1] + bv0);
            float2 v1 = make_float2(a4[2] + bv1, a4[3] + bv1);
            if (ep == 1) {
                v0.x /= (1.f + expf(-v0.x)); v0.y /= (1.f + expf(-v0.y));
                v1.x /= (1.f + expf(-v1.x)); v1.y /= (1.f + expf(-v1.y));
            } else if (ep == 2) {
                const float* Rb = R + (size_t)b * rStrB;
                float2 r0 = *(const float2*)&Rb[(size_t)gm * TT + gn];
                float2 r1 = *(const float2*)&Rb[(size_t)(gm + 8) * TT + gn];
                v0.x += r0.x; v0.y += r0.y; v1.x += r1.x; v1.y += r1.y;
            }
            if (Yh) {
                __half* Yb = Yh + (size_t)b * yStrB;
                *(__half2*)&Yb[(size_t)gm * TT + gn] =
                    __halves2half2(__float2half(v0.x), __float2half(v0.y));
                *(__half2*)&Yb[(size_t)(gm + 8) * TT + gn] =
                    __halves2half2(__float2half(v1.x), __float2half(v1.y));
            } else {
                float* Yb = Y + (size_t)b * yStrB;
                *(float2*)&Yb[(size_t)gm * TT + gn] = v0;
                *(float2*)&Yb[(size_t)(gm + 8) * TT + gn] = v1;
            }
        }
    }
}

// ==================== operand conversion ====================
// fp32 -> fp16 stream (activations)
__global__ void conv_h_kernel(const float* __restrict__ src, __half* __restrict__ dst)
{
    size_t i = ((size_t)blockIdx.x * 256 + threadIdx.x) * 8;
    float4 a = *(const float4*)(src + i);
    float4 b = *(const float4*)(src + i + 4);
    __half h[8] = {__float2half(a.x), __float2half(a.y), __float2half(a.z), __float2half(a.w),
                   __float2half(b.x), __float2half(b.y), __float2half(b.z), __float2half(b.w)};
    *(uint4*)(dst + i) = *(uint4*)h;
}

// weight fold: dst[b][m][k] = fp16(W[m][k] * aS[b][k]); aS null -> plain convert (gridDim.y==1)
__global__ void conv_w_kernel(const float* __restrict__ W, const float* __restrict__ aS,
                              __half* __restrict__ dst, int MK, int K)
{
    int b = blockIdx.y;
    int idx = (blockIdx.x * 256 + threadIdx.x) * 4;
    int k = idx % K;   // K multiple of 4; vector stays within one row
    float4 w = *(const float4*)(W + idx);
    if (aS) {
        const float* a = aS + b * K + k;
        w.x *= a[0]; w.y *= a[1]; w.z *= a[2]; w.w *= a[3];
    }
    __half h[4] = {__float2half(w.x), __float2half(w.y), __float2half(w.z), __float2half(w.w)};
    *(uint2*)(dst + (size_t)b * MK + idx) = *(uint2*)h;
}

// ==================== group-norm / attention kernels ====================
__global__ void gn_stats_kernel(const float* __restrict__ x, int GC,
                                float* __restrict__ mu, float* __restrict__ rs)
{
    const size_t n = (size_t)GC * TT;
    const float4* x4 = (const float4*)(x + (size_t)blockIdx.x * n);
    const int n4 = (int)(n >> 2);
    float s = 0.f, sq = 0.f;
    for (int i = threadIdx.x; i < n4; i += 256) {
        float4 v = x4[i];
        s += (v.x + v.y) + (v.z + v.w);
        sq += v.x*v.x + v.y*v.y + v.z*v.z + v.w*v.w;
    }
    __shared__ float sh1[8], sh2[8];
    int lane = threadIdx.x & 31, w = threadIdx.x >> 5;
    #pragma unroll
    for (int o = 16; o > 0; o >>= 1) {
        s += __shfl_xor_sync(0xffffffffu, s, o);
        sq += __shfl_xor_sync(0xffffffffu, sq, o);
    }
    if (lane == 0) { sh1[w] = s; sh2[w] = sq; }
    __syncthreads();
    if (threadIdx.x < 8) {
        s = sh1[threadIdx.x]; sq = sh2[threadIdx.x];
        #pragma unroll
        for (int o = 4; o > 0; o >>= 1) {
            s += __shfl_xor_sync(0xffu, s, o);
            sq += __shfl_xor_sync(0xffu, sq, o);
        }
        if (threadIdx.x == 0) {
            float inv_n = 1.f / (float)n;
            float m = s * inv_n;
            float var = sq * inv_n - m * m;
            mu[blockIdx.x] = m;
            rs[blockIdx.x] = rsqrtf(fmaxf(var, 0.f) + EPSV);
        }
    }
}

__global__ void affine_kernel(const float* __restrict__ g, const float* __restrict__ be,
                              const float* __restrict__ mu, const float* __restrict__ rs,
                              float* __restrict__ a, float* __restrict__ bb, int C)
{
    int b = blockIdx.x;
    int GC = C >> 5;
    for (int c = threadIdx.x; c < C; c += blockDim.x) {
        int grp = c / GC;
        float r = rs[b*32 + grp], m = mu[b*32 + grp];
        float av = g[c] * r;
        a [b*C + c] = av;
        bb[b*C + c] = be[c] - m * av;
    }
}

__global__ void beff_kernel(const float* __restrict__ W, const float* __restrict__ bbv,
                            const float* __restrict__ bias, float* __restrict__ beff,
                            int M, int K)
{
    int m = blockIdx.x, b = blockIdx.y;
    float s = 0.f;
    for (int k = threadIdx.x; k < K; k += 128)
        s += W[(size_t)m*K + k] * bbv[b*K + k];
    __shared__ float sh[4];
    int lane = threadIdx.x & 31, w = threadIdx.x >> 5;
    #pragma unroll
    for (int o = 16; o > 0; o >>= 1) s += __shfl_xor_sync(0xffffffffu, s, o);
    if (lane == 0) sh[w] = s;
    __syncthreads();
    if (threadIdx.x == 0)
        beff[(size_t)b*M + m] = sh[0] + sh[1] + sh[2] + sh[3] + (bias ? bias[m] : 0.f);
}

__global__ void ksm_stats_kernel(const float* __restrict__ kbase, size_t strideB,
                                 float* __restrict__ kmax, float* __restrict__ kinv)
{
    int r = blockIdx.x, b = blockIdx.y;
    const float4* p4 = (const float4*)(kbase + (size_t)b * strideB + (size_t)r * TT);
    float mx = -1e30f;
    for (int i = threadIdx.x; i < TT/4; i += 256) {
        float4 v = p4[i];
        mx = fmaxf(mx, fmaxf(fmaxf(v.x, v.y), fmaxf(v.z, v.w)));
    }
    __shared__ float sh[8];
    __shared__ float bmax, bsum;
    int lane = threadIdx.x & 31, w = threadIdx.x >> 5;
    #pragma unroll
    for (int o = 16; o > 0; o >>= 1) mx = fmaxf(mx, __shfl_xor_sync(0xffffffffu, mx, o));
    if (lane == 0) sh[w] = mx;
    __syncthreads();
    if (threadIdx.x < 8) {
        mx = sh[threadIdx.x];
        #pragma unroll
        for (int o = 4; o > 0; o >>= 1) mx = fmaxf(mx, __shfl_xor_sync(0xffu, mx, o));
        if (threadIdx.x == 0) bmax = mx;
    }
    __syncthreads();
    float m = bmax;
    float s = 0.f;
    for (int i = threadIdx.x; i < TT/4; i += 256) {
        float4 v = p4[i];
        s += expf(v.x - m) + expf(v.y - m) + expf(v.z - m) + expf(v.w - m);
    }
    #pragma unroll
    for (int o = 16; o > 0; o >>= 1) s += __shfl_xor_sync(0xffffffffu, s, o);
    if (lane == 0) sh[w] = s;
    __syncthreads();
    if (threadIdx.x < 8) {
        s = sh[threadIdx.x];
        #pragma unroll
        for (int o = 4; o > 0; o >>= 1) s += __shfl_xor_sync(0xffu, s, o);
        if (threadIdx.x == 0) bsum = s;
    }
    __syncthreads();
    if (threadIdx.x == 0) { kmax[b*256 + r] = m; kinv[b*256 + r] = 1.f / bsum; }
}

__global__ void ctx_kernel(const float* __restrict__ kv, size_t strideB, int koff, int voff,
                           const float* __restrict__ kmax, const float* __restrict__ kinv,
                           float* __restrict__ cpart)
{
    int bh = blockIdx.x;
    int slice = blockIdx.y;
    int b = bh / NH, h = bh % NH;
    __shared__ float ks[32][65], vs[32][65];
    __shared__ float km[32], ki[32];
    int tid = threadIdx.x;
    if (tid < 32) {
        km[tid] = kmax[b*256 + h*32 + tid];
        ki[tid] = kinv[b*256 + h*32 + tid];
    }
    const float* kp = kv + (size_t)b*strideB + (size_t)(koff + h*32)*TT + slice*1024;
    const float* vp = kv + (size_t)b*strideB + (size_t)(voff + h*32)*TT + slice*1024;
    int d = tid >> 3, e0 = (tid & 7) * 4;
    float c0 = 0.f, c1 = 0.f, c2 = 0.f, c3 = 0.f;
    for (int tc = 0; tc < 1024; tc += 64) {
        __syncthreads();
        for (int i = tid; i < 32*64; i += 256) {
            int r = i >> 6, t = i & 63;
            ks[r][t] = expf(kp[(size_t)r*TT + tc + t] - km[r]) * ki[r];
            vs[r][t] = vp[(size_t)r*TT + tc + t];
        }
        __syncthreads();
        #pragma unroll 8
        for (int t = 0; t < 64; t++) {
            float kd = ks[d][t];
            c0 += kd * vs[e0+0][t];
            c1 += kd * vs[e0+1][t];
            c2 += kd * vs[e0+2][t];
            c3 += kd * vs[e0+3][t];
        }
    }
    float* cp = cpart + (size_t)slice*65536 + (size_t)bh*1024 + d*32 + e0;
    cp[0] = c0; cp[1] = c1; cp[2] = c2; cp[3] = c3;
}

__global__ void ctx_reduce_kernel(const float* __restrict__ cpart, float* __restrict__ ctx)
{
    int i = blockIdx.x * 256 + threadIdx.x;
    float s = 0.f;
    #pragma unroll
    for (int sl = 0; sl < 8; sl++) s += cpart[(size_t)sl*65536 + i];
    ctx[i] = s;
}

// writes fp16 plane (input to the following GEMM)
__global__ void attn_out_kernel(const float* __restrict__ q, size_t strideB, int qoff,
                                const float* __restrict__ ctx,
                                __half* __restrict__ o, size_t oStrideB)
{
    int bh = blockIdx.x;
    int b = bh / NH, h = bh % NH;
    int t = blockIdx.y * 256 + threadIdx.x;
    __shared__ float cs[32][32];
    for (int i = threadIdx.x; i < 1024; i += 256)
        cs[i >> 5][i & 31] = ctx[(size_t)bh*1024 + i];
    __syncthreads();
    const float* qp = q + (size_t)b*strideB + (size_t)(qoff + h*32)*TT + t;
    float p[32];
    float mx = -1e30f;
    #pragma unroll
    for (int d = 0; d < 32; d++) { p[d] = qp[(size_t)d*TT]; mx = fmaxf(mx, p[d]); }
    float s = 0.f;
    #pragma unroll
    for (int d = 0; d < 32; d++) { p[d] = expf(p[d] - mx); s += p[d]; }
    float inv = 0.17677669529663687f / s;
    #pragma unroll
    for (int d = 0; d < 32; d++) p[d] *= inv;
    float accv[32];
    #pragma unroll
    for (int e = 0; e < 32; e++) accv[e] = 0.f;
    #pragma unroll
    for (int d = 0; d < 32; d++) {
        float pd = p[d];
        #pragma unroll
        for (int e4 = 0; e4 < 8; e4++) {
            float4 cv = *(const float4*)&cs[d][e4*4];
            accv[e4*4+0] += cv.x * pd;
            accv[e4*4+1] += cv.y * pd;
            accv[e4*4+2] += cv.z * pd;
            accv[e4*4+3] += cv.w * pd;
        }
    }
    __half* op = o + (size_t)b*oStrideB + (size_t)(h*32)*TT + t;
    #pragma unroll
    for (int e = 0; e < 32; e++) op[(size_t)e*TT] = __float2half(accv[e]);
}

// y = gn(v)*g + b + r ; writes fp32 y AND fp16 plane yh
__global__ void gn_add_kernel(const float* __restrict__ v,
                              const float* __restrict__ gamma, const float* __restrict__ beta,
                              const float* __restrict__ mu, const float* __restrict__ rs,
                              const float* __restrict__ r, float* __restrict__ y,
                              __half* __restrict__ yh)
{
    size_t i = ((size_t)blockIdx.x * 256 + threadIdx.x) * 4;
    int c = (int)((i / TT) % DIMC);
    int b = (int)(i / ((size_t)DIMC * TT));
    int grp = c >> 3;
    float rr = rs[b*32 + grp], m = mu[b*32 + grp];
    float sc = gamma[c] * rr;
    float sh = beta[c] - m * sc;
    float4 vv = *(const float4*)(v + i);
    float4 rv = *(const float4*)(r + i);
    float4 o;
    o.x = vv.x * sc + sh + rv.x;
    o.y = vv.y * sc + sh + rv.y;
    o.z = vv.z * sc + sh + rv.z;
    o.w = vv.w * sc + sh + rv.w;
    *(float4*)(y + i) = o;
    __half h[4] = {__float2half(o.x), __float2half(o.y), __float2half(o.z), __float2half(o.w)};
    *(uint2*)(yh + i) = *(uint2*)h;
}

// ==================== host orchestration ====================
extern "C" void kernel_launch(void* const* d_in, const int* in_sizes, int n_in,
                              void* d_out, int out_size)
{
    const float* x     = (const float*)d_in[0];
    const float* c     = (const float*)d_in[1];
    const float* W_qkv = (const float*)d_in[2];
    const float* W_so  = (const float*)d_in[3];
    const float* b_so  = (const float*)d_in[4];
    const float* sa_g  = (const float*)d_in[5];
    const float* sa_b  = (const float*)d_in[6];
    const float* W_cq  = (const float*)d_in[7];
    const float* W_ckv = (const float*)d_in[8];
    const float* W_co  = (const float*)d_in[9];
    const float* b_co  = (const float*)d_in[10];
    const float* ca_g  = (const float*)d_in[11];
    const float* ca_b  = (const float*)d_in[12];
    const float* W_m1  = (const float*)d_in[13];
    const float* b_m1  = (const float*)d_in[14];
    const float* W_m2  = (const float*)d_in[15];
    const float* b_m2  = (const float*)d_in[16];
    const float* nm_g  = (const float*)d_in[17];
    const float* nm_b  = (const float*)d_in[18];
    const float* nm1_g = (const float*)d_in[19];
    const float* nm1_b = (const float*)d_in[20];
    const float* nm2_g = (const float*)d_in[21];
    const float* nm2_b = (const float*)d_in[22];
    const float* nm3_g = (const float*)d_in[23];
    const float* nm3_b = (const float*)d_in[24];
    float* out = (float*)d_out;

    float *big, *attn, *so, *xb, *beff, *mu, *rs, *aa, *ab, *kmax, *kinv, *ctx, *ctxp;
    __half *w16, *h1, *h2;
    cudaGetSymbolAddress((void**)&big,  g_big);
    cudaGetSymbolAddress((void**)&attn, g_attn);
    cudaGetSymbolAddress((void**)&so,   g_so);
    cudaGetSymbolAddress((void**)&xb,   g_x);
    cudaGetSymbolAddress((void**)&beff, g_beff);
    cudaGetSymbolAddress((void**)&mu,   g_mu);
    cudaGetSymbolAddress((void**)&rs,   g_rs);
    cudaGetSymbolAddress((void**)&aa,   g_affa);
    cudaGetSymbolAddress((void**)&ab,   g_affb);
    cudaGetSymbolAddress((void**)&kmax, g_kmax);
    cudaGetSymbolAddress((void**)&kinv, g_kinv);
    cudaGetSymbolAddress((void**)&ctx,  g_ctx);
    cudaGetSymbolAddress((void**)&ctxp, g_ctxp);
    cudaGetSymbolAddress((void**)&w16,  g_w16);
    cudaGetSymbolAddress((void**)&h1,   g_h1);
    cudaGetSymbolAddress((void**)&h2,   g_h2);

    static bool attr_set = false;
    if (!attr_set) {
        cudaFuncSetAttribute(mm_kernel, cudaFuncAttributeMaxDynamicSharedMemorySize, SMEM_MM);
        attr_set = true;
    }

    const size_t XT = (size_t)DIMC * TT;

    // ================= Phase 1: self linear attention =================
    gn_stats_kernel<<<BQ*32, 256>>>(x, 8, mu, rs);
    affine_kernel<<<BQ, 256>>>(nm_g, nm_b, mu, rs, aa, ab, 256);
    conv_w_kernel<<<dim3(192, BQ), 256>>>(W_qkv, aa, w16, 768*256, 256);
    beff_kernel<<<dim3(768, BQ), 128>>>(W_qkv, ab, nullptr, beff, 768, 256);
    conv_h_kernel<<<8192, 256>>>(x, h1);                                  // x -> fp16
    mm_kernel<<<dim3(6, 64, BQ), 256, SMEM_MM>>>(w16, (size_t)768*256, beff, 1,
                                                 h1, XT, big, nullptr, (size_t)768*TT,
                                                 nullptr, 0, 768, 256, 0);
    ksm_stats_kernel<<<dim3(256, BQ), 256>>>(big + (size_t)256*TT, (size_t)768*TT, kmax, kinv);
    ctx_kernel<<<dim3(64, 8), 256>>>(big, (size_t)768*TT, 256, 512, kmax, kinv, ctxp);
    ctx_reduce_kernel<<<256, 256>>>(ctxp, ctx);
    attn_out_kernel<<<dim3(64, 32), 256>>>(big, (size_t)768*TT, 0, ctx, h1, XT);   // fp16 out
    conv_w_kernel<<<dim3(64, 1), 256>>>(W_so, nullptr, w16, 256*256, 256);
    mm_kernel<<<dim3(2, 64, BQ), 256, SMEM_MM>>>(w16, 0, b_so, 0,
                                                 h1, XT, so, nullptr, XT,
                                                 nullptr, 0, 256, 256, 0);
    gn_stats_kernel<<<BQ*32, 256>>>(so, 8, mu, rs);
    gn_add_kernel<<<16384, 256>>>(so, sa_g, sa_b, mu, rs, x, xb, h1);     // xb fp32 + fp16

    // ================= Phase 2: cross linear attention =================
    gn_stats_kernel<<<BQ*32, 256>>>(xb, 8, mu, rs);
    affine_kernel<<<BQ, 256>>>(nm1_g, nm1_b, mu, rs, aa, ab, 256);
    conv_w_kernel<<<dim3(64, BQ), 256>>>(W_cq, aa, w16, 256*256, 256);
    beff_kernel<<<dim3(256, BQ), 128>>>(W_cq, ab, nullptr, beff, 256, 256);
    mm_kernel<<<dim3(2, 64, BQ), 256, SMEM_MM>>>(w16, (size_t)256*256, beff, 1,
                                                 h1, XT, attn, nullptr, XT,
                                                 nullptr, 0, 256, 256, 0);
    gn_stats_kernel<<<BQ*32, 256>>>(c, 16, mu, rs);
    affine_kernel<<<BQ, 256>>>(nm3_g, nm3_b, mu, rs, aa, ab, 512);
    conv_w_kernel<<<dim3(256, BQ), 256>>>(W_ckv, aa, w16, 512*512, 512);
    beff_kernel<<<dim3(512, BQ), 128>>>(W_ckv, ab, nullptr, beff, 512, 512);
    conv_h_kernel<<<16384, 256>>>(c, h1);                                 // c -> fp16
    mm_kernel<<<dim3(4, 64, BQ), 256, SMEM_MM>>>(w16, (size_t)512*512, beff, 1,
                                                 h1, (size_t)512*TT, big, nullptr, (size_t)512*TT,
                                                 nullptr, 0, 512, 512, 0);
    ksm_stats_kernel<<<dim3(256, BQ), 256>>>(big, (size_t)512*TT, kmax, kinv);
    ctx_kernel<<<dim3(64, 8), 256>>>(big, (size_t)512*TT, 0, 256, kmax, kinv, ctxp);
    ctx_reduce_kernel<<<256, 256>>>(ctxp, ctx);
    attn_out_kernel<<<dim3(64, 32), 256>>>(attn, XT, 0, ctx, h1, XT);     // fp16 out
    conv_w_kernel<<<dim3(64, 1), 256>>>(W_co, nullptr, w16, 256*256, 256);
    mm_kernel<<<dim3(2, 64, BQ), 256, SMEM_MM>>>(w16, 0, b_co, 0,
                                                 h1, XT, so, nullptr, XT,
                                                 nullptr, 0, 256, 256, 0);
    gn_stats_kernel<<<BQ*32, 256>>>(so, 8, mu, rs);
    gn_add_kernel<<<16384, 256>>>(so, ca_g, ca_b, mu, rs, xb, xb, h1);    // xb fp32 + fp16

    // ================= Phase 3: SiLU MLP =================
    gn_stats_kernel<<<BQ*32, 256>>>(xb, 8, mu, rs);
    affine_kernel<<<BQ, 256>>>(nm2_g, nm2_b, mu, rs, aa, ab, 256);
    conv_w_kernel<<<dim3(160, BQ), 256>>>(W_m1, aa, w16, 640*256, 256);
    beff_kernel<<<dim3(640, BQ), 128>>>(W_m1, ab, b_m1, beff, 640, 256);
    mm_kernel<<<dim3(5, 64, BQ), 256, SMEM_MM>>>(w16, (size_t)640*256, beff, 1,
                                                 h1, XT, nullptr, h2, (size_t)640*TT,
                                                 nullptr, 0, 640, 256, 1 /*silu, fp16 out*/);
    conv_w_kernel<<<dim3(160, 1), 256>>>(W_m2, nullptr, w16, 256*640, 640);
    mm_kernel<<<dim3(2, 64, BQ), 256, SMEM_MM>>>(w16, 0, b_m2, 0,
                                                 h2, (size_t)640*TT, out, nullptr, XT,
                                                 xb, XT, 256, 640, 2 /*residual*/);
}

// round 12
// speedup vs baseline: 2.9473x; 1.0737x over previous
#include <cuda_runtime.h>
#include <cuda_fp16.h>
#include <cstdint>

#define BQ 8
#define DIMC 256
#define TT 8192
#define NH 8
#define EPSV 1e-5f

// fp16 stage: A[128 rows x 32k, pad 40h]=10240B, B[32k x 128n, pad 136h]=8704B
#define A_BYTES   10240
#define STG_BYTES 18944
#define NSTG      3
#define SMEM_MM   (NSTG * STG_BYTES)

// ---------------- scratch (device globals) ----------------
__device__ float g_so  [(size_t)BQ * DIMC * TT];
__device__ float g_x   [(size_t)BQ * DIMC * TT];
__device__ float g_beff[BQ * 1024];
__device__ float g_mu  [BQ * 32];
__device__ float g_rs  [BQ * 32];
__device__ float g_affa[BQ * 512];
__device__ float g_affb[BQ * 512];
__device__ float g_kmax[BQ * 256];
__device__ float g_kinv[BQ * 256];
__device__ float g_ctx [BQ * NH * 32 * 32];
__device__ float g_ctxp[8 * BQ * NH * 32 * 32];
__device__ float2 g_part[16384];
// fp16 planes
__device__ __align__(256) __half g_w16 [(size_t)BQ * 512 * 512];     // folded weights
__device__ __align__(256) __half g_h1  [(size_t)BQ * 512 * TT];      // activation plane (reused)
__device__ __align__(256) __half g_h2  [(size_t)BQ * 640 * TT];      // cq out / m1 out
__device__ __align__(256) __half g_bigh[(size_t)BQ * 768 * TT];      // qkv / ckv GEMM out

// ==================== PTX helpers (plain sm_80+ only) ====================
__device__ __forceinline__ unsigned s2u(const void* p) {
    unsigned a;
    asm("{ .reg .u64 t; cvta.to.shared.u64 t, %1; cvt.u32.u64 %0, t; }" : "=r"(a) : "l"(p));
    return a;
}
#define LDSM4(r, addr) \
    asm volatile("ldmatrix.sync.aligned.m8n8.x4.shared.b16 {%0,%1,%2,%3}, [%4];" \
        : "=r"((r)[0]), "=r"((r)[1]), "=r"((r)[2]), "=r"((r)[3]) : "r"(addr))
#define LDSM4T(r, addr) \
    asm volatile("ldmatrix.sync.aligned.m8n8.x4.trans.shared.b16 {%0,%1,%2,%3}, [%4];" \
        : "=r"((r)[0]), "=r"((r)[1]), "=r"((r)[2]), "=r"((r)[3]) : "r"(addr))
__device__ __forceinline__ void mma_f16(float* c, const unsigned* a, const unsigned* b) {
    asm volatile("mma.sync.aligned.m16n8k16.row.col.f32.f16.f16.f32 "
        "{%0,%1,%2,%3}, {%4,%5,%6,%7}, {%8,%9}, {%0,%1,%2,%3};"
        : "+f"(c[0]), "+f"(c[1]), "+f"(c[2]), "+f"(c[3])
        : "r"(a[0]), "r"(a[1]), "r"(a[2]), "r"(a[3]), "r"(b[0]), "r"(b[1]));
}
__device__ __forceinline__ void cp16(unsigned saddr, const void* gaddr) {
    asm volatile("cp.async.cg.shared.global [%0], [%1], 16;" :: "r"(saddr), "l"(gaddr));
}
__device__ __forceinline__ void cp_commit() {
    asm volatile("cp.async.commit_group;");
}
template <int N>
__device__ __forceinline__ void cp_wait() {
    asm volatile("cp.async.wait_group %0;" :: "n"(N));
}

// ==================== tensor-core GEMM (pure fp16 operands, fp32 accum) ====================
__global__ __launch_bounds__(256, 2)
void mm_kernel(const __half* __restrict__ A16, size_t aStrB,
               const float* __restrict__ bias, int perB,
               const __half* __restrict__ B16, size_t bStrB,
               float* __restrict__ Y, __half* __restrict__ Yh, size_t yStrB,
               const float* __restrict__ R, size_t rStrB,
               int M, int K, int ep)
{
    extern __shared__ char smem[];
    const unsigned sb = s2u(smem);
    const int tid = threadIdx.x, lane = tid & 31, wid = tid >> 5;
    const int wr = wid >> 2, wc = wid & 3;
    const int mt = blockIdx.x, nt = blockIdx.y, b = blockIdx.z;
    const int m0 = mt * 128, n0 = nt * 128;
    const __half* Ab = A16 + (size_t)b * aStrB;
    const __half* Bb = B16 + (size_t)b * bStrB;

    float acc[4][4][4];
    #pragma unroll
    for (int i = 0; i < 4; i++)
        #pragma unroll
        for (int j = 0; j < 4; j++)
            #pragma unroll
            for (int r = 0; r < 4; r++) acc[i][j][r] = 0.f;

    const unsigned aoff = (lane & 15) * 80  + (lane >> 4) * 16;
    const unsigned boff = (lane & 15) * 272 + (lane >> 4) * 16;
    const int nk = K >> 5;

    auto cpChunk = [&](int kc, int st) {
        unsigned base = sb + st * STG_BYTES;
        #pragma unroll
        for (int u = 0; u < 2; u++) {
            int f = tid + u * 256;
            int row = f >> 2, c16 = f & 3;
            cp16(base + row * 80 + c16 * 16,
                 Ab + (size_t)(m0 + row) * K + kc * 32 + c16 * 8);
        }
        #pragma unroll
        for (int u = 0; u < 2; u++) {
            int f = tid + u * 256;
            int r = f >> 4, c16 = f & 15;
            cp16(base + A_BYTES + r * 272 + c16 * 16,
                 Bb + (size_t)(kc * 32 + r) * TT + n0 + c16 * 8);
        }
        cp_commit();
    };

    auto compute = [&](int st) {
        unsigned stb = sb + st * STG_BYTES;
        #pragma unroll
        for (int ks = 0; ks < 2; ks++) {
            unsigned bh[2][4];
            #pragma unroll
            for (int np = 0; np < 2; np++)
                LDSM4T(bh[np], stb + A_BYTES + ks * 4352 + wc * 64 + np * 32 + boff);
            #pragma unroll
            for (int mf = 0; mf < 4; mf++) {
                unsigned ah[4];
                LDSM4(ah, stb + wr * 5120 + mf * 1280 + ks * 32 + aoff);
                #pragma unroll
                for (int nf = 0; nf < 4; nf++)
                    mma_f16(acc[mf][nf], ah, &bh[nf >> 1][(nf & 1) * 2]);
            }
        }
    };

    const int pre = nk < NSTG ? nk : NSTG;
    for (int i = 0; i < pre; i++) cpChunk(i, i);

    for (int i = 0; i < nk; i++) {
        if (i + 2 < nk)      cp_wait<2>();
        else if (i + 1 < nk) cp_wait<1>();
        else                 cp_wait<0>();
        __syncthreads();
        compute(i % NSTG);
        __syncthreads();
        if (i + NSTG < nk) cpChunk(i + NSTG, i % NSTG);
    }

    const float* biasB = bias + (perB ? (size_t)b * M : 0);
    #pragma unroll
    for (int mf = 0; mf < 4; mf++) {
        int gm = m0 + wr * 64 + mf * 16 + (lane >> 2);
        float bv0 = biasB[gm], bv1 = biasB[gm + 8];
        #pragma unroll
        for (int nf = 0; nf < 4; nf++) {
            int gn = n0 + wc * 32 + nf * 8 + (lane & 3) * 2;
            float* a4 = acc[mf][nf];
            float2 v0 = make_float2(a4[0] + bv0, a4[1] + bv0);
            float2 v1 = make_float2(a4[2] + bv1, a4[3] + bv1);
            if (ep == 1) {
                v0.x /= (1.f + expf(-v0.x)); v0.y /= (1.f + expf(-v0.y));
                v1.x /= (1.f + expf(-v1.x)); v1.y /= (1.f + expf(-v1.y));
            } else if (ep == 2) {
                const float* Rb = R + (size_t)b * rStrB;
                float2 r0 = *(const float2*)&Rb[(size_t)gm * TT + gn];
                float2 r1 = *(const float2*)&Rb[(size_t)(gm + 8) * TT + gn];
                v0.x += r0.x; v0.y += r0.y; v1.x += r1.x; v1.y += r1.y;
            }
            if (Yh) {
                __half* Yb = Yh + (size_t)b * yStrB;
                *(__half2*)&Yb[(size_t)gm * TT + gn] =
                    __halves2half2(__float2half(v0.x), __float2half(v0.y));
                *(__half2*)&Yb[(size_t)(gm + 8) * TT + gn] =
                    __halves2half2(__float2half(v1.x), __float2half(v1.y));
            } else {
                float* Yb = Y + (size_t)b * yStrB;
                *(float2*)&Yb[(size_t)gm * TT + gn] = v0;
                *(float2*)&Yb[(size_t)(gm + 8) * TT + gn] = v1;
            }
        }
    }
}

// ==================== weight fold ====================
__global__ void conv_w_kernel(const float* __restrict__ W, const float* __restrict__ aS,
                              __half* __restrict__ dst, int MK, int K)
{
    int b = blockIdx.y;
    int idx = (blockIdx.x * 256 + threadIdx.x) * 4;
    int k = idx % K;
    float4 w = *(const float4*)(W + idx);
    if (aS) {
        const float* a = aS + b * K + k;
        w.x *= a[0]; w.y *= a[1]; w.z *= a[2]; w.w *= a[3];
    }
    __half h[4] = {__float2half(w.x), __float2half(w.y), __float2half(w.z), __float2half(w.w)};
    *(uint2*)(dst + (size_t)b * MK + idx) = *(uint2*)h;
}

// ==================== group-norm stats (+ optional fused fp16 convert) ====================
__global__ void gn_stats_kernel(const float* __restrict__ x, int GC,
                                float* __restrict__ mu, float* __restrict__ rs)
{
    const size_t n = (size_t)GC * TT;
    const float4* x4 = (const float4*)(x + (size_t)blockIdx.x * n);
    const int n4 = (int)(n >> 2);
    float s = 0.f, sq = 0.f;
    for (int i = threadIdx.x; i < n4; i += 256) {
        float4 v = x4[i];
        s += (v.x + v.y) + (v.z + v.w);
        sq += v.x*v.x + v.y*v.y + v.z*v.z + v.w*v.w;
    }
    __shared__ float sh1[8], sh2[8];
    int lane = threadIdx.x & 31, w = threadIdx.x >> 5;
    #pragma unroll
    for (int o = 16; o > 0; o >>= 1) {
        s += __shfl_xor_sync(0xffffffffu, s, o);
        sq += __shfl_xor_sync(0xffffffffu, sq, o);
    }
    if (lane == 0) { sh1[w] = s; sh2[w] = sq; }
    __syncthreads();
    if (threadIdx.x < 8) {
        s = sh1[threadIdx.x]; sq = sh2[threadIdx.x];
        #pragma unroll
        for (int o = 4; o > 0; o >>= 1) {
            s += __shfl_xor_sync(0xffu, s, o);
            sq += __shfl_xor_sync(0xffu, sq, o);
        }
        if (threadIdx.x == 0) {
            float inv_n = 1.f / (float)n;
            float m = s * inv_n;
            float var = sq * inv_n - m * m;
            mu[blockIdx.x] = m;
            rs[blockIdx.x] = rsqrtf(fmaxf(var, 0.f) + EPSV);
        }
    }
}

// stats + fp32->fp16 convert in one pass
__global__ void gn_stats_conv_kernel(const float* __restrict__ x, __half* __restrict__ xh,
                                     int GC, float* __restrict__ mu, float* __restrict__ rs)
{
    const size_t n = (size_t)GC * TT;
    const size_t base = (size_t)blockIdx.x * n;
    const float4* x4 = (const float4*)(x + base);
    const int n4 = (int)(n >> 2);
    float s = 0.f, sq = 0.f;
    for (int i = threadIdx.x; i < n4; i += 256) {
        float4 v = x4[i];
        s += (v.x + v.y) + (v.z + v.w);
        sq += v.x*v.x + v.y*v.y + v.z*v.z + v.w*v.w;
        __half h[4] = {__float2half(v.x), __float2half(v.y),
                       __float2half(v.z), __float2half(v.w)};
        *(uint2*)(xh + base + (size_t)i * 4) = *(uint2*)h;
    }
    __shared__ float sh1[8], sh2[8];
    int lane = threadIdx.x & 31, w = threadIdx.x >> 5;
    #pragma unroll
    for (int o = 16; o > 0; o >>= 1) {
        s += __shfl_xor_sync(0xffffffffu, s, o);
        sq += __shfl_xor_sync(0xffffffffu, sq, o);
    }
    if (lane == 0) { sh1[w] = s; sh2[w] = sq; }
    __syncthreads();
    if (threadIdx.x < 8) {
        s = sh1[threadIdx.x]; sq = sh2[threadIdx.x];
        #pragma unroll
        for (int o = 4; o > 0; o >>= 1) {
            s += __shfl_xor_sync(0xffu, s, o);
            sq += __shfl_xor_sync(0xffu, sq, o);
        }
        if (threadIdx.x == 0) {
            float inv_n = 1.f / (float)n;
            float m = s * inv_n;
            float var = sq * inv_n - m * m;
            mu[blockIdx.x] = m;
            rs[blockIdx.x] = rsqrtf(fmaxf(var, 0.f) + EPSV);
        }
    }
}

__global__ void affine_kernel(const float* __restrict__ g, const float* __restrict__ be,
                              const float* __restrict__ mu, const float* __restrict__ rs,
                              float* __restrict__ a, float* __restrict__ bb, int C)
{
    int b = blockIdx.x;
    int GC = C >> 5;
    for (int c = threadIdx.x; c < C; c += blockDim.x) {
        int grp = c / GC;
        float r = rs[b*32 + grp], m = mu[b*32 + grp];
        float av = g[c] * r;
        a [b*C + c] = av;
        bb[b*C + c] = be[c] - m * av;
    }
}

__global__ void beff_kernel(const float* __restrict__ W, const float* __restrict__ bbv,
                            const float* __restrict__ bias, float* __restrict__ beff,
                            int M, int K)
{
    int m = blockIdx.x, b = blockIdx.y;
    float s = 0.f;
    for (int k = threadIdx.x; k < K; k += 128)
        s += W[(size_t)m*K + k] * bbv[b*K + k];
    __shared__ float sh[4];
    int lane = threadIdx.x & 31, w = threadIdx.x >> 5;
    #pragma unroll
    for (int o = 16; o > 0; o >>= 1) s += __shfl_xor_sync(0xffffffffu, s, o);
    if (lane == 0) sh[w] = s;
    __syncthreads();
    if (threadIdx.x == 0)
        beff[(size_t)b*M + m] = sh[0] + sh[1] + sh[2] + sh[3] + (bias ? bias[m] : 0.f);
}

// ==================== attention kernels (fp16 planes) ====================
__global__ void ksm_stats_kernel(const __half* __restrict__ kbase, size_t strideB,
                                 float* __restrict__ kmax, float* __restrict__ kinv)
{
    int r = blockIdx.x, b = blockIdx.y;
    const uint4* p8 = (const uint4*)(kbase + (size_t)b * strideB + (size_t)r * TT);
    float mx = -1e30f;
    for (int i = threadIdx.x; i < TT/8; i += 256) {
        uint4 v = p8[i];
        const __half2* hh = (const __half2*)&v;
        #pragma unroll
        for (int j = 0; j < 4; j++) {
            float2 f = __half22float2(hh[j]);
            mx = fmaxf(mx, fmaxf(f.x, f.y));
        }
    }
    __shared__ float sh[8];
    __shared__ float bmax, bsum;
    int lane = threadIdx.x & 31, w = threadIdx.x >> 5;
    #pragma unroll
    for (int o = 16; o > 0; o >>= 1) mx = fmaxf(mx, __shfl_xor_sync(0xffffffffu, mx, o));
    if (lane == 0) sh[w] = mx;
    __syncthreads();
    if (threadIdx.x < 8) {
        mx = sh[threadIdx.x];
        #pragma unroll
        for (int o = 4; o > 0; o >>= 1) mx = fmaxf(mx, __shfl_xor_sync(0xffu, mx, o));
        if (threadIdx.x == 0) bmax = mx;
    }
    __syncthreads();
    float m = bmax;
    float s = 0.f;
    for (int i = threadIdx.x; i < TT/8; i += 256) {
        uint4 v = p8[i];
        const __half2* hh = (const __half2*)&v;
        #pragma unroll
        for (int j = 0; j < 4; j++) {
            float2 f = __half22float2(hh[j]);
            s += expf(f.x - m) + expf(f.y - m);
        }
    }
    #pragma unroll
    for (int o = 16; o > 0; o >>= 1) s += __shfl_xor_sync(0xffffffffu, s, o);
    if (lane == 0) sh[w] = s;
    __syncthreads();
    if (threadIdx.x < 8) {
        s = sh[threadIdx.x];
        #pragma unroll
        for (int o = 4; o > 0; o >>= 1) s += __shfl_xor_sync(0xffu, s, o);
        if (threadIdx.x == 0) bsum = s;
    }
    __syncthreads();
    if (threadIdx.x == 0) { kmax[b*256 + r] = m; kinv[b*256 + r] = 1.f / bsum; }
}

__global__ void ctx_kernel(const __half* __restrict__ kv, size_t strideB, int koff, int voff,
                           const float* __restrict__ kmax, const float* __restrict__ kinv,
                           float* __restrict__ cpart)
{
    int bh = blockIdx.x;
    int slice = blockIdx.y;
    int b = bh / NH, h = bh % NH;
    __shared__ float ks[32][65], vs[32][65];
    __shared__ float km[32], ki[32];
    int tid = threadIdx.x;
    if (tid < 32) {
        km[tid] = kmax[b*256 + h*32 + tid];
        ki[tid] = kinv[b*256 + h*32 + tid];
    }
    const __half* kp = kv + (size_t)b*strideB + (size_t)(koff + h*32)*TT + slice*1024;
    const __half* vp = kv + (size_t)b*strideB + (size_t)(voff + h*32)*TT + slice*1024;
    int d = tid >> 3, e0 = (tid & 7) * 4;
    float c0 = 0.f, c1 = 0.f, c2 = 0.f, c3 = 0.f;
    for (int tc = 0; tc < 1024; tc += 64) {
        __syncthreads();
        for (int i = tid; i < 32*64; i += 256) {
            int r = i >> 6, t = i & 63;
            ks[r][t] = expf(__half2float(kp[(size_t)r*TT + tc + t]) - km[r]) * ki[r];
            vs[r][t] = __half2float(vp[(size_t)r*TT + tc + t]);
        }
        __syncthreads();
        #pragma unroll 8
        for (int t = 0; t < 64; t++) {
            float kd = ks[d][t];
            c0 += kd * vs[e0+0][t];
            c1 += kd * vs[e0+1][t];
            c2 += kd * vs[e0+2][t];
            c3 += kd * vs[e0+3][t];
        }
    }
    float* cp = cpart + (size_t)slice*65536 + (size_t)bh*1024 + d*32 + e0;
    cp[0] = c0; cp[1] = c1; cp[2] = c2; cp[3] = c3;
}

__global__ void ctx_reduce_kernel(const float* __restrict__ cpart, float* __restrict__ ctx)
{
    int i = blockIdx.x * 256 + threadIdx.x;
    float s = 0.f;
    #pragma unroll
    for (int sl = 0; sl < 8; sl++) s += cpart[(size_t)sl*65536 + i];
    ctx[i] = s;
}

__global__ void attn_out_kernel(const __half* __restrict__ q, size_t strideB, int qoff,
                                const float* __restrict__ ctx,
                                __half* __restrict__ o, size_t oStrideB)
{
    int bh = blockIdx.x;
    int b = bh / NH, h = bh % NH;
    int t = blockIdx.y * 256 + threadIdx.x;
    __shared__ float cs[32][32];
    for (int i = threadIdx.x; i < 1024; i += 256)
        cs[i >> 5][i & 31] = ctx[(size_t)bh*1024 + i];
    __syncthreads();
    const __half* qp = q + (size_t)b*strideB + (size_t)(qoff + h*32)*TT + t;
    float p[32];
    float mx = -1e30f;
    #pragma unroll
    for (int d = 0; d < 32; d++) { p[d] = __half2float(qp[(size_t)d*TT]); mx = fmaxf(mx, p[d]); }
    float s = 0.f;
    #pragma unroll
    for (int d = 0; d < 32; d++) { p[d] = expf(p[d] - mx); s += p[d]; }
    float inv = 0.17677669529663687f / s;
    #pragma unroll
    for (int d = 0; d < 32; d++) p[d] *= inv;
    float accv[32];
    #pragma unroll
    for (int e = 0; e < 32; e++) accv[e] = 0.f;
    #pragma unroll
    for (int d = 0; d < 32; d++) {
        float pd = p[d];
        #pragma unroll
        for (int e4 = 0; e4 < 8; e4++) {
            float4 cv = *(const float4*)&cs[d][e4*4];
            accv[e4*4+0] += cv.x * pd;
            accv[e4*4+1] += cv.y * pd;
            accv[e4*4+2] += cv.z * pd;
            accv[e4*4+3] += cv.w * pd;
        }
    }
    __half* op = o + (size_t)b*oStrideB + (size_t)(h*32)*TT + t;
    #pragma unroll
    for (int e = 0; e < 32; e++) op[(size_t)e*TT] = __float2half(accv[e]);
}

// y = gn(v)*g + b + r ; writes fp32 y, fp16 yh, and per-block (sum,sumsq) partials of y
__global__ void gn_add_kernel(const float* __restrict__ v,
                              const float* __restrict__ gamma, const float* __restrict__ beta,
                              const float* __restrict__ mu, const float* __restrict__ rs,
                              const float* __restrict__ r, float* __restrict__ y,
                              __half* __restrict__ yh, float2* __restrict__ part)
{
    size_t i = ((size_t)blockIdx.x * 256 + threadIdx.x) * 4;
    int c = (int)((i / TT) % DIMC);
    int b = (int)(i / ((size_t)DIMC * TT));
    int grp = c >> 3;
    float rr = rs[b*32 + grp], m = mu[b*32 + grp];
    float sc = gamma[c] * rr;
    float sh = beta[c] - m * sc;
    float4 vv = *(const float4*)(v + i);
    float4 rv = *(const float4*)(r + i);
    float4 o;
    o.x = vv.x * sc + sh + rv.x;
    o.y = vv.y * sc + sh + rv.y;
    o.z = vv.z * sc + sh + rv.z;
    o.w = vv.w * sc + sh + rv.w;
    *(float4*)(y + i) = o;
    __half h[4] = {__float2half(o.x), __float2half(o.y), __float2half(o.z), __float2half(o.w)};
    *(uint2*)(yh + i) = *(uint2*)h;

    float s  = (o.x + o.y) + (o.z + o.w);
    float sq = o.x*o.x + o.y*o.y + o.z*o.z + o.w*o.w;
    __shared__ float sh1[8], sh2[8];
    int lane = threadIdx.x & 31, w = threadIdx.x >> 5;
    #pragma unroll
    for (int o2 = 16; o2 > 0; o2 >>= 1) {
        s  += __shfl_xor_sync(0xffffffffu, s,  o2);
        sq += __shfl_xor_sync(0xffffffffu, sq, o2);
    }
    if (lane == 0) { sh1[w] = s; sh2[w] = sq; }
    __syncthreads();
    if (threadIdx.x < 8) {
        s = sh1[threadIdx.x]; sq = sh2[threadIdx.x];
        #pragma unroll
        for (int o2 = 4; o2 > 0; o2 >>= 1) {
            s  += __shfl_xor_sync(0xffu, s,  o2);
            sq += __shfl_xor_sync(0xffu, sq, o2);
        }
        if (threadIdx.x == 0) part[blockIdx.x] = make_float2(s, sq);
    }
}

// reduce 64 block-partials per group -> mu, rs  (group size = 65536 elements)
__global__ void gn_reduce_kernel(const float2* __restrict__ part,
                                 float* __restrict__ mu, float* __restrict__ rs)
{
    int g = blockIdx.x;                 // 256 groups
    int t = threadIdx.x;                // 64 threads
    float2 p = part[g * 64 + t];
    float s = p.x, sq = p.y;
    #pragma unroll
    for (int o = 16; o > 0; o >>= 1) {
        s  += __shfl_xor_sync(0xffffffffu, s,  o);
        sq += __shfl_xor_sync(0xffffffffu, sq, o);
    }
    __shared__ float a[2], bsh[2];
    if ((t & 31) == 0) { a[t >> 5] = s; bsh[t >> 5] = sq; }
    __syncthreads();
    if (t == 0) {
        s = a[0] + a[1]; sq = bsh[0] + bsh[1];
        const float inv_n = 1.f / 65536.f;
        float m = s * inv_n;
        float var = sq * inv_n - m * m;
        mu[g] = m;
        rs[g] = rsqrtf(fmaxf(var, 0.f) + EPSV);
    }
}

// ==================== host orchestration ====================
extern "C" void kernel_launch(void* const* d_in, const int* in_sizes, int n_in,
                              void* d_out, int out_size)
{
    const float* x     = (const float*)d_in[0];
    const float* c     = (const float*)d_in[1];
    const float* W_qkv = (const float*)d_in[2];
    const float* W_so  = (const float*)d_in[3];
    const float* b_so  = (const float*)d_in[4];
    const float* sa_g  = (const float*)d_in[5];
    const float* sa_b  = (const float*)d_in[6];
    const float* W_cq  = (const float*)d_in[7];
    const float* W_ckv = (const float*)d_in[8];
    const float* W_co  = (const float*)d_in[9];
    const float* b_co  = (const float*)d_in[10];
    const float* ca_g  = (const float*)d_in[11];
    const float* ca_b  = (const float*)d_in[12];
    const float* W_m1  = (const float*)d_in[13];
    const float* b_m1  = (const float*)d_in[14];
    const float* W_m2  = (const float*)d_in[15];
    const float* b_m2  = (const float*)d_in[16];
    const float* nm_g  = (const float*)d_in[17];
    const float* nm_b  = (const float*)d_in[18];
    const float* nm1_g = (const float*)d_in[19];
    const float* nm1_b = (const float*)d_in[20];
    const float* nm2_g = (const float*)d_in[21];
    const float* nm2_b = (const float*)d_in[22];
    const float* nm3_g = (const float*)d_in[23];
    const float* nm3_b = (const float*)d_in[24];
    float* out = (float*)d_out;

    float *so, *xb, *beff, *mu, *rs, *aa, *ab, *kmax, *kinv, *ctx, *ctxp;
    float2* part;
    __half *w16, *h1, *h2, *bigh;
    cudaGetSymbolAddress((void**)&so,   g_so);
    cudaGetSymbolAddress((void**)&xb,   g_x);
    cudaGetSymbolAddress((void**)&beff, g_beff);
    cudaGetSymbolAddress((void**)&mu,   g_mu);
    cudaGetSymbolAddress((void**)&rs,   g_rs);
    cudaGetSymbolAddress((void**)&aa,   g_affa);
    cudaGetSymbolAddress((void**)&ab,   g_affb);
    cudaGetSymbolAddress((void**)&kmax, g_kmax);
    cudaGetSymbolAddress((void**)&kinv, g_kinv);
    cudaGetSymbolAddress((void**)&ctx,  g_ctx);
    cudaGetSymbolAddress((void**)&ctxp, g_ctxp);
    cudaGetSymbolAddress((void**)&part, g_part);
    cudaGetSymbolAddress((void**)&w16,  g_w16);
    cudaGetSymbolAddress((void**)&h1,   g_h1);
    cudaGetSymbolAddress((void**)&h2,   g_h2);
    cudaGetSymbolAddress((void**)&bigh, g_bigh);

    static bool attr_set = false;
    if (!attr_set) {
        cudaFuncSetAttribute(mm_kernel, cudaFuncAttributeMaxDynamicSharedMemorySize, SMEM_MM);
        attr_set = true;
    }

    const size_t XT = (size_t)DIMC * TT;

    // ================= Phase 1: self linear attention =================
    gn_stats_conv_kernel<<<BQ*32, 256>>>(x, h1, 8, mu, rs);              // x stats + x->fp16
    affine_kernel<<<BQ, 256>>>(nm_g, nm_b, mu, rs, aa, ab, 256);
    conv_w_kernel<<<dim3(192, BQ), 256>>>(W_qkv, aa, w16, 768*256, 256);
    beff_kernel<<<dim3(768, BQ), 128>>>(W_qkv, ab, nullptr, beff, 768, 256);
    mm_kernel<<<dim3(6, 64, BQ), 256, SMEM_MM>>>(w16, (size_t)768*256, beff, 1,
                                                 h1, XT, nullptr, bigh, (size_t)768*TT,
                                                 nullptr, 0, 768, 256, 0);
    ksm_stats_kernel<<<dim3(256, BQ), 256>>>(bigh + (size_t)256*TT, (size_t)768*TT, kmax, kinv);
    ctx_kernel<<<dim3(64, 8), 256>>>(bigh, (size_t)768*TT, 256, 512, kmax, kinv, ctxp);
    ctx_reduce_kernel<<<256, 256>>>(ctxp, ctx);
    attn_out_kernel<<<dim3(64, 32), 256>>>(bigh, (size_t)768*TT, 0, ctx, h1, XT);
    conv_w_kernel<<<dim3(64, 1), 256>>>(W_so, nullptr, w16, 256*256, 256);
    mm_kernel<<<dim3(2, 64, BQ), 256, SMEM_MM>>>(w16, 0, b_so, 0,
                                                 h1, XT, so, nullptr, XT,
                                                 nullptr, 0, 256, 256, 0);
    gn_stats_kernel<<<BQ*32, 256>>>(so, 8, mu, rs);
    gn_add_kernel<<<16384, 256>>>(so, sa_g, sa_b, mu, rs, x, xb, h1, part);
    gn_reduce_kernel<<<256, 64>>>(part, mu, rs);                         // xb stats (for nm1)

    // ================= Phase 2: cross linear attention =================
    affine_kernel<<<BQ, 256>>>(nm1_g, nm1_b, mu, rs, aa, ab, 256);
    conv_w_kernel<<<dim3(64, BQ), 256>>>(W_cq, aa, w16, 256*256, 256);
    beff_kernel<<<dim3(256, BQ), 128>>>(W_cq, ab, nullptr, beff, 256, 256);
    mm_kernel<<<dim3(2, 64, BQ), 256, SMEM_MM>>>(w16, (size_t)256*256, beff, 1,
                                                 h1, XT, nullptr, h2, XT,
                                                 nullptr, 0, 256, 256, 0);
    gn_stats_conv_kernel<<<BQ*32, 256>>>(c, h1, 16, mu, rs);             // c stats + c->fp16
    affine_kernel<<<BQ, 256>>>(nm3_g, nm3_b, mu, rs, aa, ab, 512);
    conv_w_kernel<<<dim3(256, BQ), 256>>>(W_ckv, aa, w16, 512*512, 512);
    beff_kernel<<<dim3(512, BQ), 128>>>(W_ckv, ab, nullptr, beff, 512, 512);
    mm_kernel<<<dim3(4, 64, BQ), 256, SMEM_MM>>>(w16, (size_t)512*512, beff, 1,
                                                 h1, (size_t)512*TT, nullptr, bigh, (size_t)512*TT,
                                                 nullptr, 0, 512, 512, 0);
    ksm_stats_kernel<<<dim3(256, BQ), 256>>>(bigh, (size_t)512*TT, kmax, kinv);
    ctx_kernel<<<dim3(64, 8), 256>>>(bigh, (size_t)512*TT, 0, 256, kmax, kinv, ctxp);
    ctx_reduce_kernel<<<256, 256>>>(ctxp, ctx);
    attn_out_kernel<<<dim3(64, 32), 256>>>(h2, XT, 0, ctx, h1, XT);
    conv_w_kernel<<<dim3(64, 1), 256>>>(W_co, nullptr, w16, 256*256, 256);
    mm_kernel<<<dim3(2, 64, BQ), 256, SMEM_MM>>>(w16, 0, b_co, 0,
                                                 h1, XT, so, nullptr, XT,
                                                 nullptr, 0, 256, 256, 0);
    gn_stats_kernel<<<BQ*32, 256>>>(so, 8, mu, rs);
    gn_add_kernel<<<16384, 256>>>(so, ca_g, ca_b, mu, rs, xb, xb, h1, part);
    gn_reduce_kernel<<<256, 64>>>(part, mu, rs);                         // xb stats (for nm2)

    // ================= Phase 3: SiLU MLP =================
    affine_kernel<<<BQ, 256>>>(nm2_g, nm2_b, mu, rs, aa, ab, 256);
    conv_w_kernel<<<dim3(160, BQ), 256>>>(W_m1, aa, w16, 640*256, 256);
    beff_kernel<<<dim3(640, BQ), 128>>>(W_m1, ab, b_m1, beff, 640, 256);
    mm_kernel<<<dim3(5, 64, BQ), 256, SMEM_MM>>>(w16, (size_t)640*256, beff, 1,
                                                 h1, XT, nullptr, h2, (size_t)640*TT,
                                                 nullptr, 0, 640, 256, 1 /*silu, fp16 out*/);
    conv_w_kernel<<<dim3(160, 1), 256>>>(W_m2, nullptr, w16, 256*640, 640);
    mm_kernel<<<dim3(2, 64, BQ), 256, SMEM_MM>>>(w16, 0, b_m2, 0,
                                                 h2, (size_t)640*TT, out, nullptr, XT,
                                                 xb, XT, 256, 640, 2 /*residual*/);
}

// round 13
// speedup vs baseline: 2.9728x; 1.0086x over previous
#include <cuda_runtime.h>
#include <cuda_fp16.h>
#include <cstdint>

#define BQ 8
#define DIMC 256
#define TT 8192
#define NH 8
#define EPSV 1e-5f

// fp16 stage: A[128 rows x 32k, pad 40h]=10240B, B[32k x 128n, pad 136h]=8704B
#define A_BYTES   10240
#define STG_BYTES 18944
#define NSTG      3
#define SMEM_MM   (NSTG * STG_BYTES)

// ---------------- scratch (device globals) ----------------
__device__ float g_x   [(size_t)BQ * DIMC * TT];     // xb residual (fp32)
__device__ float g_beff[BQ * 1024];
__device__ float g_mu  [BQ * 32];
__device__ float g_rs  [BQ * 32];
__device__ float g_ctx [BQ * NH * 32 * 32];
__device__ float g_ctxp[8 * BQ * NH * 32 * 32];
__device__ float g_cmax[8 * BQ * NH * 32];
__device__ float g_csum[8 * BQ * NH * 32];
__device__ float2 g_part[16384];
// fp16 planes
__device__ __align__(256) __half g_w16 [(size_t)BQ * 512 * 512];     // folded weights
__device__ __align__(256) __half g_h1  [(size_t)BQ * 512 * TT];      // activation plane (reused)
__device__ __align__(256) __half g_h2  [(size_t)BQ * 640 * TT];      // cq out / m1 out
__device__ __align__(256) __half g_bigh[(size_t)BQ * 768 * TT];      // qkv/ckv out; later so plane

// ==================== PTX helpers (plain sm_80+ only) ====================
__device__ __forceinline__ unsigned s2u(const void* p) {
    unsigned a;
    asm("{ .reg .u64 t; cvta.to.shared.u64 t, %1; cvt.u32.u64 %0, t; }" : "=r"(a) : "l"(p));
    return a;
}
#define LDSM4(r, addr) \
    asm volatile("ldmatrix.sync.aligned.m8n8.x4.shared.b16 {%0,%1,%2,%3}, [%4];" \
        : "=r"((r)[0]), "=r"((r)[1]), "=r"((r)[2]), "=r"((r)[3]) : "r"(addr))
#define LDSM4T(r, addr) \
    asm volatile("ldmatrix.sync.aligned.m8n8.x4.trans.shared.b16 {%0,%1,%2,%3}, [%4];" \
        : "=r"((r)[0]), "=r"((r)[1]), "=r"((r)[2]), "=r"((r)[3]) : "r"(addr))
__device__ __forceinline__ void mma_f16(float* c, const unsigned* a, const unsigned* b) {
    asm volatile("mma.sync.aligned.m16n8k16.row.col.f32.f16.f16.f32 "
        "{%0,%1,%2,%3}, {%4,%5,%6,%7}, {%8,%9}, {%0,%1,%2,%3};"
        : "+f"(c[0]), "+f"(c[1]), "+f"(c[2]), "+f"(c[3])
        : "r"(a[0]), "r"(a[1]), "r"(a[2]), "r"(a[3]), "r"(b[0]), "r"(b[1]));
}
__device__ __forceinline__ void cp16(unsigned saddr, const void* gaddr) {
    asm volatile("cp.async.cg.shared.global [%0], [%1], 16;" :: "r"(saddr), "l"(gaddr));
}
__device__ __forceinline__ void cp_commit() {
    asm volatile("cp.async.commit_group;");
}
template <int N>
__device__ __forceinline__ void cp_wait() {
    asm volatile("cp.async.wait_group %0;" :: "n"(N));
}

// ==================== tensor-core GEMM (pure fp16 operands, fp32 accum) ====================
__global__ __launch_bounds__(256, 2)
void mm_kernel(const __half* __restrict__ A16, size_t aStrB,
               const float* __restrict__ bias, int perB,
               const __half* __restrict__ B16, size_t bStrB,
               float* __restrict__ Y, __half* __restrict__ Yh, size_t yStrB,
               const float* __restrict__ R, size_t rStrB,
               int M, int K, int ep)
{
    extern __shared__ char smem[];
    const unsigned sb = s2u(smem);
    const int tid = threadIdx.x, lane = tid & 31, wid = tid >> 5;
    const int wr = wid >> 2, wc = wid & 3;
    const int mt = blockIdx.x, nt = blockIdx.y, b = blockIdx.z;
    const int m0 = mt * 128, n0 = nt * 128;
    const __half* Ab = A16 + (size_t)b * aStrB;
    const __half* Bb = B16 + (size_t)b * bStrB;

    float acc[4][4][4];
    #pragma unroll
    for (int i = 0; i < 4; i++)
        #pragma unroll
        for (int j = 0; j < 4; j++)
            #pragma unroll
            for (int r = 0; r < 4; r++) acc[i][j][r] = 0.f;

    const unsigned aoff = (lane & 15) * 80  + (lane >> 4) * 16;
    const unsigned boff = (lane & 15) * 272 + (lane >> 4) * 16;
    const int nk = K >> 5;

    auto cpChunk = [&](int kc, int st) {
        unsigned base = sb + st * STG_BYTES;
        #pragma unroll
        for (int u = 0; u < 2; u++) {
            int f = tid + u * 256;
            int row = f >> 2, c16 = f & 3;
            cp16(base + row * 80 + c16 * 16,
                 Ab + (size_t)(m0 + row) * K + kc * 32 + c16 * 8);
        }
        #pragma unroll
        for (int u = 0; u < 2; u++) {
            int f = tid + u * 256;
            int r = f >> 4, c16 = f & 15;
            cp16(base + A_BYTES + r * 272 + c16 * 16,
                 Bb + (size_t)(kc * 32 + r) * TT + n0 + c16 * 8);
        }
        cp_commit();
    };

    auto compute = [&](int st) {
        unsigned stb = sb + st * STG_BYTES;
        #pragma unroll
        for (int ks = 0; ks < 2; ks++) {
            unsigned bh[2][4];
            #pragma unroll
            for (int np = 0; np < 2; np++)
                LDSM4T(bh[np], stb + A_BYTES + ks * 4352 + wc * 64 + np * 32 + boff);
            #pragma unroll
            for (int mf = 0; mf < 4; mf++) {
                unsigned ah[4];
                LDSM4(ah, stb + wr * 5120 + mf * 1280 + ks * 32 + aoff);
                #pragma unroll
                for (int nf = 0; nf < 4; nf++)
                    mma_f16(acc[mf][nf], ah, &bh[nf >> 1][(nf & 1) * 2]);
            }
        }
    };

    const int pre = nk < NSTG ? nk : NSTG;
    for (int i = 0; i < pre; i++) cpChunk(i, i);

    for (int i = 0; i < nk; i++) {
        if (i + 2 < nk)      cp_wait<2>();
        else if (i + 1 < nk) cp_wait<1>();
        else                 cp_wait<0>();
        __syncthreads();
        compute(i % NSTG);
        __syncthreads();
        if (i + NSTG < nk) cpChunk(i + NSTG, i % NSTG);
    }

    const float* biasB = bias + (perB ? (size_t)b * M : 0);
    #pragma unroll
    for (int mf = 0; mf < 4; mf++) {
        int gm = m0 + wr * 64 + mf * 16 + (lane >> 2);
        float bv0 = biasB[gm], bv1 = biasB[gm + 8];
        #pragma unroll
        for (int nf = 0; nf < 4; nf++) {
            int gn = n0 + wc * 32 + nf * 8 + (lane & 3) * 2;
            float* a4 = acc[mf][nf];
            float2 v0 = make_float2(a4[0] + bv0, a4[1] + bv0);
            float2 v1 = make_float2(a4[2] + bv1, a4[3] + bv1);
            if (ep == 1) {
                v0.x /= (1.f + expf(-v0.x)); v0.y /= (1.f + expf(-v0.y));
                v1.x /= (1.f + expf(-v1.x)); v1.y /= (1.f + expf(-v1.y));
            } else if (ep == 2) {
                const float* Rb = R + (size_t)b * rStrB;
                float2 r0 = *(const float2*)&Rb[(size_t)gm * TT + gn];
                float2 r1 = *(const float2*)&Rb[(size_t)(gm + 8) * TT + gn];
                v0.x += r0.x; v0.y += r0.y; v1.x += r1.x; v1.y += r1.y;
            }
            if (Yh) {
                __half* Yb = Yh + (size_t)b * yStrB;
                *(__half2*)&Yb[(size_t)gm * TT + gn] =
                    __halves2half2(__float2half(v0.x), __float2half(v0.y));
                *(__half2*)&Yb[(size_t)(gm + 8) * TT + gn] =
                    __halves2half2(__float2half(v1.x), __float2half(v1.y));
            } else {
                float* Yb = Y + (size_t)b * yStrB;
                *(float2*)&Yb[(size_t)gm * TT + gn] = v0;
                *(float2*)&Yb[(size_t)(gm + 8) * TT + gn] = v1;
            }
        }
    }
}

// ==================== wprep: fused affine + weight fold + beff ====================
// grid (M/32, B), 256 threads. If g==null: a=1, bb=0 (plain convert, beff=bias).
__global__ void wprep_kernel(const float* __restrict__ W,
                             const float* __restrict__ g, const float* __restrict__ be,
                             const float* __restrict__ mu, const float* __restrict__ rs,
                             const float* __restrict__ bias,
                             __half* __restrict__ w16, float* __restrict__ beff,
                             int M, int K)
{
    __shared__ float a_s[640], bb_s[640];
    const int b = blockIdx.y;
    const int GC = K >> 5;
    for (int c = threadIdx.x; c < K; c += 256) {
        if (g) {
            int grp = c / GC;
            float r = rs[b*32 + grp], m = mu[b*32 + grp];
            float av = g[c] * r;
            a_s[c] = av;
            bb_s[c] = be[c] - m * av;
        } else { a_s[c] = 1.f; bb_s[c] = 0.f; }
    }
    __syncthreads();
    const int m = blockIdx.x * 32 + (threadIdx.x >> 3);
    const int l8 = threadIdx.x & 7;
    const float* Wr = W + (size_t)m * K;
    __half* dst = w16 + (size_t)b * M * K + (size_t)m * K;
    float dot = 0.f;
    for (int k0 = l8 * 4; k0 < K; k0 += 32) {
        float4 w = *(const float4*)(Wr + k0);
        dot += w.x*bb_s[k0] + w.y*bb_s[k0+1] + w.z*bb_s[k0+2] + w.w*bb_s[k0+3];
        __half h[4] = {__float2half(w.x * a_s[k0]),   __float2half(w.y * a_s[k0+1]),
                       __float2half(w.z * a_s[k0+2]), __float2half(w.w * a_s[k0+3])};
        *(uint2*)(dst + k0) = *(uint2*)h;
    }
    dot += __shfl_down_sync(0xffffffffu, dot, 4, 8);
    dot += __shfl_down_sync(0xffffffffu, dot, 2, 8);
    dot += __shfl_down_sync(0xffffffffu, dot, 1, 8);
    if (l8 == 0)
        beff[(size_t)b * M + m] = dot + (bias ? bias[m] : 0.f);
}

// ==================== group-norm stats ====================
__global__ void gn_stats_conv_kernel(const float* __restrict__ x, __half* __restrict__ xh,
                                     int GC, float* __restrict__ mu, float* __restrict__ rs)
{
    const size_t n = (size_t)GC * TT;
    const size_t base = (size_t)blockIdx.x * n;
    const float4* x4 = (const float4*)(x + base);
    const int n4 = (int)(n >> 2);
    float s = 0.f, sq = 0.f;
    for (int i = threadIdx.x; i < n4; i += 256) {
        float4 v = x4[i];
        s += (v.x + v.y) + (v.z + v.w);
        sq += v.x*v.x + v.y*v.y + v.z*v.z + v.w*v.w;
        __half h[4] = {__float2half(v.x), __float2half(v.y),
                       __float2half(v.z), __float2half(v.w)};
        *(uint2*)(xh + base + (size_t)i * 4) = *(uint2*)h;
    }
    __shared__ float sh1[8], sh2[8];
    int lane = threadIdx.x & 31, w = threadIdx.x >> 5;
    #pragma unroll
    for (int o = 16; o > 0; o >>= 1) {
        s += __shfl_xor_sync(0xffffffffu, s, o);
        sq += __shfl_xor_sync(0xffffffffu, sq, o);
    }
    if (lane == 0) { sh1[w] = s; sh2[w] = sq; }
    __syncthreads();
    if (threadIdx.x < 8) {
        s = sh1[threadIdx.x]; sq = sh2[threadIdx.x];
        #pragma unroll
        for (int o = 4; o > 0; o >>= 1) {
            s += __shfl_xor_sync(0xffu, s, o);
            sq += __shfl_xor_sync(0xffu, sq, o);
        }
        if (threadIdx.x == 0) {
            float inv_n = 1.f / (float)n;
            float m = s * inv_n;
            float var = sq * inv_n - m * m;
            mu[blockIdx.x] = m;
            rs[blockIdx.x] = rsqrtf(fmaxf(var, 0.f) + EPSV);
        }
    }
}

// stats over an fp16 plane
__global__ void gn_stats_h_kernel(const __half* __restrict__ x, int GC,
                                  float* __restrict__ mu, float* __restrict__ rs)
{
    const size_t n = (size_t)GC * TT;
    const uint4* x8 = (const uint4*)(x + (size_t)blockIdx.x * n);
    const int n8 = (int)(n >> 3);
    float s = 0.f, sq = 0.f;
    for (int i = threadIdx.x; i < n8; i += 256) {
        uint4 v = x8[i];
        const __half2* hh = (const __half2*)&v;
        #pragma unroll
        for (int j = 0; j < 4; j++) {
            float2 f = __half22float2(hh[j]);
            s += f.x + f.y;
            sq += f.x*f.x + f.y*f.y;
        }
    }
    __shared__ float sh1[8], sh2[8];
    int lane = threadIdx.x & 31, w = threadIdx.x >> 5;
    #pragma unroll
    for (int o = 16; o > 0; o >>= 1) {
        s += __shfl_xor_sync(0xffffffffu, s, o);
        sq += __shfl_xor_sync(0xffffffffu, sq, o);
    }
    if (lane == 0) { sh1[w] = s; sh2[w] = sq; }
    __syncthreads();
    if (threadIdx.x < 8) {
        s = sh1[threadIdx.x]; sq = sh2[threadIdx.x];
        #pragma unroll
        for (int o = 4; o > 0; o >>= 1) {
            s += __shfl_xor_sync(0xffu, s, o);
            sq += __shfl_xor_sync(0xffu, sq, o);
        }
        if (threadIdx.x == 0) {
            float inv_n = 1.f / (float)n;
            float m = s * inv_n;
            float var = sq * inv_n - m * m;
            mu[blockIdx.x] = m;
            rs[blockIdx.x] = rsqrtf(fmaxf(var, 0.f) + EPSV);
        }
    }
}

// ==================== attention: online-softmax ctx ====================
__global__ void ctx_kernel(const __half* __restrict__ kv, size_t strideB, int koff, int voff,
                           float* __restrict__ cpart,
                           float* __restrict__ cmax, float* __restrict__ csum)
{
    int bh = blockIdx.x;
    int slice = blockIdx.y;
    int b = bh / NH, h = bh % NH;
    __shared__ float ks[32][65], vs[32][65];
    __shared__ float mrow[32];
    int tid = threadIdx.x;
    const __half* kp = kv + (size_t)b*strideB + (size_t)(koff + h*32)*TT + slice*1024;
    const __half* vp = kv + (size_t)b*strideB + (size_t)(voff + h*32)*TT + slice*1024;
    int d = tid >> 3, e0 = (tid & 7) * 4;
    float c0 = 0.f, c1 = 0.f, c2 = 0.f, c3 = 0.f;
    float mold = -1e30f, ssum = 0.f;
    for (int tc = 0; tc < 1024; tc += 64) {
        __syncthreads();
        for (int i = tid; i < 32*64; i += 256) {
            int r = i >> 6, t = i & 63;
            ks[r][t] = __half2float(kp[(size_t)r*TT + tc + t]);
            vs[r][t] = __half2float(vp[(size_t)r*TT + tc + t]);
        }
        __syncthreads();
        float tmax = -1e30f;
        #pragma unroll 8
        for (int t = 0; t < 64; t++) tmax = fmaxf(tmax, ks[d][t]);
        float mnew = fmaxf(mold, tmax);
        float scale = expf(mold - mnew);
        c0 *= scale; c1 *= scale; c2 *= scale; c3 *= scale; ssum *= scale;
        if ((tid & 7) == 0) mrow[d] = mnew;
        mold = mnew;
        __syncthreads();
        for (int i = tid; i < 32*64; i += 256) {
            int r = i >> 6, t = i & 63;
            ks[r][t] = expf(ks[r][t] - mrow[r]);
        }
        __syncthreads();
        #pragma unroll 8
        for (int t = 0; t < 64; t++) {
            float kd = ks[d][t];
            ssum += kd;
            c0 += kd * vs[e0+0][t];
            c1 += kd * vs[e0+1][t];
            c2 += kd * vs[e0+2][t];
            c3 += kd * vs[e0+3][t];
        }
    }
    float* cp = cpart + (size_t)slice*65536 + (size_t)bh*1024 + d*32 + e0;
    cp[0] = c0; cp[1] = c1; cp[2] = c2; cp[3] = c3;
    if ((tid & 7) == 0) {
        cmax[slice*2048 + bh*32 + d] = mold;
        csum[slice*2048 + bh*32 + d] = ssum;
    }
}

__global__ void ctx_reduce_kernel(const float* __restrict__ cpart,
                                  const float* __restrict__ cmax,
                                  const float* __restrict__ csum,
                                  float* __restrict__ ctx)
{
    int i = blockIdx.x * 256 + threadIdx.x;   // 65536
    int bh = i >> 10, d = (i & 1023) >> 5;
    float M = -1e30f;
    #pragma unroll
    for (int sl = 0; sl < 8; sl++) M = fmaxf(M, cmax[sl*2048 + bh*32 + d]);
    float tot = 0.f, v = 0.f;
    #pragma unroll
    for (int sl = 0; sl < 8; sl++) {
        float w = expf(cmax[sl*2048 + bh*32 + d] - M);
        tot += csum[sl*2048 + bh*32 + d] * w;
        v   += cpart[(size_t)sl*65536 + i] * w;
    }
    ctx[i] = v / tot;
}

__global__ void attn_out_kernel(const __half* __restrict__ q, size_t strideB, int qoff,
                                const float* __restrict__ ctx,
                                __half* __restrict__ o, size_t oStrideB)
{
    int bh = blockIdx.x;
    int b = bh / NH, h = bh % NH;
    int t = blockIdx.y * 256 + threadIdx.x;
    __shared__ float cs[32][32];
    for (int i = threadIdx.x; i < 1024; i += 256)
        cs[i >> 5][i & 31] = ctx[(size_t)bh*1024 + i];
    __syncthreads();
    const __half* qp = q + (size_t)b*strideB + (size_t)(qoff + h*32)*TT + t;
    float p[32];
    float mx = -1e30f;
    #pragma unroll
    for (int d = 0; d < 32; d++) { p[d] = __half2float(qp[(size_t)d*TT]); mx = fmaxf(mx, p[d]); }
    float s = 0.f;
    #pragma unroll
    for (int d = 0; d < 32; d++) { p[d] = expf(p[d] - mx); s += p[d]; }
    float inv = 0.17677669529663687f / s;
    #pragma unroll
    for (int d = 0; d < 32; d++) p[d] *= inv;
    float accv[32];
    #pragma unroll
    for (int e = 0; e < 32; e++) accv[e] = 0.f;
    #pragma unroll
    for (int d = 0; d < 32; d++) {
        float pd = p[d];
        #pragma unroll
        for (int e4 = 0; e4 < 8; e4++) {
            float4 cv = *(const float4*)&cs[d][e4*4];
            accv[e4*4+0] += cv.x * pd;
            accv[e4*4+1] += cv.y * pd;
            accv[e4*4+2] += cv.z * pd;
            accv[e4*4+3] += cv.w * pd;
        }
    }
    __half* op = o + (size_t)b*oStrideB + (size_t)(h*32)*TT + t;
    #pragma unroll
    for (int e = 0; e < 32; e++) op[(size_t)e*TT] = __float2half(accv[e]);
}

// y = gn(v_fp16)*g + b + r ; writes fp32 y, fp16 yh, per-block (sum,sumsq) partials of y
__global__ void gn_add_kernel(const __half* __restrict__ v,
                              const float* __restrict__ gamma, const float* __restrict__ beta,
                              const float* __restrict__ mu, const float* __restrict__ rs,
                              const float* __restrict__ r, float* __restrict__ y,
                              __half* __restrict__ yh, float2* __restrict__ part)
{
    size_t i = ((size_t)blockIdx.x * 256 + threadIdx.x) * 4;
    int c = (int)((i / TT) % DIMC);
    int b = (int)(i / ((size_t)DIMC * TT));
    int grp = c >> 3;
    float rr = rs[b*32 + grp], m = mu[b*32 + grp];
    float sc = gamma[c] * rr;
    float sh = beta[c] - m * sc;
    uint2 hv = *(const uint2*)(v + i);
    float2 f0 = __half22float2(((const __half2*)&hv)[0]);
    float2 f1 = __half22float2(((const __half2*)&hv)[1]);
    float4 rv = *(const float4*)(r + i);
    float4 o;
    o.x = f0.x * sc + sh + rv.x;
    o.y = f0.y * sc + sh + rv.y;
    o.z = f1.x * sc + sh + rv.z;
    o.w = f1.y * sc + sh + rv.w;
    *(float4*)(y + i) = o;
    __half h[4] = {__float2half(o.x), __float2half(o.y), __float2half(o.z), __float2half(o.w)};
    *(uint2*)(yh + i) = *(uint2*)h;

    float s  = (o.x + o.y) + (o.z + o.w);
    float sq = o.x*o.x + o.y*o.y + o.z*o.z + o.w*o.w;
    __shared__ float sh1[8], sh2[8];
    int lane = threadIdx.x & 31, w = threadIdx.x >> 5;
    #pragma unroll
    for (int o2 = 16; o2 > 0; o2 >>= 1) {
        s  += __shfl_xor_sync(0xffffffffu, s,  o2);
        sq += __shfl_xor_sync(0xffffffffu, sq, o2);
    }
    if (lane == 0) { sh1[w] = s; sh2[w] = sq; }
    __syncthreads();
    if (threadIdx.x < 8) {
        s = sh1[threadIdx.x]; sq = sh2[threadIdx.x];
        #pragma unroll
        for (int o2 = 4; o2 > 0; o2 >>= 1) {
            s  += __shfl_xor_sync(0xffu, s,  o2);
            sq += __shfl_xor_sync(0xffu, sq, o2);
        }
        if (threadIdx.x == 0) part[blockIdx.x] = make_float2(s, sq);
    }
}

__global__ void gn_reduce_kernel(const float2* __restrict__ part,
                                 float* __restrict__ mu, float* __restrict__ rs)
{
    int g = blockIdx.x;
    int t = threadIdx.x;
    float2 p = part[g * 64 + t];
    float s = p.x, sq = p.y;
    #pragma unroll
    for (int o = 16; o > 0; o >>= 1) {
        s  += __shfl_xor_sync(0xffffffffu, s,  o);
        sq += __shfl_xor_sync(0xffffffffu, sq, o);
    }
    __shared__ float a[2], bsh[2];
    if ((t & 31) == 0) { a[t >> 5] = s; bsh[t >> 5] = sq; }
    __syncthreads();
    if (t == 0) {
        s = a[0] + a[1]; sq = bsh[0] + bsh[1];
        const float inv_n = 1.f / 65536.f;
        float m = s * inv_n;
        float var = sq * inv_n - m * m;
        mu[g] = m;
        rs[g] = rsqrtf(fmaxf(var, 0.f) + EPSV);
    }
}

// ==================== host orchestration ====================
extern "C" void kernel_launch(void* const* d_in, const int* in_sizes, int n_in,
                              void* d_out, int out_size)
{
    const float* x     = (const float*)d_in[0];
    const float* c     = (const float*)d_in[1];
    const float* W_qkv = (const float*)d_in[2];
    const float* W_so  = (const float*)d_in[3];
    const float* b_so  = (const float*)d_in[4];
    const float* sa_g  = (const float*)d_in[5];
    const float* sa_b  = (const float*)d_in[6];
    const float* W_cq  = (const float*)d_in[7];
    const float* W_ckv = (const float*)d_in[8];
    const float* W_co  = (const float*)d_in[9];
    const float* b_co  = (const float*)d_in[10];
    const float* ca_g  = (const float*)d_in[11];
    const float* ca_b  = (const float*)d_in[12];
    const float* W_m1  = (const float*)d_in[13];
    const float* b_m1  = (const float*)d_in[14];
    const float* W_m2  = (const float*)d_in[15];
    const float* b_m2  = (const float*)d_in[16];
    const float* nm_g  = (const float*)d_in[17];
    const float* nm_b  = (const float*)d_in[18];
    const float* nm1_g = (const float*)d_in[19];
    const float* nm1_b = (const float*)d_in[20];
    const float* nm2_g = (const float*)d_in[21];
    const float* nm2_b = (const float*)d_in[22];
    const float* nm3_g = (const float*)d_in[23];
    const float* nm3_b = (const float*)d_in[24];
    float* out = (float*)d_out;

    float *xb, *beff, *mu, *rs, *ctx, *ctxp, *cmax, *csum;
    float2* part;
    __half *w16, *h1, *h2, *bigh;
    cudaGetSymbolAddress((void**)&xb,   g_x);
    cudaGetSymbolAddress((void**)&beff, g_beff);
    cudaGetSymbolAddress((void**)&mu,   g_mu);
    cudaGetSymbolAddress((void**)&rs,   g_rs);
    cudaGetSymbolAddress((void**)&ctx,  g_ctx);
    cudaGetSymbolAddress((void**)&ctxp, g_ctxp);
    cudaGetSymbolAddress((void**)&cmax, g_cmax);
    cudaGetSymbolAddress((void**)&csum, g_csum);
    cudaGetSymbolAddress((void**)&part, g_part);
    cudaGetSymbolAddress((void**)&w16,  g_w16);
    cudaGetSymbolAddress((void**)&h1,   g_h1);
    cudaGetSymbolAddress((void**)&h2,   g_h2);
    cudaGetSymbolAddress((void**)&bigh, g_bigh);

    static bool attr_set = false;
    if (!attr_set) {
        cudaFuncSetAttribute(mm_kernel, cudaFuncAttributeMaxDynamicSharedMemorySize, SMEM_MM);
        attr_set = true;
    }

    const size_t XT = (size_t)DIMC * TT;

    // ================= Phase 1: self linear attention =================
    gn_stats_conv_kernel<<<BQ*32, 256>>>(x, h1, 8, mu, rs);
    wprep_kernel<<<dim3(24, BQ), 256>>>(W_qkv, nm_g, nm_b, mu, rs, nullptr, w16, beff, 768, 256);
    mm_kernel<<<dim3(6, 64, BQ), 256, SMEM_MM>>>(w16, (size_t)768*256, beff, 1,
                                                 h1, XT, nullptr, bigh, (size_t)768*TT,
                                                 nullptr, 0, 768, 256, 0);
    ctx_kernel<<<dim3(64, 8), 256>>>(bigh, (size_t)768*TT, 256, 512, ctxp, cmax, csum);
    ctx_reduce_kernel<<<256, 256>>>(ctxp, cmax, csum, ctx);
    attn_out_kernel<<<dim3(64, 32), 256>>>(bigh, (size_t)768*TT, 0, ctx, h1, XT);
    wprep_kernel<<<dim3(8, 1), 256>>>(W_so, nullptr, nullptr, nullptr, nullptr, b_so,
                                      w16, beff, 256, 256);
    mm_kernel<<<dim3(2, 64, BQ), 256, SMEM_MM>>>(w16, 0, beff, 0,
                                                 h1, XT, nullptr, bigh, XT,
                                                 nullptr, 0, 256, 256, 0);
    gn_stats_h_kernel<<<BQ*32, 256>>>(bigh, 8, mu, rs);
    gn_add_kernel<<<16384, 256>>>(bigh, sa_g, sa_b, mu, rs, x, xb, h1, part);
    gn_reduce_kernel<<<256, 64>>>(part, mu, rs);

    // ================= Phase 2: cross linear attention =================
    wprep_kernel<<<dim3(8, BQ), 256>>>(W_cq, nm1_g, nm1_b, mu, rs, nullptr, w16, beff, 256, 256);
    mm_kernel<<<dim3(2, 64, BQ), 256, SMEM_MM>>>(w16, (size_t)256*256, beff, 1,
                                                 h1, XT, nullptr, h2, XT,
                                                 nullptr, 0, 256, 256, 0);
    gn_stats_conv_kernel<<<BQ*32, 256>>>(c, h1, 16, mu, rs);
    wprep_kernel<<<dim3(16, BQ), 256>>>(W_ckv, nm3_g, nm3_b, mu, rs, nullptr, w16, beff, 512, 512);
    mm_kernel<<<dim3(4, 64, BQ), 256, SMEM_MM>>>(w16, (size_t)512*512, beff, 1,
                                                 h1, (size_t)512*TT, nullptr, bigh, (size_t)512*TT,
                                                 nullptr, 0, 512, 512, 0);
    ctx_kernel<<<dim3(64, 8), 256>>>(bigh, (size_t)512*TT, 0, 256, ctxp, cmax, csum);
    ctx_reduce_kernel<<<256, 256>>>(ctxp, cmax, csum, ctx);
    attn_out_kernel<<<dim3(64, 32), 256>>>(h2, XT, 0, ctx, h1, XT);
    wprep_kernel<<<dim3(8, 1), 256>>>(W_co, nullptr, nullptr, nullptr, nullptr, b_co,
                                      w16, beff, 256, 256);
    mm_kernel<<<dim3(2, 64, BQ), 256, SMEM_MM>>>(w16, 0, beff, 0,
                                                 h1, XT, nullptr, bigh, XT,
                                                 nullptr, 0, 256, 256, 0);
    gn_stats_h_kernel<<<BQ*32, 256>>>(bigh, 8, mu, rs);
    gn_add_kernel<<<16384, 256>>>(bigh, ca_g, ca_b, mu, rs, xb, xb, h1, part);
    gn_reduce_kernel<<<256, 64>>>(part, mu, rs);

    // ================= Phase 3: SiLU MLP =================
    wprep_kernel<<<dim3(20, BQ), 256>>>(W_m1, nm2_g, nm2_b, mu, rs, b_m1, w16, beff, 640, 256);
    mm_kernel<<<dim3(5, 64, BQ), 256, SMEM_MM>>>(w16, (size_t)640*256, beff, 1,
                                                 h1, XT, nullptr, h2, (size_t)640*TT,
                                                 nullptr, 0, 640, 256, 1 /*silu, fp16 out*/);
    wprep_kernel<<<dim3(8, 1), 256>>>(W_m2, nullptr, nullptr, nullptr, nullptr, b_m2,
                                      w16, beff, 256, 640);
    mm_kernel<<<dim3(2, 64, BQ), 256, SMEM_MM>>>(w16, 0, beff, 0,
                                                 h2, (size_t)640*TT, out, nullptr, XT,
                                                 xb, XT, 256, 640, 2 /*residual*/);
}

// round 14
// speedup vs baseline: 3.0649x; 1.0310x over previous
#include <cuda_runtime.h>
#include <cuda_fp16.h>
#include <cstdint>

#define BQ 8
#define DIMC 256
#define TT 8192
#define NH 8
#define EPSV 1e-5f
#define CSL 16          // ctx slices
#define CT  512         // t per slice

// fp16 stage: A[128 rows x 32k, pad 40h]=10240B, B[32k x 128n, pad 136h]=8704B
#define A_BYTES   10240
#define STG_BYTES 18944
#define NSTG      3
#define SMEM_MM   (NSTG * STG_BYTES)

// ---------------- scratch (device globals) ----------------
__device__ float g_x   [(size_t)BQ * DIMC * TT];     // xb residual (fp32)
__device__ float g_beff[BQ * 1024];
__device__ float g_mu  [BQ * 32];
__device__ float g_rs  [BQ * 32];
__device__ float g_ctx [BQ * NH * 32 * 32];
__device__ float g_ctxp[(size_t)CSL * BQ * NH * 32 * 32];
__device__ float g_cmax[CSL * BQ * NH * 32];
__device__ float g_csum[CSL * BQ * NH * 32];
__device__ float2 g_part[16384];
// fp16 planes
__device__ __align__(256) __half g_w16 [(size_t)BQ * 512 * 512];     // folded weights
__device__ __align__(256) __half g_h1  [(size_t)BQ * 512 * TT];      // activation plane (reused)
__device__ __align__(256) __half g_h2  [(size_t)BQ * 640 * TT];      // cq out / m1 out
__device__ __align__(256) __half g_bigh[(size_t)BQ * 768 * TT];      // qkv/ckv out; later so plane

// ==================== PTX helpers (plain sm_80+ only) ====================
__device__ __forceinline__ unsigned s2u(const void* p) {
    unsigned a;
    asm("{ .reg .u64 t; cvta.to.shared.u64 t, %1; cvt.u32.u64 %0, t; }" : "=r"(a) : "l"(p));
    return a;
}
#define LDSM4(r, addr) \
    asm volatile("ldmatrix.sync.aligned.m8n8.x4.shared.b16 {%0,%1,%2,%3}, [%4];" \
        : "=r"((r)[0]), "=r"((r)[1]), "=r"((r)[2]), "=r"((r)[3]) : "r"(addr))
#define LDSM4T(r, addr) \
    asm volatile("ldmatrix.sync.aligned.m8n8.x4.trans.shared.b16 {%0,%1,%2,%3}, [%4];" \
        : "=r"((r)[0]), "=r"((r)[1]), "=r"((r)[2]), "=r"((r)[3]) : "r"(addr))
__device__ __forceinline__ void mma_f16(float* c, const unsigned* a, const unsigned* b) {
    asm volatile("mma.sync.aligned.m16n8k16.row.col.f32.f16.f16.f32 "
        "{%0,%1,%2,%3}, {%4,%5,%6,%7}, {%8,%9}, {%0,%1,%2,%3};"
        : "+f"(c[0]), "+f"(c[1]), "+f"(c[2]), "+f"(c[3])
        : "r"(a[0]), "r"(a[1]), "r"(a[2]), "r"(a[3]), "r"(b[0]), "r"(b[1]));
}
__device__ __forceinline__ void cp16(unsigned saddr, const void* gaddr) {
    asm volatile("cp.async.cg.shared.global [%0], [%1], 16;" :: "r"(saddr), "l"(gaddr));
}
__device__ __forceinline__ void cp_commit() {
    asm volatile("cp.async.commit_group;");
}
template <int N>
__device__ __forceinline__ void cp_wait() {
    asm volatile("cp.async.wait_group %0;" :: "n"(N));
}

// ==================== tensor-core GEMM (pure fp16 operands, fp32 accum) ====================
__global__ __launch_bounds__(256, 2)
void mm_kernel(const __half* __restrict__ A16, size_t aStrB,
               const float* __restrict__ bias, int perB,
               const __half* __restrict__ B16, size_t bStrB,
               float* __restrict__ Y, __half* __restrict__ Yh, size_t yStrB,
               const float* __restrict__ R, size_t rStrB,
               int M, int K, int ep)
{
    extern __shared__ char smem[];
    const unsigned sb = s2u(smem);
    const int tid = threadIdx.x, lane = tid & 31, wid = tid >> 5;
    const int wr = wid >> 2, wc = wid & 3;
    const int mt = blockIdx.x, nt = blockIdx.y, b = blockIdx.z;
    const int m0 = mt * 128, n0 = nt * 128;
    const __half* Ab = A16 + (size_t)b * aStrB;
    const __half* Bb = B16 + (size_t)b * bStrB;

    float acc[4][4][4];
    #pragma unroll
    for (int i = 0; i < 4; i++)
        #pragma unroll
        for (int j = 0; j < 4; j++)
            #pragma unroll
            for (int r = 0; r < 4; r++) acc[i][j][r] = 0.f;

    const unsigned aoff = (lane & 15) * 80  + (lane >> 4) * 16;
    const unsigned boff = (lane & 15) * 272 + (lane >> 4) * 16;
    const int nk = K >> 5;

    auto cpChunk = [&](int kc, int st) {
        unsigned base = sb + st * STG_BYTES;
        #pragma unroll
        for (int u = 0; u < 2; u++) {
            int f = tid + u * 256;
            int row = f >> 2, c16 = f & 3;
            cp16(base + row * 80 + c16 * 16,
                 Ab + (size_t)(m0 + row) * K + kc * 32 + c16 * 8);
        }
        #pragma unroll
        for (int u = 0; u < 2; u++) {
            int f = tid + u * 256;
            int r = f >> 4, c16 = f & 15;
            cp16(base + A_BYTES + r * 272 + c16 * 16,
                 Bb + (size_t)(kc * 32 + r) * TT + n0 + c16 * 8);
        }
        cp_commit();
    };

    auto compute = [&](int st) {
        unsigned stb = sb + st * STG_BYTES;
        #pragma unroll
        for (int ks = 0; ks < 2; ks++) {
            unsigned bh[2][4];
            #pragma unroll
            for (int np = 0; np < 2; np++)
                LDSM4T(bh[np], stb + A_BYTES + ks * 4352 + wc * 64 + np * 32 + boff);
            #pragma unroll
            for (int mf = 0; mf < 4; mf++) {
                unsigned ah[4];
                LDSM4(ah, stb + wr * 5120 + mf * 1280 + ks * 32 + aoff);
                #pragma unroll
                for (int nf = 0; nf < 4; nf++)
                    mma_f16(acc[mf][nf], ah, &bh[nf >> 1][(nf & 1) * 2]);
            }
        }
    };

    const int pre = nk < NSTG ? nk : NSTG;
    for (int i = 0; i < pre; i++) cpChunk(i, i);

    for (int i = 0; i < nk; i++) {
        if (i + 2 < nk)      cp_wait<2>();
        else if (i + 1 < nk) cp_wait<1>();
        else                 cp_wait<0>();
        __syncthreads();
        compute(i % NSTG);
        __syncthreads();
        if (i + NSTG < nk) cpChunk(i + NSTG, i % NSTG);
    }

    const float* biasB = bias + (perB ? (size_t)b * M : 0);
    #pragma unroll
    for (int mf = 0; mf < 4; mf++) {
        int gm = m0 + wr * 64 + mf * 16 + (lane >> 2);
        float bv0 = biasB[gm], bv1 = biasB[gm + 8];
        #pragma unroll
        for (int nf = 0; nf < 4; nf++) {
            int gn = n0 + wc * 32 + nf * 8 + (lane & 3) * 2;
            float* a4 = acc[mf][nf];
            float2 v0 = make_float2(a4[0] + bv0, a4[1] + bv0);
            float2 v1 = make_float2(a4[2] + bv1, a4[3] + bv1);
            if (ep == 1) {
                v0.x /= (1.f + expf(-v0.x)); v0.y /= (1.f + expf(-v0.y));
                v1.x /= (1.f + expf(-v1.x)); v1.y /= (1.f + expf(-v1.y));
            } else if (ep == 2) {
                const float* Rb = R + (size_t)b * rStrB;
                float2 r0 = *(const float2*)&Rb[(size_t)gm * TT + gn];
                float2 r1 = *(const float2*)&Rb[(size_t)(gm + 8) * TT + gn];
                v0.x += r0.x; v0.y += r0.y; v1.x += r1.x; v1.y += r1.y;
            }
            if (Yh) {
                __half* Yb = Yh + (size_t)b * yStrB;
                *(__half2*)&Yb[(size_t)gm * TT + gn] =
                    __halves2half2(__float2half(v0.x), __float2half(v0.y));
                *(__half2*)&Yb[(size_t)(gm + 8) * TT + gn] =
                    __halves2half2(__float2half(v1.x), __float2half(v1.y));
            } else {
                float* Yb = Y + (size_t)b * yStrB;
                *(float2*)&Yb[(size_t)gm * TT + gn] = v0;
                *(float2*)&Yb[(size_t)(gm + 8) * TT + gn] = v1;
            }
        }
    }
}

// ==================== wprep: fused affine + weight fold + beff ====================
__global__ void wprep_kernel(const float* __restrict__ W,
                             const float* __restrict__ g, const float* __restrict__ be,
                             const float* __restrict__ mu, const float* __restrict__ rs,
                             const float* __restrict__ bias,
                             __half* __restrict__ w16, float* __restrict__ beff,
                             int M, int K)
{
    __shared__ float a_s[640], bb_s[640];
    const int b = blockIdx.y;
    const int GC = K >> 5;
    for (int c = threadIdx.x; c < K; c += 256) {
        if (g) {
            int grp = c / GC;
            float r = rs[b*32 + grp], m = mu[b*32 + grp];
            float av = g[c] * r;
            a_s[c] = av;
            bb_s[c] = be[c] - m * av;
        } else { a_s[c] = 1.f; bb_s[c] = 0.f; }
    }
    __syncthreads();
    const int m = blockIdx.x * 32 + (threadIdx.x >> 3);
    const int l8 = threadIdx.x & 7;
    const float* Wr = W + (size_t)m * K;
    __half* dst = w16 + (size_t)b * M * K + (size_t)m * K;
    float dot = 0.f;
    for (int k0 = l8 * 4; k0 < K; k0 += 32) {
        float4 w = *(const float4*)(Wr + k0);
        dot += w.x*bb_s[k0] + w.y*bb_s[k0+1] + w.z*bb_s[k0+2] + w.w*bb_s[k0+3];
        __half h[4] = {__float2half(w.x * a_s[k0]),   __float2half(w.y * a_s[k0+1]),
                       __float2half(w.z * a_s[k0+2]), __float2half(w.w * a_s[k0+3])};
        *(uint2*)(dst + k0) = *(uint2*)h;
    }
    dot += __shfl_down_sync(0xffffffffu, dot, 4, 8);
    dot += __shfl_down_sync(0xffffffffu, dot, 2, 8);
    dot += __shfl_down_sync(0xffffffffu, dot, 1, 8);
    if (l8 == 0)
        beff[(size_t)b * M + m] = dot + (bias ? bias[m] : 0.f);
}

// ==================== group-norm stats ====================
__global__ void gn_stats_conv_kernel(const float* __restrict__ x, __half* __restrict__ xh,
                                     int GC, float* __restrict__ mu, float* __restrict__ rs)
{
    const size_t n = (size_t)GC * TT;
    const size_t base = (size_t)blockIdx.x * n;
    const float4* x4 = (const float4*)(x + base);
    const int n4 = (int)(n >> 2);
    float s = 0.f, sq = 0.f;
    for (int i = threadIdx.x; i < n4; i += 256) {
        float4 v = x4[i];
        s += (v.x + v.y) + (v.z + v.w);
        sq += v.x*v.x + v.y*v.y + v.z*v.z + v.w*v.w;
        __half h[4] = {__float2half(v.x), __float2half(v.y),
                       __float2half(v.z), __float2half(v.w)};
        *(uint2*)(xh + base + (size_t)i * 4) = *(uint2*)h;
    }
    __shared__ float sh1[8], sh2[8];
    int lane = threadIdx.x & 31, w = threadIdx.x >> 5;
    #pragma unroll
    for (int o = 16; o > 0; o >>= 1) {
        s += __shfl_xor_sync(0xffffffffu, s, o);
        sq += __shfl_xor_sync(0xffffffffu, sq, o);
    }
    if (lane == 0) { sh1[w] = s; sh2[w] = sq; }
    __syncthreads();
    if (threadIdx.x < 8) {
        s = sh1[threadIdx.x]; sq = sh2[threadIdx.x];
        #pragma unroll
        for (int o = 4; o > 0; o >>= 1) {
            s += __shfl_xor_sync(0xffu, s, o);
            sq += __shfl_xor_sync(0xffu, sq, o);
        }
        if (threadIdx.x == 0) {
            float inv_n = 1.f / (float)n;
            float m = s * inv_n;
            float var = sq * inv_n - m * m;
            mu[blockIdx.x] = m;
            rs[blockIdx.x] = rsqrtf(fmaxf(var, 0.f) + EPSV);
        }
    }
}

__global__ void gn_stats_h_kernel(const __half* __restrict__ x, int GC,
                                  float* __restrict__ mu, float* __restrict__ rs)
{
    const size_t n = (size_t)GC * TT;
    const uint4* x8 = (const uint4*)(x + (size_t)blockIdx.x * n);
    const int n8 = (int)(n >> 3);
    float s = 0.f, sq = 0.f;
    for (int i = threadIdx.x; i < n8; i += 256) {
        uint4 v = x8[i];
        const __half2* hh = (const __half2*)&v;
        #pragma unroll
        for (int j = 0; j < 4; j++) {
            float2 f = __half22float2(hh[j]);
            s += f.x + f.y;
            sq += f.x*f.x + f.y*f.y;
        }
    }
    __shared__ float sh1[8], sh2[8];
    int lane = threadIdx.x & 31, w = threadIdx.x >> 5;
    #pragma unroll
    for (int o = 16; o > 0; o >>= 1) {
        s += __shfl_xor_sync(0xffffffffu, s, o);
        sq += __shfl_xor_sync(0xffffffffu, sq, o);
    }
    if (lane == 0) { sh1[w] = s; sh2[w] = sq; }
    __syncthreads();
    if (threadIdx.x < 8) {
        s = sh1[threadIdx.x]; sq = sh2[threadIdx.x];
        #pragma unroll
        for (int o = 4; o > 0; o >>= 1) {
            s += __shfl_xor_sync(0xffu, s, o);
            sq += __shfl_xor_sync(0xffu, sq, o);
        }
        if (threadIdx.x == 0) {
            float inv_n = 1.f / (float)n;
            float m = s * inv_n;
            float var = sq * inv_n - m * m;
            mu[blockIdx.x] = m;
            rs[blockIdx.x] = rsqrtf(fmaxf(var, 0.f) + EPSV);
        }
    }
}

// ==================== attention: register-staged online-softmax ctx ====================
// grid (64, CSL), 256 threads. Thread = (row d = tid>>3, segment j = tid&7).
__global__ void ctx_kernel(const __half* __restrict__ kv, size_t strideB, int koff, int voff,
                           float* __restrict__ cpart,
                           float* __restrict__ cmax, float* __restrict__ csum)
{
    int bh = blockIdx.x;
    int slice = blockIdx.y;
    int b = bh / NH, h = bh % NH;
    __shared__ __half ksh[32][72];
    __shared__ __half vsh[32][72];
    const int tid = threadIdx.x;
    const int d = tid >> 3, j = tid & 7;
    const int e0 = j * 4;
    const __half* kp = kv + (size_t)b*strideB + (size_t)(koff + h*32)*TT + slice*CT + (size_t)d*TT + j*8;
    const __half* vp = kv + (size_t)b*strideB + (size_t)(voff + h*32)*TT + slice*CT + (size_t)d*TT + j*8;
    float c0 = 0.f, c1 = 0.f, c2 = 0.f, c3 = 0.f;
    float mold = -1e30f, ssum = 0.f;

    for (int tc = 0; tc < CT; tc += 64) {
        uint4 kr = *(const uint4*)(kp + tc);
        uint4 vr = *(const uint4*)(vp + tc);
        float kf[8];
        float lmax = -1e30f;
        const __half2* kh = (const __half2*)&kr;
        #pragma unroll
        for (int q = 0; q < 4; q++) {
            float2 f = __half22float2(kh[q]);
            kf[2*q] = f.x; kf[2*q+1] = f.y;
            lmax = fmaxf(lmax, fmaxf(f.x, f.y));
        }
        #pragma unroll
        for (int o = 4; o > 0; o >>= 1)
            lmax = fmaxf(lmax, __shfl_xor_sync(0xffffffffu, lmax, o, 8));
        float mnew = fmaxf(mold, lmax);
        float scale = expf(mold - mnew);
        c0 *= scale; c1 *= scale; c2 *= scale; c3 *= scale; ssum *= scale;
        mold = mnew;
        __half eh[8];
        #pragma unroll
        for (int q = 0; q < 8; q++) eh[q] = __float2half(expf(kf[q] - mnew));
        __syncthreads();                       // prev dot done before overwrite
        *(uint4*)&ksh[d][j*8] = *(uint4*)eh;
        *(uint4*)&vsh[d][j*8] = vr;
        __syncthreads();
        #pragma unroll 4
        for (int t = 0; t < 64; t += 2) {
            float2 kd2 = __half22float2(*(const __half2*)&ksh[d][t]);
            float2 w0 = __half22float2(*(const __half2*)&vsh[e0+0][t]);
            float2 w1 = __half22float2(*(const __half2*)&vsh[e0+1][t]);
            float2 w2 = __half22float2(*(const __half2*)&vsh[e0+2][t]);
            float2 w3 = __half22float2(*(const __half2*)&vsh[e0+3][t]);
            ssum += kd2.x + kd2.y;
            c0 += kd2.x * w0.x + kd2.y * w0.y;
            c1 += kd2.x * w1.x + kd2.y * w1.y;
            c2 += kd2.x * w2.x + kd2.y * w2.y;
            c3 += kd2.x * w3.x + kd2.y * w3.y;
        }
    }
    float* cp = cpart + (size_t)slice*65536 + (size_t)bh*1024 + d*32 + e0;
    cp[0] = c0; cp[1] = c1; cp[2] = c2; cp[3] = c3;
    if (j == 0) {
        cmax[slice*2048 + bh*32 + d] = mold;
        csum[slice*2048 + bh*32 + d] = ssum;
    }
}

__global__ void ctx_reduce_kernel(const float* __restrict__ cpart,
                                  const float* __restrict__ cmax,
                                  const float* __restrict__ csum,
                                  float* __restrict__ ctx)
{
    int i = blockIdx.x * 256 + threadIdx.x;   // 65536
    int bh = i >> 10, d = (i & 1023) >> 5;
    float M = -1e30f;
    #pragma unroll
    for (int sl = 0; sl < CSL; sl++) M = fmaxf(M, cmax[sl*2048 + bh*32 + d]);
    float tot = 0.f, v = 0.f;
    #pragma unroll
    for (int sl = 0; sl < CSL; sl++) {
        float w = expf(cmax[sl*2048 + bh*32 + d] - M);
        tot += csum[sl*2048 + bh*32 + d] * w;
        v   += cpart[(size_t)sl*65536 + i] * w;
    }
    ctx[i] = v / tot;
}

__global__ void attn_out_kernel(const __half* __restrict__ q, size_t strideB, int qoff,
                                const float* __restrict__ ctx,
                                __half* __restrict__ o, size_t oStrideB)
{
    int bh = blockIdx.x;
    int b = bh / NH, h = bh % NH;
    int t = blockIdx.y * 256 + threadIdx.x;
    __shared__ float cs[32][32];
    for (int i = threadIdx.x; i < 1024; i += 256)
        cs[i >> 5][i & 31] = ctx[(size_t)bh*1024 + i];
    __syncthreads();
    const __half* qp = q + (size_t)b*strideB + (size_t)(qoff + h*32)*TT + t;
    float p[32];
    float mx = -1e30f;
    #pragma unroll
    for (int d = 0; d < 32; d++) { p[d] = __half2float(qp[(size_t)d*TT]); mx = fmaxf(mx, p[d]); }
    float s = 0.f;
    #pragma unroll
    for (int d = 0; d < 32; d++) { p[d] = expf(p[d] - mx); s += p[d]; }
    float inv = 0.17677669529663687f / s;
    #pragma unroll
    for (int d = 0; d < 32; d++) p[d] *= inv;
    float accv[32];
    #pragma unroll
    for (int e = 0; e < 32; e++) accv[e] = 0.f;
    #pragma unroll
    for (int d = 0; d < 32; d++) {
        float pd = p[d];
        #pragma unroll
        for (int e4 = 0; e4 < 8; e4++) {
            float4 cv = *(const float4*)&cs[d][e4*4];
            accv[e4*4+0] += cv.x * pd;
            accv[e4*4+1] += cv.y * pd;
            accv[e4*4+2] += cv.z * pd;
            accv[e4*4+3] += cv.w * pd;
        }
    }
    __half* op = o + (size_t)b*oStrideB + (size_t)(h*32)*TT + t;
    #pragma unroll
    for (int e = 0; e < 32; e++) op[(size_t)e*TT] = __float2half(accv[e]);
}

// y = gn(v_fp16)*g + b + r ; writes fp32 y, fp16 yh, per-block (sum,sumsq) partials of y
__global__ void gn_add_kernel(const __half* __restrict__ v,
                              const float* __restrict__ gamma, const float* __restrict__ beta,
                              const float* __restrict__ mu, const float* __restrict__ rs,
                              const float* __restrict__ r, float* __restrict__ y,
                              __half* __restrict__ yh, float2* __restrict__ part)
{
    size_t i = ((size_t)blockIdx.x * 256 + threadIdx.x) * 4;
    int c = (int)((i / TT) % DIMC);
    int b = (int)(i / ((size_t)DIMC * TT));
    int grp = c >> 3;
    float rr = rs[b*32 + grp], m = mu[b*32 + grp];
    float sc = gamma[c] * rr;
    float sh = beta[c] - m * sc;
    uint2 hv = *(const uint2*)(v + i);
    float2 f0 = __half22float2(((const __half2*)&hv)[0]);
    float2 f1 = __half22float2(((const __half2*)&hv)[1]);
    float4 rv = *(const float4*)(r + i);
    float4 o;
    o.x = f0.x * sc + sh + rv.x;
    o.y = f0.y * sc + sh + rv.y;
    o.z = f1.x * sc + sh + rv.z;
    o.w = f1.y * sc + sh + rv.w;
    *(float4*)(y + i) = o;
    __half h[4] = {__float2half(o.x), __float2half(o.y), __float2half(o.z), __float2half(o.w)};
    *(uint2*)(yh + i) = *(uint2*)h;

    float s  = (o.x + o.y) + (o.z + o.w);
    float sq = o.x*o.x + o.y*o.y + o.z*o.z + o.w*o.w;
    __shared__ float sh1[8], sh2[8];
    int lane = threadIdx.x & 31, w = threadIdx.x >> 5;
    #pragma unroll
    for (int o2 = 16; o2 > 0; o2 >>= 1) {
        s  += __shfl_xor_sync(0xffffffffu, s,  o2);
        sq += __shfl_xor_sync(0xffffffffu, sq, o2);
    }
    if (lane == 0) { sh1[w] = s; sh2[w] = sq; }
    __syncthreads();
    if (threadIdx.x < 8) {
        s = sh1[threadIdx.x]; sq = sh2[threadIdx.x];
        #pragma unroll
        for (int o2 = 4; o2 > 0; o2 >>= 1) {
            s  += __shfl_xor_sync(0xffu, s,  o2);
            sq += __shfl_xor_sync(0xffu, sq, o2);
        }
        if (threadIdx.x == 0) part[blockIdx.x] = make_float2(s, sq);
    }
}

__global__ void gn_reduce_kernel(const float2* __restrict__ part,
                                 float* __restrict__ mu, float* __restrict__ rs)
{
    int g = blockIdx.x;
    int t = threadIdx.x;
    float2 p = part[g * 64 + t];
    float s = p.x, sq = p.y;
    #pragma unroll
    for (int o = 16; o > 0; o >>= 1) {
        s  += __shfl_xor_sync(0xffffffffu, s,  o);
        sq += __shfl_xor_sync(0xffffffffu, sq, o);
    }
    __shared__ float a[2], bsh[2];
    if ((t & 31) == 0) { a[t >> 5] = s; bsh[t >> 5] = sq; }
    __syncthreads();
    if (t == 0) {
        s = a[0] + a[1]; sq = bsh[0] + bsh[1];
        const float inv_n = 1.f / 65536.f;
        float m = s * inv_n;
        float var = sq * inv_n - m * m;
        mu[g] = m;
        rs[g] = rsqrtf(fmaxf(var, 0.f) + EPSV);
    }
}

// ==================== host orchestration ====================
extern "C" void kernel_launch(void* const* d_in, const int* in_sizes, int n_in,
                              void* d_out, int out_size)
{
    const float* x     = (const float*)d_in[0];
    const float* c     = (const float*)d_in[1];
    const float* W_qkv = (const float*)d_in[2];
    const float* W_so  = (const float*)d_in[3];
    const float* b_so  = (const float*)d_in[4];
    const float* sa_g  = (const float*)d_in[5];
    const float* sa_b  = (const float*)d_in[6];
    const float* W_cq  = (const float*)d_in[7];
    const float* W_ckv = (const float*)d_in[8];
    const float* W_co  = (const float*)d_in[9];
    const float* b_co  = (const float*)d_in[10];
    const float* ca_g  = (const float*)d_in[11];
    const float* ca_b  = (const float*)d_in[12];
    const float* W_m1  = (const float*)d_in[13];
    const float* b_m1  = (const float*)d_in[14];
    const float* W_m2  = (const float*)d_in[15];
    const float* b_m2  = (const float*)d_in[16];
    const float* nm_g  = (const float*)d_in[17];
    const float* nm_b  = (const float*)d_in[18];
    const float* nm1_g = (const float*)d_in[19];
    const float* nm1_b = (const float*)d_in[20];
    const float* nm2_g = (const float*)d_in[21];
    const float* nm2_b = (const float*)d_in[22];
    const float* nm3_g = (const float*)d_in[23];
    const float* nm3_b = (const float*)d_in[24];
    float* out = (float*)d_out;

    float *xb, *beff, *mu, *rs, *ctx, *ctxp, *cmax, *csum;
    float2* part;
    __half *w16, *h1, *h2, *bigh;
    cudaGetSymbolAddress((void**)&xb,   g_x);
    cudaGetSymbolAddress((void**)&beff, g_beff);
    cudaGetSymbolAddress((void**)&mu,   g_mu);
    cudaGetSymbolAddress((void**)&rs,   g_rs);
    cudaGetSymbolAddress((void**)&ctx,  g_ctx);
    cudaGetSymbolAddress((void**)&ctxp, g_ctxp);
    cudaGetSymbolAddress((void**)&cmax, g_cmax);
    cudaGetSymbolAddress((void**)&csum, g_csum);
    cudaGetSymbolAddress((void**)&part, g_part);
    cudaGetSymbolAddress((void**)&w16,  g_w16);
    cudaGetSymbolAddress((void**)&h1,   g_h1);
    cudaGetSymbolAddress((void**)&h2,   g_h2);
    cudaGetSymbolAddress((void**)&bigh, g_bigh);

    static bool attr_set = false;
    if (!attr_set) {
        cudaFuncSetAttribute(mm_kernel, cudaFuncAttributeMaxDynamicSharedMemorySize, SMEM_MM);
        attr_set = true;
    }

    const size_t XT = (size_t)DIMC * TT;

    // ================= Phase 1: self linear attention =================
    gn_stats_conv_kernel<<<BQ*32, 256>>>(x, h1, 8, mu, rs);
    wprep_kernel<<<dim3(24, BQ), 256>>>(W_qkv, nm_g, nm_b, mu, rs, nullptr, w16, beff, 768, 256);
    mm_kernel<<<dim3(6, 64, BQ), 256, SMEM_MM>>>(w16, (size_t)768*256, beff, 1,
                                                 h1, XT, nullptr, bigh, (size_t)768*TT,
                                                 nullptr, 0, 768, 256, 0);
    ctx_kernel<<<dim3(64, CSL), 256>>>(bigh, (size_t)768*TT, 256, 512, ctxp, cmax, csum);
    ctx_reduce_kernel<<<256, 256>>>(ctxp, cmax, csum, ctx);
    attn_out_kernel<<<dim3(64, 32), 256>>>(bigh, (size_t)768*TT, 0, ctx, h1, XT);
    wprep_kernel<<<dim3(8, 1), 256>>>(W_so, nullptr, nullptr, nullptr, nullptr, b_so,
                                      w16, beff, 256, 256);
    mm_kernel<<<dim3(2, 64, BQ), 256, SMEM_MM>>>(w16, 0, beff, 0,
                                                 h1, XT, nullptr, bigh, XT,
                                                 nullptr, 0, 256, 256, 0);
    gn_stats_h_kernel<<<BQ*32, 256>>>(bigh, 8, mu, rs);
    gn_add_kernel<<<16384, 256>>>(bigh, sa_g, sa_b, mu, rs, x, xb, h1, part);
    gn_reduce_kernel<<<256, 64>>>(part, mu, rs);

    // ================= Phase 2: cross linear attention =================
    wprep_kernel<<<dim3(8, BQ), 256>>>(W_cq, nm1_g, nm1_b, mu, rs, nullptr, w16, beff, 256, 256);
    mm_kernel<<<dim3(2, 64, BQ), 256, SMEM_MM>>>(w16, (size_t)256*256, beff, 1,
                                                 h1, XT, nullptr, h2, XT,
                                                 nullptr, 0, 256, 256, 0);
    gn_stats_conv_kernel<<<BQ*32, 256>>>(c, h1, 16, mu, rs);
    wprep_kernel<<<dim3(16, BQ), 256>>>(W_ckv, nm3_g, nm3_b, mu, rs, nullptr, w16, beff, 512, 512);
    mm_kernel<<<dim3(4, 64, BQ), 256, SMEM_MM>>>(w16, (size_t)512*512, beff, 1,
                                                 h1, (size_t)512*TT, nullptr, bigh, (size_t)512*TT,
                                                 nullptr, 0, 512, 512, 0);
    ctx_kernel<<<dim3(64, CSL), 256>>>(bigh, (size_t)512*TT, 0, 256, ctxp, cmax, csum);
    ctx_reduce_kernel<<<256, 256>>>(ctxp, cmax, csum, ctx);
    attn_out_kernel<<<dim3(64, 32), 256>>>(h2, XT, 0, ctx, h1, XT);
    wprep_kernel<<<dim3(8, 1), 256>>>(W_co, nullptr, nullptr, nullptr, nullptr, b_co,
                                      w16, beff, 256, 256);
    mm_kernel<<<dim3(2, 64, BQ), 256, SMEM_MM>>>(w16, 0, beff, 0,
                                                 h1, XT, nullptr, bigh, XT,
                                                 nullptr, 0, 256, 256, 0);
    gn_stats_h_kernel<<<BQ*32, 256>>>(bigh, 8, mu, rs);
    gn_add_kernel<<<16384, 256>>>(bigh, ca_g, ca_b, mu, rs, xb, xb, h1, part);
    gn_reduce_kernel<<<256, 64>>>(part, mu, rs);

    // ================= Phase 3: SiLU MLP =================
    wprep_kernel<<<dim3(20, BQ), 256>>>(W_m1, nm2_g, nm2_b, mu, rs, b_m1, w16, beff, 640, 256);
    mm_kernel<<<dim3(5, 64, BQ), 256, SMEM_MM>>>(w16, (size_t)640*256, beff, 1,
                                                 h1, XT, nullptr, h2, (size_t)640*TT,
                                                 nullptr, 0, 640, 256, 1 /*silu, fp16 out*/);
    wprep_kernel<<<dim3(8, 1), 256>>>(W_m2, nullptr, nullptr, nullptr, nullptr, b_m2,
                                      w16, beff, 256, 640);
    mm_kernel<<<dim3(2, 64, BQ), 256, SMEM_MM>>>(w16, 0, beff, 0,
                                                 h2, (size_t)640*TT, out, nullptr, XT,
                                                 xb, XT, 256, 640, 2 /*residual*/);
}

// round 15
// speedup vs baseline: 3.8387x; 1.2525x over previous
#include <cuda_runtime.h>
#include <cuda_fp16.h>
#include <cstdint>

#define BQ 8
#define DIMC 256
#define TT 8192
#define NH 8
#define EPSV 1e-5f
#define CSL 16          // ctx slices
#define CT  512         // t per slice

// fp16 stage: A[128 rows x 32k, pad 40h]=10240B, B[32k x 128n, pad 136h]=8704B
#define A_BYTES   10240
#define STG_BYTES 18944
#define NSTG      3
#define SMEM_MM   (NSTG * STG_BYTES)

// ---------------- scratch (device globals) ----------------
__device__ float g_x   [(size_t)BQ * DIMC * TT];     // xb residual (fp32)
__device__ float g_beff[BQ * 1024];
__device__ float g_mu  [BQ * 32];
__device__ float g_rs  [BQ * 32];
__device__ float g_ctx [BQ * NH * 32 * 32];
__device__ float g_ctxp[(size_t)CSL * BQ * NH * 32 * 32];
__device__ float g_cmax[CSL * BQ * NH * 32];
__device__ float g_csum[CSL * BQ * NH * 32];
__device__ float2 g_part[16384];
// fp16 planes
__device__ __align__(256) __half g_w16 [(size_t)BQ * 512 * 512];     // folded weights
__device__ __align__(256) __half g_h1  [(size_t)BQ * 512 * TT];      // activation plane (reused)
__device__ __align__(256) __half g_h2  [(size_t)BQ * 640 * TT];      // cq out / m1 out
__device__ __align__(256) __half g_bigh[(size_t)BQ * 768 * TT];      // qkv/ckv out; later so plane

// ==================== PTX helpers (plain sm_80+ only) ====================
__device__ __forceinline__ unsigned s2u(const void* p) {
    unsigned a;
    asm("{ .reg .u64 t; cvta.to.shared.u64 t, %1; cvt.u32.u64 %0, t; }" : "=r"(a) : "l"(p));
    return a;
}
#define LDSM4(r, addr) \
    asm volatile("ldmatrix.sync.aligned.m8n8.x4.shared.b16 {%0,%1,%2,%3}, [%4];" \
        : "=r"((r)[0]), "=r"((r)[1]), "=r"((r)[2]), "=r"((r)[3]) : "r"(addr))
#define LDSM2(r, addr) \
    asm volatile("ldmatrix.sync.aligned.m8n8.x2.shared.b16 {%0,%1}, [%2];" \
        : "=r"((r)[0]), "=r"((r)[1]) : "r"(addr))
#define LDSM4T(r, addr) \
    asm volatile("ldmatrix.sync.aligned.m8n8.x4.trans.shared.b16 {%0,%1,%2,%3}, [%4];" \
        : "=r"((r)[0]), "=r"((r)[1]), "=r"((r)[2]), "=r"((r)[3]) : "r"(addr))
__device__ __forceinline__ void mma_f16(float* c, const unsigned* a, const unsigned* b) {
    asm volatile("mma.sync.aligned.m16n8k16.row.col.f32.f16.f16.f32 "
        "{%0,%1,%2,%3}, {%4,%5,%6,%7}, {%8,%9}, {%0,%1,%2,%3};"
        : "+f"(c[0]), "+f"(c[1]), "+f"(c[2]), "+f"(c[3])
        : "r"(a[0]), "r"(a[1]), "r"(a[2]), "r"(a[3]), "r"(b[0]), "r"(b[1]));
}
__device__ __forceinline__ void cp16(unsigned saddr, const void* gaddr) {
    asm volatile("cp.async.cg.shared.global [%0], [%1], 16;" :: "r"(saddr), "l"(gaddr));
}
__device__ __forceinline__ void cp_commit() {
    asm volatile("cp.async.commit_group;");
}
template <int N>
__device__ __forceinline__ void cp_wait() {
    asm volatile("cp.async.wait_group %0;" :: "n"(N));
}

// ==================== tensor-core GEMM (pure fp16 operands, fp32 accum) ====================
__global__ __launch_bounds__(256, 2)
void mm_kernel(const __half* __restrict__ A16, size_t aStrB,
               const float* __restrict__ bias, int perB,
               const __half* __restrict__ B16, size_t bStrB,
               float* __restrict__ Y, __half* __restrict__ Yh, size_t yStrB,
               const float* __restrict__ R, size_t rStrB,
               int M, int K, int ep)
{
    extern __shared__ char smem[];
    const unsigned sb = s2u(smem);
    const int tid = threadIdx.x, lane = tid & 31, wid = tid >> 5;
    const int wr = wid >> 2, wc = wid & 3;
    const int mt = blockIdx.x, nt = blockIdx.y, b = blockIdx.z;
    const int m0 = mt * 128, n0 = nt * 128;
    const __half* Ab = A16 + (size_t)b * aStrB;
    const __half* Bb = B16 + (size_t)b * bStrB;

    float acc[4][4][4];
    #pragma unroll
    for (int i = 0; i < 4; i++)
        #pragma unroll
        for (int j = 0; j < 4; j++)
            #pragma unroll
            for (int r = 0; r < 4; r++) acc[i][j][r] = 0.f;

    const unsigned aoff = (lane & 15) * 80  + (lane >> 4) * 16;
    const unsigned boff = (lane & 15) * 272 + (lane >> 4) * 16;
    const int nk = K >> 5;

    auto cpChunk = [&](int kc, int st) {
        unsigned base = sb + st * STG_BYTES;
        #pragma unroll
        for (int u = 0; u < 2; u++) {
            int f = tid + u * 256;
            int row = f >> 2, c16 = f & 3;
            cp16(base + row * 80 + c16 * 16,
                 Ab + (size_t)(m0 + row) * K + kc * 32 + c16 * 8);
        }
        #pragma unroll
        for (int u = 0; u < 2; u++) {
            int f = tid + u * 256;
            int r = f >> 4, c16 = f & 15;
            cp16(base + A_BYTES + r * 272 + c16 * 16,
                 Bb + (size_t)(kc * 32 + r) * TT + n0 + c16 * 8);
        }
        cp_commit();
    };

    auto compute = [&](int st) {
        unsigned stb = sb + st * STG_BYTES;
        #pragma unroll
        for (int ks = 0; ks < 2; ks++) {
            unsigned bh[2][4];
            #pragma unroll
            for (int np = 0; np < 2; np++)
                LDSM4T(bh[np], stb + A_BYTES + ks * 4352 + wc * 64 + np * 32 + boff);
            #pragma unroll
            for (int mf = 0; mf < 4; mf++) {
                unsigned ah[4];
                LDSM4(ah, stb + wr * 5120 + mf * 1280 + ks * 32 + aoff);
                #pragma unroll
                for (int nf = 0; nf < 4; nf++)
                    mma_f16(acc[mf][nf], ah, &bh[nf >> 1][(nf & 1) * 2]);
            }
        }
    };

    const int pre = nk < NSTG ? nk : NSTG;
    for (int i = 0; i < pre; i++) cpChunk(i, i);

    for (int i = 0; i < nk; i++) {
        if (i + 2 < nk)      cp_wait<2>();
        else if (i + 1 < nk) cp_wait<1>();
        else                 cp_wait<0>();
        __syncthreads();
        compute(i % NSTG);
        __syncthreads();
        if (i + NSTG < nk) cpChunk(i + NSTG, i % NSTG);
    }

    const float* biasB = bias + (perB ? (size_t)b * M : 0);
    #pragma unroll
    for (int mf = 0; mf < 4; mf++) {
        int gm = m0 + wr * 64 + mf * 16 + (lane >> 2);
        float bv0 = biasB[gm], bv1 = biasB[gm + 8];
        #pragma unroll
        for (int nf = 0; nf < 4; nf++) {
            int gn = n0 + wc * 32 + nf * 8 + (lane & 3) * 2;
            float* a4 = acc[mf][nf];
            float2 v0 = make_float2(a4[0] + bv0, a4[1] + bv0);
            float2 v1 = make_float2(a4[2] + bv1, a4[3] + bv1);
            if (ep == 1) {
                v0.x /= (1.f + expf(-v0.x)); v0.y /= (1.f + expf(-v0.y));
                v1.x /= (1.f + expf(-v1.x)); v1.y /= (1.f + expf(-v1.y));
            } else if (ep == 2) {
                const float* Rb = R + (size_t)b * rStrB;
                float2 r0 = *(const float2*)&Rb[(size_t)gm * TT + gn];
                float2 r1 = *(const float2*)&Rb[(size_t)(gm + 8) * TT + gn];
                v0.x += r0.x; v0.y += r0.y; v1.x += r1.x; v1.y += r1.y;
            }
            if (Yh) {
                __half* Yb = Yh + (size_t)b * yStrB;
                *(__half2*)&Yb[(size_t)gm * TT + gn] =
                    __halves2half2(__float2half(v0.x), __float2half(v0.y));
                *(__half2*)&Yb[(size_t)(gm + 8) * TT + gn] =
                    __halves2half2(__float2half(v1.x), __float2half(v1.y));
            } else {
                float* Yb = Y + (size_t)b * yStrB;
                *(float2*)&Yb[(size_t)gm * TT + gn] = v0;
                *(float2*)&Yb[(size_t)(gm + 8) * TT + gn] = v1;
            }
        }
    }
}

// ==================== wprep: fused affine + weight fold + beff ====================
__global__ void wprep_kernel(const float* __restrict__ W,
                             const float* __restrict__ g, const float* __restrict__ be,
                             const float* __restrict__ mu, const float* __restrict__ rs,
                             const float* __restrict__ bias,
                             __half* __restrict__ w16, float* __restrict__ beff,
                             int M, int K)
{
    __shared__ float a_s[640], bb_s[640];
    const int b = blockIdx.y;
    const int GC = K >> 5;
    for (int c = threadIdx.x; c < K; c += 256) {
        if (g) {
            int grp = c / GC;
            float r = rs[b*32 + grp], m = mu[b*32 + grp];
            float av = g[c] * r;
            a_s[c] = av;
            bb_s[c] = be[c] - m * av;
        } else { a_s[c] = 1.f; bb_s[c] = 0.f; }
    }
    __syncthreads();
    const int m = blockIdx.x * 32 + (threadIdx.x >> 3);
    const int l8 = threadIdx.x & 7;
    const float* Wr = W + (size_t)m * K;
    __half* dst = w16 + (size_t)b * M * K + (size_t)m * K;
    float dot = 0.f;
    for (int k0 = l8 * 4; k0 < K; k0 += 32) {
        float4 w = *(const float4*)(Wr + k0);
        dot += w.x*bb_s[k0] + w.y*bb_s[k0+1] + w.z*bb_s[k0+2] + w.w*bb_s[k0+3];
        __half h[4] = {__float2half(w.x * a_s[k0]),   __float2half(w.y * a_s[k0+1]),
                       __float2half(w.z * a_s[k0+2]), __float2half(w.w * a_s[k0+3])};
        *(uint2*)(dst + k0) = *(uint2*)h;
    }
    dot += __shfl_down_sync(0xffffffffu, dot, 4, 8);
    dot += __shfl_down_sync(0xffffffffu, dot, 2, 8);
    dot += __shfl_down_sync(0xffffffffu, dot, 1, 8);
    if (l8 == 0)
        beff[(size_t)b * M + m] = dot + (bias ? bias[m] : 0.f);
}

// ==================== group-norm stats ====================
__global__ void gn_stats_conv_kernel(const float* __restrict__ x, __half* __restrict__ xh,
                                     int GC, float* __restrict__ mu, float* __restrict__ rs)
{
    const size_t n = (size_t)GC * TT;
    const size_t base = (size_t)blockIdx.x * n;
    const float4* x4 = (const float4*)(x + base);
    const int n4 = (int)(n >> 2);
    float s = 0.f, sq = 0.f;
    for (int i = threadIdx.x; i < n4; i += 256) {
        float4 v = x4[i];
        s += (v.x + v.y) + (v.z + v.w);
        sq += v.x*v.x + v.y*v.y + v.z*v.z + v.w*v.w;
        __half h[4] = {__float2half(v.x), __float2half(v.y),
                       __float2half(v.z), __float2half(v.w)};
        *(uint2*)(xh + base + (size_t)i * 4) = *(uint2*)h;
    }
    __shared__ float sh1[8], sh2[8];
    int lane = threadIdx.x & 31, w = threadIdx.x >> 5;
    #pragma unroll
    for (int o = 16; o > 0; o >>= 1) {
        s += __shfl_xor_sync(0xffffffffu, s, o);
        sq += __shfl_xor_sync(0xffffffffu, sq, o);
    }
    if (lane == 0) { sh1[w] = s; sh2[w] = sq; }
    __syncthreads();
    if (threadIdx.x < 8) {
        s = sh1[threadIdx.x]; sq = sh2[threadIdx.x];
        #pragma unroll
        for (int o = 4; o > 0; o >>= 1) {
            s += __shfl_xor_sync(0xffu, s, o);
            sq += __shfl_xor_sync(0xffu, sq, o);
        }
        if (threadIdx.x == 0) {
            float inv_n = 1.f / (float)n;
            float m = s * inv_n;
            float var = sq * inv_n - m * m;
            mu[blockIdx.x] = m;
            rs[blockIdx.x] = rsqrtf(fmaxf(var, 0.f) + EPSV);
        }
    }
}

__global__ void gn_stats_h_kernel(const __half* __restrict__ x, int GC,
                                  float* __restrict__ mu, float* __restrict__ rs)
{
    const size_t n = (size_t)GC * TT;
    const uint4* x8 = (const uint4*)(x + (size_t)blockIdx.x * n);
    const int n8 = (int)(n >> 3);
    float s = 0.f, sq = 0.f;
    for (int i = threadIdx.x; i < n8; i += 256) {
        uint4 v = x8[i];
        const __half2* hh = (const __half2*)&v;
        #pragma unroll
        for (int j = 0; j < 4; j++) {
            float2 f = __half22float2(hh[j]);
            s += f.x + f.y;
            sq += f.x*f.x + f.y*f.y;
        }
    }
    __shared__ float sh1[8], sh2[8];
    int lane = threadIdx.x & 31, w = threadIdx.x >> 5;
    #pragma unroll
    for (int o = 16; o > 0; o >>= 1) {
        s += __shfl_xor_sync(0xffffffffu, s, o);
        sq += __shfl_xor_sync(0xffffffffu, sq, o);
    }
    if (lane == 0) { sh1[w] = s; sh2[w] = sq; }
    __syncthreads();
    if (threadIdx.x < 8) {
        s = sh1[threadIdx.x]; sq = sh2[threadIdx.x];
        #pragma unroll
        for (int o = 4; o > 0; o >>= 1) {
            s += __shfl_xor_sync(0xffu, s, o);
            sq += __shfl_xor_sync(0xffu, sq, o);
        }
        if (threadIdx.x == 0) {
            float inv_n = 1.f / (float)n;
            float m = s * inv_n;
            float var = sq * inv_n - m * m;
            mu[blockIdx.x] = m;
            rs[blockIdx.x] = rsqrtf(fmaxf(var, 0.f) + EPSV);
        }
    }
}

// ==================== attention: tensor-core online-softmax ctx ====================
// grid (64, CSL), 256 threads. Exp phase: thread = (row d = tid>>3, seg j = tid&7).
// MMA phase: 8 warps in a 2(m) x 4(n) grid of 16x8 ctx tiles.
__global__ void ctx_kernel(const __half* __restrict__ kv, size_t strideB, int koff, int voff,
                           float* __restrict__ cpart,
                           float* __restrict__ cmax, float* __restrict__ csum)
{
    int bh = blockIdx.x;
    int slice = blockIdx.y;
    int b = bh / NH, h = bh % NH;
    __shared__ __half ksh[32][72];
    __shared__ __half vsh[32][72];
    __shared__ float scale_s[32];
    const int tid = threadIdx.x, lane = tid & 31, wid = tid >> 5;
    const int d = tid >> 3, j = tid & 7;
    const int mt = wid >> 2, nt = wid & 3;
    const __half* kp = kv + (size_t)b*strideB + (size_t)(koff + h*32 + d)*TT + slice*CT + j*8;
    const __half* vp = kv + (size_t)b*strideB + (size_t)(voff + h*32 + d)*TT + slice*CT + j*8;

    const unsigned ksb = s2u(ksh), vsb = s2u(vsh);
    const unsigned aaddr = ksb + (mt*16 + (lane & 15)) * 144 + (lane >> 4) * 16;
    const unsigned baddr = vsb + (nt*8 + (lane & 7)) * 144 + ((lane >> 3) & 1) * 16;

    float mold = -1e30f, ssum = 0.f;
    float c[4] = {0.f, 0.f, 0.f, 0.f};

    uint4 kr = *(const uint4*)kp;
    uint4 vr = *(const uint4*)vp;

    for (int tc = 0; tc < CT; tc += 64) {
        float kf[8];
        float lmax = -1e30f;
        const __half2* kh = (const __half2*)&kr;
        #pragma unroll
        for (int q = 0; q < 4; q++) {
            float2 f = __half22float2(kh[q]);
            kf[2*q] = f.x; kf[2*q+1] = f.y;
            lmax = fmaxf(lmax, fmaxf(f.x, f.y));
        }
        #pragma unroll
        for (int o = 4; o > 0; o >>= 1)
            lmax = fmaxf(lmax, __shfl_xor_sync(0xffffffffu, lmax, o, 8));
        float mnew = fmaxf(mold, lmax);
        float scale = expf(mold - mnew);
        mold = mnew;
        __half eh[8];
        float psum = 0.f;
        #pragma unroll
        for (int q = 0; q < 8; q++) {
            float e = expf(kf[q] - mnew);
            eh[q] = __float2half(e);
            psum += e;
        }
        #pragma unroll
        for (int o = 4; o > 0; o >>= 1)
            psum += __shfl_xor_sync(0xffffffffu, psum, o, 8);
        ssum = ssum * scale + psum;

        __syncthreads();                     // prior chunk's MMA reads done
        *(uint4*)&ksh[d][j*8] = *(uint4*)eh;
        *(uint4*)&vsh[d][j*8] = vr;
        if (j == 0) scale_s[d] = scale;
        __syncthreads();                     // stage built

        if (tc + 64 < CT) {                  // prefetch next chunk over MMA phase
            kr = *(const uint4*)(kp + tc + 64);
            vr = *(const uint4*)(vp + tc + 64);
        }

        float s0 = scale_s[mt*16 + (lane >> 2)];
        float s1 = scale_s[mt*16 + (lane >> 2) + 8];
        c[0] *= s0; c[1] *= s0; c[2] *= s1; c[3] *= s1;
        #pragma unroll
        for (int ks = 0; ks < 4; ks++) {
            unsigned a[4], bfr[2];
            LDSM4(a, aaddr + ks * 32);
            LDSM2(bfr, baddr + ks * 32);
            mma_f16(c, a, bfr);
        }
    }

    int row0 = mt*16 + (lane >> 2);
    int col = nt*8 + (lane & 3) * 2;
    float* cp = cpart + (size_t)slice*65536 + (size_t)bh*1024;
    cp[row0*32 + col]       = c[0];
    cp[row0*32 + col + 1]   = c[1];
    cp[(row0+8)*32 + col]   = c[2];
    cp[(row0+8)*32 + col+1] = c[3];
    if (j == 0) {
        cmax[slice*2048 + bh*32 + d] = mold;
        csum[slice*2048 + bh*32 + d] = ssum;
    }
}

__global__ void ctx_reduce_kernel(const float* __restrict__ cpart,
                                  const float* __restrict__ cmax,
                                  const float* __restrict__ csum,
                                  float* __restrict__ ctx)
{
    int i = blockIdx.x * 256 + threadIdx.x;   // 65536
    int bh = i >> 10, d = (i & 1023) >> 5;
    float M = -1e30f;
    #pragma unroll
    for (int sl = 0; sl < CSL; sl++) M = fmaxf(M, cmax[sl*2048 + bh*32 + d]);
    float tot = 0.f, v = 0.f;
    #pragma unroll
    for (int sl = 0; sl < CSL; sl++) {
        float w = expf(cmax[sl*2048 + bh*32 + d] - M);
        tot += csum[sl*2048 + bh*32 + d] * w;
        v   += cpart[(size_t)sl*65536 + i] * w;
    }
    ctx[i] = v / tot;
}

__global__ void attn_out_kernel(const __half* __restrict__ q, size_t strideB, int qoff,
                                const float* __restrict__ ctx,
                                __half* __restrict__ o, size_t oStrideB)
{
    int bh = blockIdx.x;
    int b = bh / NH, h = bh % NH;
    int t = blockIdx.y * 256 + threadIdx.x;
    __shared__ float cs[32][32];
    for (int i = threadIdx.x; i < 1024; i += 256)
        cs[i >> 5][i & 31] = ctx[(size_t)bh*1024 + i];
    __syncthreads();
    const __half* qp = q + (size_t)b*strideB + (size_t)(qoff + h*32)*TT + t;
    float p[32];
    float mx = -1e30f;
    #pragma unroll
    for (int d = 0; d < 32; d++) { p[d] = __half2float(qp[(size_t)d*TT]); mx = fmaxf(mx, p[d]); }
    float s = 0.f;
    #pragma unroll
    for (int d = 0; d < 32; d++) { p[d] = expf(p[d] - mx); s += p[d]; }
    float inv = 0.17677669529663687f / s;
    #pragma unroll
    for (int d = 0; d < 32; d++) p[d] *= inv;
    float accv[32];
    #pragma unroll
    for (int e = 0; e < 32; e++) accv[e] = 0.f;
    #pragma unroll
    for (int d = 0; d < 32; d++) {
        float pd = p[d];
        #pragma unroll
        for (int e4 = 0; e4 < 8; e4++) {
            float4 cv = *(const float4*)&cs[d][e4*4];
            accv[e4*4+0] += cv.x * pd;
            accv[e4*4+1] += cv.y * pd;
            accv[e4*4+2] += cv.z * pd;
            accv[e4*4+3] += cv.w * pd;
        }
    }
    __half* op = o + (size_t)b*oStrideB + (size_t)(h*32)*TT + t;
    #pragma unroll
    for (int e = 0; e < 32; e++) op[(size_t)e*TT] = __float2half(accv[e]);
}

// y = gn(v_fp16)*g + b + r ; writes fp32 y, fp16 yh, per-block (sum,sumsq) partials of y
__global__ void gn_add_kernel(const __half* __restrict__ v,
                              const float* __restrict__ gamma, const float* __restrict__ beta,
                              const float* __restrict__ mu, const float* __restrict__ rs,
                              const float* __restrict__ r, float* __restrict__ y,
                              __half* __restrict__ yh, float2* __restrict__ part)
{
    size_t i = ((size_t)blockIdx.x * 256 + threadIdx.x) * 4;
    int c = (int)((i / TT) % DIMC);
    int b = (int)(i / ((size_t)DIMC * TT));
    int grp = c >> 3;
    float rr = rs[b*32 + grp], m = mu[b*32 + grp];
    float sc = gamma[c] * rr;
    float sh = beta[c] - m * sc;
    uint2 hv = *(const uint2*)(v + i);
    float2 f0 = __half22float2(((const __half2*)&hv)[0]);
    float2 f1 = __half22float2(((const __half2*)&hv)[1]);
    float4 rv = *(const float4*)(r + i);
    float4 o;
    o.x = f0.x * sc + sh + rv.x;
    o.y = f0.y * sc + sh + rv.y;
    o.z = f1.x * sc + sh + rv.z;
    o.w = f1.y * sc + sh + rv.w;
    *(float4*)(y + i) = o;
    __half h[4] = {__float2half(o.x), __float2half(o.y), __float2half(o.z), __float2half(o.w)};
    *(uint2*)(yh + i) = *(uint2*)h;

    float s  = (o.x + o.y) + (o.z + o.w);
    float sq = o.x*o.x + o.y*o.y + o.z*o.z + o.w*o.w;
    __shared__ float sh1[8], sh2[8];
    int lane = threadIdx.x & 31, w = threadIdx.x >> 5;
    #pragma unroll
    for (int o2 = 16; o2 > 0; o2 >>= 1) {
        s  += __shfl_xor_sync(0xffffffffu, s,  o2);
        sq += __shfl_xor_sync(0xffffffffu, sq, o2);
    }
    if (lane == 0) { sh1[w] = s; sh2[w] = sq; }
    __syncthreads();
    if (threadIdx.x < 8) {
        s = sh1[threadIdx.x]; sq = sh2[threadIdx.x];
        #pragma unroll
        for (int o2 = 4; o2 > 0; o2 >>= 1) {
            s  += __shfl_xor_sync(0xffu, s,  o2);
            sq += __shfl_xor_sync(0xffu, sq, o2);
        }
        if (threadIdx.x == 0) part[blockIdx.x] = make_float2(s, sq);
    }
}

__global__ void gn_reduce_kernel(const float2* __restrict__ part,
                                 float* __restrict__ mu, float* __restrict__ rs)
{
    int g = blockIdx.x;
    int t = threadIdx.x;
    float2 p = part[g * 64 + t];
    float s = p.x, sq = p.y;
    #pragma unroll
    for (int o = 16; o > 0; o >>= 1) {
        s  += __shfl_xor_sync(0xffffffffu, s,  o);
        sq += __shfl_xor_sync(0xffffffffu, sq, o);
    }
    __shared__ float a[2], bsh[2];
    if ((t & 31) == 0) { a[t >> 5] = s; bsh[t >> 5] = sq; }
    __syncthreads();
    if (t == 0) {
        s = a[0] + a[1]; sq = bsh[0] + bsh[1];
        const float inv_n = 1.f / 65536.f;
        float m = s * inv_n;
        float var = sq * inv_n - m * m;
        mu[g] = m;
        rs[g] = rsqrtf(fmaxf(var, 0.f) + EPSV);
    }
}

// ==================== host orchestration ====================
extern "C" void kernel_launch(void* const* d_in, const int* in_sizes, int n_in,
                              void* d_out, int out_size)
{
    const float* x     = (const float*)d_in[0];
    const float* c     = (const float*)d_in[1];
    const float* W_qkv = (const float*)d_in[2];
    const float* W_so  = (const float*)d_in[3];
    const float* b_so  = (const float*)d_in[4];
    const float* sa_g  = (const float*)d_in[5];
    const float* sa_b  = (const float*)d_in[6];
    const float* W_cq  = (const float*)d_in[7];
    const float* W_ckv = (const float*)d_in[8];
    const float* W_co  = (const float*)d_in[9];
    const float* b_co  = (const float*)d_in[10];
    const float* ca_g  = (const float*)d_in[11];
    const float* ca_b  = (const float*)d_in[12];
    const float* W_m1  = (const float*)d_in[13];
    const float* b_m1  = (const float*)d_in[14];
    const float* W_m2  = (const float*)d_in[15];
    const float* b_m2  = (const float*)d_in[16];
    const float* nm_g  = (const float*)d_in[17];
    const float* nm_b  = (const float*)d_in[18];
    const float* nm1_g = (const float*)d_in[19];
    const float* nm1_b = (const float*)d_in[20];
    const float* nm2_g = (const float*)d_in[21];
    const float* nm2_b = (const float*)d_in[22];
    const float* nm3_g = (const float*)d_in[23];
    const float* nm3_b = (const float*)d_in[24];
    float* out = (float*)d_out;

    float *xb, *beff, *mu, *rs, *ctx, *ctxp, *cmax, *csum;
    float2* part;
    __half *w16, *h1, *h2, *bigh;
    cudaGetSymbolAddress((void**)&xb,   g_x);
    cudaGetSymbolAddress((void**)&beff, g_beff);
    cudaGetSymbolAddress((void**)&mu,   g_mu);
    cudaGetSymbolAddress((void**)&rs,   g_rs);
    cudaGetSymbolAddress((void**)&ctx,  g_ctx);
    cudaGetSymbolAddress((void**)&ctxp, g_ctxp);
    cudaGetSymbolAddress((void**)&cmax, g_cmax);
    cudaGetSymbolAddress((void**)&csum, g_csum);
    cudaGetSymbolAddress((void**)&part, g_part);
    cudaGetSymbolAddress((void**)&w16,  g_w16);
    cudaGetSymbolAddress((void**)&h1,   g_h1);
    cudaGetSymbolAddress((void**)&h2,   g_h2);
    cudaGetSymbolAddress((void**)&bigh, g_bigh);

    static bool attr_set = false;
    if (!attr_set) {
        cudaFuncSetAttribute(mm_kernel, cudaFuncAttributeMaxDynamicSharedMemorySize, SMEM_MM);
        attr_set = true;
    }

    const size_t XT = (size_t)DIMC * TT;

    // ================= Phase 1: self linear attention =================
    gn_stats_conv_kernel<<<BQ*32, 256>>>(x, h1, 8, mu, rs);
    wprep_kernel<<<dim3(24, BQ), 256>>>(W_qkv, nm_g, nm_b, mu, rs, nullptr, w16, beff, 768, 256);
    mm_kernel<<<dim3(6, 64, BQ), 256, SMEM_MM>>>(w16, (size_t)768*256, beff, 1,
                                                 h1, XT, nullptr, bigh, (size_t)768*TT,
                                                 nullptr, 0, 768, 256, 0);
    ctx_kernel<<<dim3(64, CSL), 256>>>(bigh, (size_t)768*TT, 256, 512, ctxp, cmax, csum);
    ctx_reduce_kernel<<<256, 256>>>(ctxp, cmax, csum, ctx);
    attn_out_kernel<<<dim3(64, 32), 256>>>(bigh, (size_t)768*TT, 0, ctx, h1, XT);
    wprep_kernel<<<dim3(8, 1), 256>>>(W_so, nullptr, nullptr, nullptr, nullptr, b_so,
                                      w16, beff, 256, 256);
    mm_kernel<<<dim3(2, 64, BQ), 256, SMEM_MM>>>(w16, 0, beff, 0,
                                                 h1, XT, nullptr, bigh, XT,
                                                 nullptr, 0, 256, 256, 0);
    gn_stats_h_kernel<<<BQ*32, 256>>>(bigh, 8, mu, rs);
    gn_add_kernel<<<16384, 256>>>(bigh, sa_g, sa_b, mu, rs, x, xb, h1, part);
    gn_reduce_kernel<<<256, 64>>>(part, mu, rs);

    // ================= Phase 2: cross linear attention =================
    wprep_kernel<<<dim3(8, BQ), 256>>>(W_cq, nm1_g, nm1_b, mu, rs, nullptr, w16, beff, 256, 256);
    mm_kernel<<<dim3(2, 64, BQ), 256, SMEM_MM>>>(w16, (size_t)256*256, beff, 1,
                                                 h1, XT, nullptr, h2, XT,
                                                 nullptr, 0, 256, 256, 0);
    gn_stats_conv_kernel<<<BQ*32, 256>>>(c, h1, 16, mu, rs);
    wprep_kernel<<<dim3(16, BQ), 256>>>(W_ckv, nm3_g, nm3_b, mu, rs, nullptr, w16, beff, 512, 512);
    mm_kernel<<<dim3(4, 64, BQ), 256, SMEM_MM>>>(w16, (size_t)512*512, beff, 1,
                                                 h1, (size_t)512*TT, nullptr, bigh, (size_t)512*TT,
                                                 nullptr, 0, 512, 512, 0);
    ctx_kernel<<<dim3(64, CSL), 256>>>(bigh, (size_t)512*TT, 0, 256, ctxp, cmax, csum);
    ctx_reduce_kernel<<<256, 256>>>(ctxp, cmax, csum, ctx);
    attn_out_kernel<<<dim3(64, 32), 256>>>(h2, XT, 0, ctx, h1, XT);
    wprep_kernel<<<dim3(8, 1), 256>>>(W_co, nullptr, nullptr, nullptr, nullptr, b_co,
                                      w16, beff, 256, 256);
    mm_kernel<<<dim3(2, 64, BQ), 256, SMEM_MM>>>(w16, 0, beff, 0,
                                                 h1, XT, nullptr, bigh, XT,
                                                 nullptr, 0, 256, 256, 0);
    gn_stats_h_kernel<<<BQ*32, 256>>>(bigh, 8, mu, rs);
    gn_add_kernel<<<16384, 256>>>(bigh, ca_g, ca_b, mu, rs, xb, xb, h1, part);
    gn_reduce_kernel<<<256, 64>>>(part, mu, rs);

    // ================= Phase 3: SiLU MLP =================
    wprep_kernel<<<dim3(20, BQ), 256>>>(W_m1, nm2_g, nm2_b, mu, rs, b_m1, w16, beff, 640, 256);
    mm_kernel<<<dim3(5, 64, BQ), 256, SMEM_MM>>>(w16, (size_t)640*256, beff, 1,
                                                 h1, XT, nullptr, h2, (size_t)640*TT,
                                                 nullptr, 0, 640, 256, 1 /*silu, fp16 out*/);
    wprep_kernel<<<dim3(8, 1), 256>>>(W_m2, nullptr, nullptr, nullptr, nullptr, b_m2,
                                      w16, beff, 256, 640);
    mm_kernel<<<dim3(2, 64, BQ), 256, SMEM_MM>>>(w16, 0, beff, 0,
                                                 h2, (size_t)640*TT, out, nullptr, XT,
                                                 xb, XT, 256, 640, 2 /*residual*/);
}

// round 16
// speedup vs baseline: 4.0880x; 1.0649x over previous
#include <cuda_runtime.h>
#include <cuda_fp16.h>
#include <cstdint>

#define BQ 8
#define DIMC 256
#define TT 8192
#define NH 8
#define EPSV 1e-5f
#define CSL 16          // ctx slices
#define CT  512         // t per slice

// fp16 stage, BK=64: A[128 rows x 64k, pad 72h]=18432B, B[64k x 128n, pad 136h]=17408B
#define A_BYTES   18432
#define STG_BYTES 35840
#define NSTG      3
#define SMEM_MM   (NSTG * STG_BYTES)

// ---------------- scratch (device globals) ----------------
__device__ float g_x   [(size_t)BQ * DIMC * TT];     // xb residual (fp32)
__device__ float g_beff[BQ * 1024];
__device__ float g_mu  [BQ * 32];
__device__ float g_rs  [BQ * 32];
__device__ float g_ctx [BQ * NH * 32 * 32];
__device__ float g_ctxp[(size_t)CSL * BQ * NH * 32 * 32];
__device__ float g_cmax[CSL * BQ * NH * 32];
__device__ float g_csum[CSL * BQ * NH * 32];
__device__ float2 g_part[16384];
// fp16 planes
__device__ __align__(256) __half g_w16 [(size_t)BQ * 512 * 512];     // folded weights
__device__ __align__(256) __half g_h1  [(size_t)BQ * 512 * TT];      // activation plane (reused)
__device__ __align__(256) __half g_h2  [(size_t)BQ * 640 * TT];      // cq out / m1 out
__device__ __align__(256) __half g_bigh[(size_t)BQ * 768 * TT];      // qkv/ckv out; later so plane

// ==================== PTX helpers (plain sm_80+ only) ====================
__device__ __forceinline__ unsigned s2u(const void* p) {
    unsigned a;
    asm("{ .reg .u64 t; cvta.to.shared.u64 t, %1; cvt.u32.u64 %0, t; }" : "=r"(a) : "l"(p));
    return a;
}
#define LDSM4(r, addr) \
    asm volatile("ldmatrix.sync.aligned.m8n8.x4.shared.b16 {%0,%1,%2,%3}, [%4];" \
        : "=r"((r)[0]), "=r"((r)[1]), "=r"((r)[2]), "=r"((r)[3]) : "r"(addr))
#define LDSM2(r, addr) \
    asm volatile("ldmatrix.sync.aligned.m8n8.x2.shared.b16 {%0,%1}, [%2];" \
        : "=r"((r)[0]), "=r"((r)[1]) : "r"(addr))
#define LDSM4T(r, addr) \
    asm volatile("ldmatrix.sync.aligned.m8n8.x4.trans.shared.b16 {%0,%1,%2,%3}, [%4];" \
        : "=r"((r)[0]), "=r"((r)[1]), "=r"((r)[2]), "=r"((r)[3]) : "r"(addr))
__device__ __forceinline__ void mma_f16(float* c, const unsigned* a, const unsigned* b) {
    asm volatile("mma.sync.aligned.m16n8k16.row.col.f32.f16.f16.f32 "
        "{%0,%1,%2,%3}, {%4,%5,%6,%7}, {%8,%9}, {%0,%1,%2,%3};"
        : "+f"(c[0]), "+f"(c[1]), "+f"(c[2]), "+f"(c[3])
        : "r"(a[0]), "r"(a[1]), "r"(a[2]), "r"(a[3]), "r"(b[0]), "r"(b[1]));
}
__device__ __forceinline__ void cp16(unsigned saddr, const void* gaddr) {
    asm volatile("cp.async.cg.shared.global [%0], [%1], 16;" :: "r"(saddr), "l"(gaddr));
}
__device__ __forceinline__ void cp_commit() {
    asm volatile("cp.async.commit_group;");
}
template <int N>
__device__ __forceinline__ void cp_wait() {
    asm volatile("cp.async.wait_group %0;" :: "n"(N));
}

// ==================== tensor-core GEMM (fp16, BK=64, single sync/chunk) ====================
__global__ __launch_bounds__(256, 2)
void mm_kernel(const __half* __restrict__ A16, size_t aStrB,
               const float* __restrict__ bias, int perB,
               const __half* __restrict__ B16, size_t bStrB,
               float* __restrict__ Y, __half* __restrict__ Yh, size_t yStrB,
               const float* __restrict__ R, size_t rStrB,
               int M, int K, int ep)
{
    extern __shared__ char smem[];
    const unsigned sb = s2u(smem);
    const int tid = threadIdx.x, lane = tid & 31, wid = tid >> 5;
    const int wr = wid >> 2, wc = wid & 3;
    const int mt = blockIdx.x, nt = blockIdx.y, b = blockIdx.z;
    const int m0 = mt * 128, n0 = nt * 128;
    const __half* Ab = A16 + (size_t)b * aStrB;
    const __half* Bb = B16 + (size_t)b * bStrB;

    float acc[4][4][4];
    #pragma unroll
    for (int i = 0; i < 4; i++)
        #pragma unroll
        for (int j = 0; j < 4; j++)
            #pragma unroll
            for (int r = 0; r < 4; r++) acc[i][j][r] = 0.f;

    const unsigned aoff = (lane & 15) * 144 + (lane >> 4) * 16;
    const unsigned boff = (lane & 15) * 272 + (lane >> 4) * 16;
    const int nk = K >> 6;                    // BK = 64

    auto cpChunk = [&](int kc, int st) {
        unsigned base = sb + st * STG_BYTES;
        #pragma unroll
        for (int u = 0; u < 4; u++) {          // A: 1024 cp16 (128 rows x 8)
            int f = tid + u * 256;
            int row = f >> 3, c16 = f & 7;
            cp16(base + row * 144 + c16 * 16,
                 Ab + (size_t)(m0 + row) * K + kc * 64 + c16 * 8);
        }
        #pragma unroll
        for (int u = 0; u < 4; u++) {          // B: 1024 cp16 (64 rows x 16)
            int f = tid + u * 256;
            int r = f >> 4, c16 = f & 15;
            cp16(base + A_BYTES + r * 272 + c16 * 16,
                 Bb + (size_t)(kc * 64 + r) * TT + n0 + c16 * 8);
        }
        cp_commit();
    };

    auto compute = [&](int st) {
        unsigned stb = sb + st * STG_BYTES;
        #pragma unroll
        for (int ks = 0; ks < 4; ks++) {
            unsigned bh[2][4];
            #pragma unroll
            for (int np = 0; np < 2; np++)
                LDSM4T(bh[np], stb + A_BYTES + ks * 4352 + wc * 64 + np * 32 + boff);
            #pragma unroll
            for (int mf = 0; mf < 4; mf++) {
                unsigned ah[4];
                LDSM4(ah, stb + wr * 9216 + mf * 2304 + ks * 32 + aoff);
                #pragma unroll
                for (int nf = 0; nf < 4; nf++)
                    mma_f16(acc[mf][nf], ah, &bh[nf >> 1][(nf & 1) * 2]);
            }
        }
    };

    // prologue: 2 stages in flight; lookahead-2 writes the stage consumed LAST iter,
    // so the top-of-loop barrier is the only barrier needed.
    cpChunk(0, 0);
    cpChunk(1, 1);
    for (int i = 0; i < nk; i++) {
        if (i + 1 < nk) cp_wait<1>(); else cp_wait<0>();
        __syncthreads();
        compute(i % NSTG);
        int nx = i + 2;
        if (nx < nk) cpChunk(nx, nx % NSTG);   // stage (i-1)%3: consumed last iter
    }

    const float* biasB = bias + (perB ? (size_t)b * M : 0);
    #pragma unroll
    for (int mf = 0; mf < 4; mf++) {
        int gm = m0 + wr * 64 + mf * 16 + (lane >> 2);
        float bv0 = biasB[gm], bv1 = biasB[gm + 8];
        #pragma unroll
        for (int nf = 0; nf < 4; nf++) {
            int gn = n0 + wc * 32 + nf * 8 + (lane & 3) * 2;
            float* a4 = acc[mf][nf];
            float2 v0 = make_float2(a4[0] + bv0, a4[1] + bv0);
            float2 v1 = make_float2(a4[2] + bv1, a4[3] + bv1);
            if (ep == 1) {
                v0.x /= (1.f + expf(-v0.x)); v0.y /= (1.f + expf(-v0.y));
                v1.x /= (1.f + expf(-v1.x)); v1.y /= (1.f + expf(-v1.y));
            } else if (ep == 2) {
                const float* Rb = R + (size_t)b * rStrB;
                float2 r0 = *(const float2*)&Rb[(size_t)gm * TT + gn];
                float2 r1 = *(const float2*)&Rb[(size_t)(gm + 8) * TT + gn];
                v0.x += r0.x; v0.y += r0.y; v1.x += r1.x; v1.y += r1.y;
            }
            if (Yh) {
                __half* Yb = Yh + (size_t)b * yStrB;
                *(__half2*)&Yb[(size_t)gm * TT + gn] =
                    __halves2half2(__float2half(v0.x), __float2half(v0.y));
                *(__half2*)&Yb[(size_t)(gm + 8) * TT + gn] =
                    __halves2half2(__float2half(v1.x), __float2half(v1.y));
            } else {
                float* Yb = Y + (size_t)b * yStrB;
                *(float2*)&Yb[(size_t)gm * TT + gn] = v0;
                *(float2*)&Yb[(size_t)(gm + 8) * TT + gn] = v1;
            }
        }
    }
}

// ==================== wprep: fused affine + weight fold + beff ====================
__global__ void wprep_kernel(const float* __restrict__ W,
                             const float* __restrict__ g, const float* __restrict__ be,
                             const float* __restrict__ mu, const float* __restrict__ rs,
                             const float* __restrict__ bias,
                             __half* __restrict__ w16, float* __restrict__ beff,
                             int M, int K)
{
    __shared__ float a_s[640], bb_s[640];
    const int b = blockIdx.y;
    const int GC = K >> 5;
    for (int c = threadIdx.x; c < K; c += 256) {
        if (g) {
            int grp = c / GC;
            float r = rs[b*32 + grp], m = mu[b*32 + grp];
            float av = g[c] * r;
            a_s[c] = av;
            bb_s[c] = be[c] - m * av;
        } else { a_s[c] = 1.f; bb_s[c] = 0.f; }
    }
    __syncthreads();
    const int m = blockIdx.x * 32 + (threadIdx.x >> 3);
    const int l8 = threadIdx.x & 7;
    const float* Wr = W + (size_t)m * K;
    __half* dst = w16 + (size_t)b * M * K + (size_t)m * K;
    float dot = 0.f;
    for (int k0 = l8 * 4; k0 < K; k0 += 32) {
        float4 w = *(const float4*)(Wr + k0);
        dot += w.x*bb_s[k0] + w.y*bb_s[k0+1] + w.z*bb_s[k0+2] + w.w*bb_s[k0+3];
        __half h[4] = {__float2half(w.x * a_s[k0]),   __float2half(w.y * a_s[k0+1]),
                       __float2half(w.z * a_s[k0+2]), __float2half(w.w * a_s[k0+3])};
        *(uint2*)(dst + k0) = *(uint2*)h;
    }
    dot += __shfl_down_sync(0xffffffffu, dot, 4, 8);
    dot += __shfl_down_sync(0xffffffffu, dot, 2, 8);
    dot += __shfl_down_sync(0xffffffffu, dot, 1, 8);
    if (l8 == 0)
        beff[(size_t)b * M + m] = dot + (bias ? bias[m] : 0.f);
}

// ==================== group-norm stats ====================
__global__ void gn_stats_conv_kernel(const float* __restrict__ x, __half* __restrict__ xh,
                                     int GC, float* __restrict__ mu, float* __restrict__ rs)
{
    const size_t n = (size_t)GC * TT;
    const size_t base = (size_t)blockIdx.x * n;
    const float4* x4 = (const float4*)(x + base);
    const int n4 = (int)(n >> 2);
    float s = 0.f, sq = 0.f;
    for (int i = threadIdx.x; i < n4; i += 256) {
        float4 v = x4[i];
        s += (v.x + v.y) + (v.z + v.w);
        sq += v.x*v.x + v.y*v.y + v.z*v.z + v.w*v.w;
        __half h[4] = {__float2half(v.x), __float2half(v.y),
                       __float2half(v.z), __float2half(v.w)};
        *(uint2*)(xh + base + (size_t)i * 4) = *(uint2*)h;
    }
    __shared__ float sh1[8], sh2[8];
    int lane = threadIdx.x & 31, w = threadIdx.x >> 5;
    #pragma unroll
    for (int o = 16; o > 0; o >>= 1) {
        s += __shfl_xor_sync(0xffffffffu, s, o);
        sq += __shfl_xor_sync(0xffffffffu, sq, o);
    }
    if (lane == 0) { sh1[w] = s; sh2[w] = sq; }
    __syncthreads();
    if (threadIdx.x < 8) {
        s = sh1[threadIdx.x]; sq = sh2[threadIdx.x];
        #pragma unroll
        for (int o = 4; o > 0; o >>= 1) {
            s += __shfl_xor_sync(0xffu, s, o);
            sq += __shfl_xor_sync(0xffu, sq, o);
        }
        if (threadIdx.x == 0) {
            float inv_n = 1.f / (float)n;
            float m = s * inv_n;
            float var = sq * inv_n - m * m;
            mu[blockIdx.x] = m;
            rs[blockIdx.x] = rsqrtf(fmaxf(var, 0.f) + EPSV);
        }
    }
}

__global__ void gn_stats_h_kernel(const __half* __restrict__ x, int GC,
                                  float* __restrict__ mu, float* __restrict__ rs)
{
    const size_t n = (size_t)GC * TT;
    const uint4* x8 = (const uint4*)(x + (size_t)blockIdx.x * n);
    const int n8 = (int)(n >> 3);
    float s = 0.f, sq = 0.f;
    for (int i = threadIdx.x; i < n8; i += 256) {
        uint4 v = x8[i];
        const __half2* hh = (const __half2*)&v;
        #pragma unroll
        for (int j = 0; j < 4; j++) {
            float2 f = __half22float2(hh[j]);
            s += f.x + f.y;
            sq += f.x*f.x + f.y*f.y;
        }
    }
    __shared__ float sh1[8], sh2[8];
    int lane = threadIdx.x & 31, w = threadIdx.x >> 5;
    #pragma unroll
    for (int o = 16; o > 0; o >>= 1) {
        s += __shfl_xor_sync(0xffffffffu, s, o);
        sq += __shfl_xor_sync(0xffffffffu, sq, o);
    }
    if (lane == 0) { sh1[w] = s; sh2[w] = sq; }
    __syncthreads();
    if (threadIdx.x < 8) {
        s = sh1[threadIdx.x]; sq = sh2[threadIdx.x];
        #pragma unroll
        for (int o = 4; o > 0; o >>= 1) {
            s += __shfl_xor_sync(0xffu, s, o);
            sq += __shfl_xor_sync(0xffu, sq, o);
        }
        if (threadIdx.x == 0) {
            float inv_n = 1.f / (float)n;
            float m = s * inv_n;
            float var = sq * inv_n - m * m;
            mu[blockIdx.x] = m;
            rs[blockIdx.x] = rsqrtf(fmaxf(var, 0.f) + EPSV);
        }
    }
}

// ==================== attention: tensor-core online-softmax ctx ====================
__global__ void ctx_kernel(const __half* __restrict__ kv, size_t strideB, int koff, int voff,
                           float* __restrict__ cpart,
                           float* __restrict__ cmax, float* __restrict__ csum)
{
    int bh = blockIdx.x;
    int slice = blockIdx.y;
    int b = bh / NH, h = bh % NH;
    __shared__ __half ksh[32][72];
    __shared__ __half vsh[32][72];
    __shared__ float scale_s[32];
    const int tid = threadIdx.x, lane = tid & 31, wid = tid >> 5;
    const int d = tid >> 3, j = tid & 7;
    const int mt = wid >> 2, nt = wid & 3;
    const __half* kp = kv + (size_t)b*strideB + (size_t)(koff + h*32 + d)*TT + slice*CT + j*8;
    const __half* vp = kv + (size_t)b*strideB + (size_t)(voff + h*32 + d)*TT + slice*CT + j*8;

    const unsigned ksb = s2u(ksh), vsb = s2u(vsh);
    const unsigned aaddr = ksb + (mt*16 + (lane & 15)) * 144 + (lane >> 4) * 16;
    const unsigned baddr = vsb + (nt*8 + (lane & 7)) * 144 + ((lane >> 3) & 1) * 16;

    float mold = -1e30f, ssum = 0.f;
    float c[4] = {0.f, 0.f, 0.f, 0.f};

    uint4 kr = *(const uint4*)kp;
    uint4 vr = *(const uint4*)vp;

    for (int tc = 0; tc < CT; tc += 64) {
        float kf[8];
        float lmax = -1e30f;
        const __half2* kh = (const __half2*)&kr;
        #pragma unroll
        for (int q = 0; q < 4; q++) {
            float2 f = __half22float2(kh[q]);
            kf[2*q] = f.x; kf[2*q+1] = f.y;
            lmax = fmaxf(lmax, fmaxf(f.x, f.y));
        }
        #pragma unroll
        for (int o = 4; o > 0; o >>= 1)
            lmax = fmaxf(lmax, __shfl_xor_sync(0xffffffffu, lmax, o, 8));
        float mnew = fmaxf(mold, lmax);
        float scale = expf(mold - mnew);
        mold = mnew;
        __half eh[8];
        float psum = 0.f;
        #pragma unroll
        for (int q = 0; q < 8; q++) {
            float e = expf(kf[q] - mnew);
            eh[q] = __float2half(e);
            psum += e;
        }
        #pragma unroll
        for (int o = 4; o > 0; o >>= 1)
            psum += __shfl_xor_sync(0xffffffffu, psum, o, 8);
        ssum = ssum * scale + psum;

        __syncthreads();
        *(uint4*)&ksh[d][j*8] = *(uint4*)eh;
        *(uint4*)&vsh[d][j*8] = vr;
        if (j == 0) scale_s[d] = scale;
        __syncthreads();

        if (tc + 64 < CT) {
            kr = *(const uint4*)(kp + tc + 64);
            vr = *(const uint4*)(vp + tc + 64);
        }

        float s0 = scale_s[mt*16 + (lane >> 2)];
        float s1 = scale_s[mt*16 + (lane >> 2) + 8];
        c[0] *= s0; c[1] *= s0; c[2] *= s1; c[3] *= s1;
        #pragma unroll
        for (int ks = 0; ks < 4; ks++) {
            unsigned a[4], bfr[2];
            LDSM4(a, aaddr + ks * 32);
            LDSM2(bfr, baddr + ks * 32);
            mma_f16(c, a, bfr);
        }
    }

    int row0 = mt*16 + (lane >> 2);
    int col = nt*8 + (lane & 3) * 2;
    float* cp = cpart + (size_t)slice*65536 + (size_t)bh*1024;
    cp[row0*32 + col]       = c[0];
    cp[row0*32 + col + 1]   = c[1];
    cp[(row0+8)*32 + col]   = c[2];
    cp[(row0+8)*32 + col+1] = c[3];
    if (j == 0) {
        cmax[slice*2048 + bh*32 + d] = mold;
        csum[slice*2048 + bh*32 + d] = ssum;
    }
}

__global__ void ctx_reduce_kernel(const float* __restrict__ cpart,
                                  const float* __restrict__ cmax,
                                  const float* __restrict__ csum,
                                  float* __restrict__ ctx)
{
    int i = blockIdx.x * 256 + threadIdx.x;
    int bh = i >> 10, d = (i & 1023) >> 5;
    float M = -1e30f;
    #pragma unroll
    for (int sl = 0; sl < CSL; sl++) M = fmaxf(M, cmax[sl*2048 + bh*32 + d]);
    float tot = 0.f, v = 0.f;
    #pragma unroll
    for (int sl = 0; sl < CSL; sl++) {
        float w = expf(cmax[sl*2048 + bh*32 + d] - M);
        tot += csum[sl*2048 + bh*32 + d] * w;
        v   += cpart[(size_t)sl*65536 + i] * w;
    }
    ctx[i] = v / tot;
}

__global__ void attn_out_kernel(const __half* __restrict__ q, size_t strideB, int qoff,
                                const float* __restrict__ ctx,
                                __half* __restrict__ o, size_t oStrideB)
{
    int bh = blockIdx.x;
    int b = bh / NH, h = bh % NH;
    int t = blockIdx.y * 256 + threadIdx.x;
    __shared__ float cs[32][32];
    for (int i = threadIdx.x; i < 1024; i += 256)
        cs[i >> 5][i & 31] = ctx[(size_t)bh*1024 + i];
    __syncthreads();
    const __half* qp = q + (size_t)b*strideB + (size_t)(qoff + h*32)*TT + t;
    float p[32];
    float mx = -1e30f;
    #pragma unroll
    for (int d = 0; d < 32; d++) { p[d] = __half2float(qp[(size_t)d*TT]); mx = fmaxf(mx, p[d]); }
    float s = 0.f;
    #pragma unroll
    for (int d = 0; d < 32; d++) { p[d] = expf(p[d] - mx); s += p[d]; }
    float inv = 0.17677669529663687f / s;
    #pragma unroll
    for (int d = 0; d < 32; d++) p[d] *= inv;
    float accv[32];
    #pragma unroll
    for (int e = 0; e < 32; e++) accv[e] = 0.f;
    #pragma unroll
    for (int d = 0; d < 32; d++) {
        float pd = p[d];
        #pragma unroll
        for (int e4 = 0; e4 < 8; e4++) {
            float4 cv = *(const float4*)&cs[d][e4*4];
            accv[e4*4+0] += cv.x * pd;
            accv[e4*4+1] += cv.y * pd;
            accv[e4*4+2] += cv.z * pd;
            accv[e4*4+3] += cv.w * pd;
        }
    }
    __half* op = o + (size_t)b*oStrideB + (size_t)(h*32)*TT + t;
    #pragma unroll
    for (int e = 0; e < 32; e++) op[(size_t)e*TT] = __float2half(accv[e]);
}

__global__ void gn_add_kernel(const __half* __restrict__ v,
                              const float* __restrict__ gamma, const float* __restrict__ beta,
                              const float* __restrict__ mu, const float* __restrict__ rs,
                              const float* __restrict__ r, float* __restrict__ y,
                              __half* __restrict__ yh, float2* __restrict__ part)
{
    size_t i = ((size_t)blockIdx.x * 256 + threadIdx.x) * 4;
    int c = (int)((i / TT) % DIMC);
    int b = (int)(i / ((size_t)DIMC * TT));
    int grp = c >> 3;
    float rr = rs[b*32 + grp], m = mu[b*32 + grp];
    float sc = gamma[c] * rr;
    float sh = beta[c] - m * sc;
    uint2 hv = *(const uint2*)(v + i);
    float2 f0 = __half22float2(((const __half2*)&hv)[0]);
    float2 f1 = __half22float2(((const __half2*)&hv)[1]);
    float4 rv = *(const float4*)(r + i);
    float4 o;
    o.x = f0.x * sc + sh + rv.x;
    o.y = f0.y * sc + sh + rv.y;
    o.z = f1.x * sc + sh + rv.z;
    o.w = f1.y * sc + sh + rv.w;
    *(float4*)(y + i) = o;
    __half h[4] = {__float2half(o.x), __float2half(o.y), __float2half(o.z), __float2half(o.w)};
    *(uint2*)(yh + i) = *(uint2*)h;

    float s  = (o.x + o.y) + (o.z + o.w);
    float sq = o.x*o.x + o.y*o.y + o.z*o.z + o.w*o.w;
    __shared__ float sh1[8], sh2[8];
    int lane = threadIdx.x & 31, w = threadIdx.x >> 5;
    #pragma unroll
    for (int o2 = 16; o2 > 0; o2 >>= 1) {
        s  += __shfl_xor_sync(0xffffffffu, s,  o2);
        sq += __shfl_xor_sync(0xffffffffu, sq, o2);
    }
    if (lane == 0) { sh1[w] = s; sh2[w] = sq; }
    __syncthreads();
    if (threadIdx.x < 8) {
        s = sh1[threadIdx.x]; sq = sh2[threadIdx.x];
        #pragma unroll
        for (int o2 = 4; o2 > 0; o2 >>= 1) {
            s  += __shfl_xor_sync(0xffu, s,  o2);
            sq += __shfl_xor_sync(0xffu, sq, o2);
        }
        if (threadIdx.x == 0) part[blockIdx.x] = make_float2(s, sq);
    }
}

__global__ void gn_reduce_kernel(const float2* __restrict__ part,
                                 float* __restrict__ mu, float* __restrict__ rs)
{
    int g = blockIdx.x;
    int t = threadIdx.x;
    float2 p = part[g * 64 + t];
    float s = p.x, sq = p.y;
    #pragma unroll
    for (int o = 16; o > 0; o >>= 1) {
        s  += __shfl_xor_sync(0xffffffffu, s,  o);
        sq += __shfl_xor_sync(0xffffffffu, sq, o);
    }
    __shared__ float a[2], bsh[2];
    if ((t & 31) == 0) { a[t >> 5] = s; bsh[t >> 5] = sq; }
    __syncthreads();
    if (t == 0) {
        s = a[0] + a[1]; sq = bsh[0] + bsh[1];
        const float inv_n = 1.f / 65536.f;
        float m = s * inv_n;
        float var = sq * inv_n - m * m;
        mu[g] = m;
        rs[g] = rsqrtf(fmaxf(var, 0.f) + EPSV);
    }
}

// ==================== host orchestration ====================
extern "C" void kernel_launch(void* const* d_in, const int* in_sizes, int n_in,
                              void* d_out, int out_size)
{
    const float* x     = (const float*)d_in[0];
    const float* c     = (const float*)d_in[1];
    const float* W_qkv = (const float*)d_in[2];
    const float* W_so  = (const float*)d_in[3];
    const float* b_so  = (const float*)d_in[4];
    const float* sa_g  = (const float*)d_in[5];
    const float* sa_b  = (const float*)d_in[6];
    const float* W_cq  = (const float*)d_in[7];
    const float* W_ckv = (const float*)d_in[8];
    const float* W_co  = (const float*)d_in[9];
    const float* b_co  = (const float*)d_in[10];
    const float* ca_g  = (const float*)d_in[11];
    const float* ca_b  = (const float*)d_in[12];
    const float* W_m1  = (const float*)d_in[13];
    const float* b_m1  = (const float*)d_in[14];
    const float* W_m2  = (const float*)d_in[15];
    const float* b_m2  = (const float*)d_in[16];
    const float* nm_g  = (const float*)d_in[17];
    const float* nm_b  = (const float*)d_in[18];
    const float* nm1_g = (const float*)d_in[19];
    const float* nm1_b = (const float*)d_in[20];
    const float* nm2_g = (const float*)d_in[21];
    const float* nm2_b = (const float*)d_in[22];
    const float* nm3_g = (const float*)d_in[23];
    const float* nm3_b = (const float*)d_in[24];
    float* out = (float*)d_out;

    float *xb, *beff, *mu, *rs, *ctx, *ctxp, *cmax, *csum;
    float2* part;
    __half *w16, *h1, *h2, *bigh;
    cudaGetSymbolAddress((void**)&xb,   g_x);
    cudaGetSymbolAddress((void**)&beff, g_beff);
    cudaGetSymbolAddress((void**)&mu,   g_mu);
    cudaGetSymbolAddress((void**)&rs,   g_rs);
    cudaGetSymbolAddress((void**)&ctx,  g_ctx);
    cudaGetSymbolAddress((void**)&ctxp, g_ctxp);
    cudaGetSymbolAddress((void**)&cmax, g_cmax);
    cudaGetSymbolAddress((void**)&csum, g_csum);
    cudaGetSymbolAddress((void**)&part, g_part);
    cudaGetSymbolAddress((void**)&w16,  g_w16);
    cudaGetSymbolAddress((void**)&h1,   g_h1);
    cudaGetSymbolAddress((void**)&h2,   g_h2);
    cudaGetSymbolAddress((void**)&bigh, g_bigh);

    static bool attr_set = false;
    if (!attr_set) {
        cudaFuncSetAttribute(mm_kernel, cudaFuncAttributeMaxDynamicSharedMemorySize, SMEM_MM);
        attr_set = true;
    }

    const size_t XT = (size_t)DIMC * TT;

    // ================= Phase 1: self linear attention =================
    gn_stats_conv_kernel<<<BQ*32, 256>>>(x, h1, 8, mu, rs);
    wprep_kernel<<<dim3(24, BQ), 256>>>(W_qkv, nm_g, nm_b, mu, rs, nullptr, w16, beff, 768, 256);
    mm_kernel<<<dim3(6, 64, BQ), 256, SMEM_MM>>>(w16, (size_t)768*256, beff, 1,
                                                 h1, XT, nullptr, bigh, (size_t)768*TT,
                                                 nullptr, 0, 768, 256, 0);
    ctx_kernel<<<dim3(64, CSL), 256>>>(bigh, (size_t)768*TT, 256, 512, ctxp, cmax, csum);
    ctx_reduce_kernel<<<256, 256>>>(ctxp, cmax, csum, ctx);
    attn_out_kernel<<<dim3(64, 32), 256>>>(bigh, (size_t)768*TT, 0, ctx, h1, XT);
    wprep_kernel<<<dim3(8, 1), 256>>>(W_so, nullptr, nullptr, nullptr, nullptr, b_so,
                                      w16, beff, 256, 256);
    mm_kernel<<<dim3(2, 64, BQ), 256, SMEM_MM>>>(w16, 0, beff, 0,
                                                 h1, XT, nullptr, bigh, XT,
                                                 nullptr, 0, 256, 256, 0);
    gn_stats_h_kernel<<<BQ*32, 256>>>(bigh, 8, mu, rs);
    gn_add_kernel<<<16384, 256>>>(bigh, sa_g, sa_b, mu, rs, x, xb, h1, part);
    gn_reduce_kernel<<<256, 64>>>(part, mu, rs);

    // ================= Phase 2: cross linear attention =================
    wprep_kernel<<<dim3(8, BQ), 256>>>(W_cq, nm1_g, nm1_b, mu, rs, nullptr, w16, beff, 256, 256);
    mm_kernel<<<dim3(2, 64, BQ), 256, SMEM_MM>>>(w16, (size_t)256*256, beff, 1,
                                                 h1, XT, nullptr, h2, XT,
                                                 nullptr, 0, 256, 256, 0);
    gn_stats_conv_kernel<<<BQ*32, 256>>>(c, h1, 16, mu, rs);
    wprep_kernel<<<dim3(16, BQ), 256>>>(W_ckv, nm3_g, nm3_b, mu, rs, nullptr, w16, beff, 512, 512);
    mm_kernel<<<dim3(4, 64, BQ), 256, SMEM_MM>>>(w16, (size_t)512*512, beff, 1,
                                                 h1, (size_t)512*TT, nullptr, bigh, (size_t)512*TT,
                                                 nullptr, 0, 512, 512, 0);
    ctx_kernel<<<dim3(64, CSL), 256>>>(bigh, (size_t)512*TT, 0, 256, ctxp, cmax, csum);
    ctx_reduce_kernel<<<256, 256>>>(ctxp, cmax, csum, ctx);
    attn_out_kernel<<<dim3(64, 32), 256>>>(h2, XT, 0, ctx, h1, XT);
    wprep_kernel<<<dim3(8, 1), 256>>>(W_co, nullptr, nullptr, nullptr, nullptr, b_co,
                                      w16, beff, 256, 256);
    mm_kernel<<<dim3(2, 64, BQ), 256, SMEM_MM>>>(w16, 0, beff, 0,
                                                 h1, XT, nullptr, bigh, XT,
                                                 nullptr, 0, 256, 256, 0);
    gn_stats_h_kernel<<<BQ*32, 256>>>(bigh, 8, mu, rs);
    gn_add_kernel<<<16384, 256>>>(bigh, ca_g, ca_b, mu, rs, xb, xb, h1, part);
    gn_reduce_kernel<<<256, 64>>>(part, mu, rs);

    // ================= Phase 3: SiLU MLP =================
    wprep_kernel<<<dim3(20, BQ), 256>>>(W_m1, nm2_g, nm2_b, mu, rs, b_m1, w16, beff, 640, 256);
    mm_kernel<<<dim3(5, 64, BQ), 256, SMEM_MM>>>(w16, (size_t)640*256, beff, 1,
                                                 h1, XT, nullptr, h2, (size_t)640*TT,
                                                 nullptr, 0, 640, 256, 1 /*silu, fp16 out*/);
    wprep_kernel<<<dim3(8, 1), 256>>>(W_m2, nullptr, nullptr, nullptr, nullptr, b_m2,
                                      w16, beff, 256, 640);
    mm_kernel<<<dim3(2, 64, BQ), 256, SMEM_MM>>>(w16, 0, beff, 0,
                                                 h2, (size_t)640*TT, out, nullptr, XT,
                                                 xb, XT, 256, 640, 2 /*residual*/);
}

// round 17
// speedup vs baseline: 4.0983x; 1.0025x over previous
#include <cuda_runtime.h>
#include <cuda_fp16.h>
#include <cstdint>

#define BQ 8
#define DIMC 256
#define TT 8192
#define NH 8
#define EPSV 1e-5f
#define CSL 16          // ctx slices
#define CT  512         // t per slice

// fp16 stage, BK=64: A[128 rows x 64k, pad 72h]=18432B, B[64k x 128n, pad 136h]=17408B
#define A_BYTES   18432
#define STG_BYTES 35840
#define NSTG      3
#define SMEM_MM   (NSTG * STG_BYTES)

// ---------------- scratch (device globals) ----------------
__device__ float g_beff[BQ * 1024];
__device__ float g_mu  [BQ * 32];
__device__ float g_rs  [BQ * 32];
__device__ float g_ctx [BQ * NH * 32 * 32];
__device__ float g_ctxp[(size_t)CSL * BQ * NH * 32 * 32];
__device__ float g_cmax[CSL * BQ * NH * 32];
__device__ float g_csum[CSL * BQ * NH * 32];
__device__ float2 g_part[16384];
// fp16 planes
__device__ __align__(256) __half g_xh  [(size_t)BQ * DIMC * TT];     // xb residual (fp16)
__device__ __align__(256) __half g_w16 [(size_t)BQ * 512 * 512];     // folded weights
__device__ __align__(256) __half g_h1  [(size_t)BQ * 512 * TT];      // activation plane (reused)
__device__ __align__(256) __half g_h2  [(size_t)BQ * 640 * TT];      // cq out / m1 out
__device__ __align__(256) __half g_bigh[(size_t)BQ * 768 * TT];      // qkv/ckv out; later so plane

// ==================== PTX helpers (plain sm_80+ only) ====================
__device__ __forceinline__ unsigned s2u(const void* p) {
    unsigned a;
    asm("{ .reg .u64 t; cvta.to.shared.u64 t, %1; cvt.u32.u64 %0, t; }" : "=r"(a) : "l"(p));
    return a;
}
#define LDSM4(r, addr) \
    asm volatile("ldmatrix.sync.aligned.m8n8.x4.shared.b16 {%0,%1,%2,%3}, [%4];" \
        : "=r"((r)[0]), "=r"((r)[1]), "=r"((r)[2]), "=r"((r)[3]) : "r"(addr))
#define LDSM2(r, addr) \
    asm volatile("ldmatrix.sync.aligned.m8n8.x2.shared.b16 {%0,%1}, [%2];" \
        : "=r"((r)[0]), "=r"((r)[1]) : "r"(addr))
#define LDSM4T(r, addr) \
    asm volatile("ldmatrix.sync.aligned.m8n8.x4.trans.shared.b16 {%0,%1,%2,%3}, [%4];" \
        : "=r"((r)[0]), "=r"((r)[1]), "=r"((r)[2]), "=r"((r)[3]) : "r"(addr))
__device__ __forceinline__ void mma_f16(float* c, const unsigned* a, const unsigned* b) {
    asm volatile("mma.sync.aligned.m16n8k16.row.col.f32.f16.f16.f32 "
        "{%0,%1,%2,%3}, {%4,%5,%6,%7}, {%8,%9}, {%0,%1,%2,%3};"
        : "+f"(c[0]), "+f"(c[1]), "+f"(c[2]), "+f"(c[3])
        : "r"(a[0]), "r"(a[1]), "r"(a[2]), "r"(a[3]), "r"(b[0]), "r"(b[1]));
}
__device__ __forceinline__ void cp16(unsigned saddr, const void* gaddr) {
    asm volatile("cp.async.cg.shared.global [%0], [%1], 16;" :: "r"(saddr), "l"(gaddr));
}
__device__ __forceinline__ void cp_commit() {
    asm volatile("cp.async.commit_group;");
}
template <int N>
__device__ __forceinline__ void cp_wait() {
    asm volatile("cp.async.wait_group %0;" :: "n"(N));
}

// ==================== tensor-core GEMM (fp16, BK=64, single sync/chunk) ====================
// sp != null (ep==0): also emit per-(group,ntile) groupnorm partials of the output.
__global__ __launch_bounds__(256, 2)
void mm_kernel(const __half* __restrict__ A16, size_t aStrB,
               const float* __restrict__ bias, int perB,
               const __half* __restrict__ B16, size_t bStrB,
               float* __restrict__ Y, __half* __restrict__ Yh, size_t yStrB,
               const __half* __restrict__ R16, size_t rStrB,
               float2* __restrict__ sp,
               int M, int K, int ep)
{
    extern __shared__ char smem[];
    const unsigned sb = s2u(smem);
    const int tid = threadIdx.x, lane = tid & 31, wid = tid >> 5;
    const int wr = wid >> 2, wc = wid & 3;
    const int mt = blockIdx.x, nt = blockIdx.y, b = blockIdx.z;
    const int m0 = mt * 128, n0 = nt * 128;
    const __half* Ab = A16 + (size_t)b * aStrB;
    const __half* Bb = B16 + (size_t)b * bStrB;

    float acc[4][4][4];
    #pragma unroll
    for (int i = 0; i < 4; i++)
        #pragma unroll
        for (int j = 0; j < 4; j++)
            #pragma unroll
            for (int r = 0; r < 4; r++) acc[i][j][r] = 0.f;

    const unsigned aoff = (lane & 15) * 144 + (lane >> 4) * 16;
    const unsigned boff = (lane & 15) * 272 + (lane >> 4) * 16;
    const int nk = K >> 6;                    // BK = 64

    auto cpChunk = [&](int kc, int st) {
        unsigned base = sb + st * STG_BYTES;
        #pragma unroll
        for (int u = 0; u < 4; u++) {          // A: 1024 cp16
            int f = tid + u * 256;
            int row = f >> 3, c16 = f & 7;
            cp16(base + row * 144 + c16 * 16,
                 Ab + (size_t)(m0 + row) * K + kc * 64 + c16 * 8);
        }
        #pragma unroll
        for (int u = 0; u < 4; u++) {          // B: 1024 cp16
            int f = tid + u * 256;
            int r = f >> 4, c16 = f & 15;
            cp16(base + A_BYTES + r * 272 + c16 * 16,
                 Bb + (size_t)(kc * 64 + r) * TT + n0 + c16 * 8);
        }
        cp_commit();
    };

    auto compute = [&](int st) {
        unsigned stb = sb + st * STG_BYTES;
        #pragma unroll
        for (int ks = 0; ks < 4; ks++) {
            unsigned bh[2][4];
            #pragma unroll
            for (int np = 0; np < 2; np++)
                LDSM4T(bh[np], stb + A_BYTES + ks * 4352 + wc * 64 + np * 32 + boff);
            #pragma unroll
            for (int mf = 0; mf < 4; mf++) {
                unsigned ah[4];
                LDSM4(ah, stb + wr * 9216 + mf * 2304 + ks * 32 + aoff);
                #pragma unroll
                for (int nf = 0; nf < 4; nf++)
                    mma_f16(acc[mf][nf], ah, &bh[nf >> 1][(nf & 1) * 2]);
            }
        }
    };

    cpChunk(0, 0);
    cpChunk(1, 1);
    for (int i = 0; i < nk; i++) {
        if (i + 1 < nk) cp_wait<1>(); else cp_wait<0>();
        __syncthreads();
        compute(i % NSTG);
        int nx = i + 2;
        if (nx < nk) cpChunk(nx, nx % NSTG);
    }

    float ls[4][2], lq[4][2];
    if (sp) {
        #pragma unroll
        for (int mf = 0; mf < 4; mf++) { ls[mf][0]=ls[mf][1]=lq[mf][0]=lq[mf][1]=0.f; }
    }

    const float* biasB = bias + (perB ? (size_t)b * M : 0);
    #pragma unroll
    for (int mf = 0; mf < 4; mf++) {
        int gm = m0 + wr * 64 + mf * 16 + (lane >> 2);
        float bv0 = biasB[gm], bv1 = biasB[gm + 8];
        #pragma unroll
        for (int nf = 0; nf < 4; nf++) {
            int gn = n0 + wc * 32 + nf * 8 + (lane & 3) * 2;
            float* a4 = acc[mf][nf];
            float2 v0 = make_float2(a4[0] + bv0, a4[1] + bv0);
            float2 v1 = make_float2(a4[2] + bv1, a4[3] + bv1);
            if (ep == 1) {
                v0.x /= (1.f + expf(-v0.x)); v0.y /= (1.f + expf(-v0.y));
                v1.x /= (1.f + expf(-v1.x)); v1.y /= (1.f + expf(-v1.y));
            } else if (ep == 2) {
                const __half* Rb = R16 + (size_t)b * rStrB;
                float2 r0 = __half22float2(*(const __half2*)&Rb[(size_t)gm * TT + gn]);
                float2 r1 = __half22float2(*(const __half2*)&Rb[(size_t)(gm + 8) * TT + gn]);
                v0.x += r0.x; v0.y += r0.y; v1.x += r1.x; v1.y += r1.y;
            }
            if (sp) {
                ls[mf][0] += v0.x + v0.y; lq[mf][0] += v0.x*v0.x + v0.y*v0.y;
                ls[mf][1] += v1.x + v1.y; lq[mf][1] += v1.x*v1.x + v1.y*v1.y;
            }
            if (Yh) {
                __half* Yb = Yh + (size_t)b * yStrB;
                *(__half2*)&Yb[(size_t)gm * TT + gn] =
                    __halves2half2(__float2half(v0.x), __float2half(v0.y));
                *(__half2*)&Yb[(size_t)(gm + 8) * TT + gn] =
                    __halves2half2(__float2half(v1.x), __float2half(v1.y));
            } else {
                float* Yb = Y + (size_t)b * yStrB;
                *(float2*)&Yb[(size_t)gm * TT + gn] = v0;
                *(float2*)&Yb[(size_t)(gm + 8) * TT + gn] = v1;
            }
        }
    }

    if (sp) {
        float* sred = (float*)smem;     // 16 groups x 4 wc x (sum,sq) = 128 floats
        __syncthreads();                // all stage reads done before reuse
        #pragma unroll
        for (int mf = 0; mf < 4; mf++) {
            #pragma unroll
            for (int hf = 0; hf < 2; hf++) {
                float s = ls[mf][hf], q = lq[mf][hf];
                #pragma unroll
                for (int o = 16; o > 0; o >>= 1) {
                    s += __shfl_xor_sync(0xffffffffu, s, o);
                    q += __shfl_xor_sync(0xffffffffu, q, o);
                }
                if (lane == 0) {
                    int gl = wr * 8 + mf * 2 + hf;
                    sred[(gl * 4 + wc) * 2 + 0] = s;
                    sred[(gl * 4 + wc) * 2 + 1] = q;
                }
            }
        }
        __syncthreads();
        if (tid < 16) {
            float s = 0.f, q = 0.f;
            #pragma unroll
            for (int w = 0; w < 4; w++) {
                s += sred[(tid * 4 + w) * 2 + 0];
                q += sred[(tid * 4 + w) * 2 + 1];
            }
            sp[((size_t)b * 32 + mt * 16 + tid) * 64 + nt] = make_float2(s, q);
        }
    }
}

// ==================== wprep: fused affine + weight fold + beff ====================
__global__ void wprep_kernel(const float* __restrict__ W,
                             const float* __restrict__ g, const float* __restrict__ be,
                             const float* __restrict__ mu, const float* __restrict__ rs,
                             const float* __restrict__ bias,
                             __half* __restrict__ w16, float* __restrict__ beff,
                             int M, int K)
{
    __shared__ float a_s[640], bb_s[640];
    const int b = blockIdx.y;
    const int GC = K >> 5;
    for (int c = threadIdx.x; c < K; c += 256) {
        if (g) {
            int grp = c / GC;
            float r = rs[b*32 + grp], m = mu[b*32 + grp];
            float av = g[c] * r;
            a_s[c] = av;
            bb_s[c] = be[c] - m * av;
        } else { a_s[c] = 1.f; bb_s[c] = 0.f; }
    }
    __syncthreads();
    const int m = blockIdx.x * 32 + (threadIdx.x >> 3);
    const int l8 = threadIdx.x & 7;
    const float* Wr = W + (size_t)m * K;
    __half* dst = w16 + (size_t)b * M * K + (size_t)m * K;
    float dot = 0.f;
    for (int k0 = l8 * 4; k0 < K; k0 += 32) {
        float4 w = *(const float4*)(Wr + k0);
        dot += w.x*bb_s[k0] + w.y*bb_s[k0+1] + w.z*bb_s[k0+2] + w.w*bb_s[k0+3];
        __half h[4] = {__float2half(w.x * a_s[k0]),   __float2half(w.y * a_s[k0+1]),
                       __float2half(w.z * a_s[k0+2]), __float2half(w.w * a_s[k0+3])};
        *(uint2*)(dst + k0) = *(uint2*)h;
    }
    dot += __shfl_down_sync(0xffffffffu, dot, 4, 8);
    dot += __shfl_down_sync(0xffffffffu, dot, 2, 8);
    dot += __shfl_down_sync(0xffffffffu, dot, 1, 8);
    if (l8 == 0)
        beff[(size_t)b * M + m] = dot + (bias ? bias[m] : 0.f);
}

// ==================== group-norm stats (fp32 input + fp16 convert) ====================
__global__ void gn_stats_conv_kernel(const float* __restrict__ x, __half* __restrict__ xh,
                                     int GC, float* __restrict__ mu, float* __restrict__ rs)
{
    const size_t n = (size_t)GC * TT;
    const size_t base = (size_t)blockIdx.x * n;
    const float4* x4 = (const float4*)(x + base);
    const int n4 = (int)(n >> 2);
    float s = 0.f, sq = 0.f;
    for (int i = threadIdx.x; i < n4; i += 256) {
        float4 v = x4[i];
        s += (v.x + v.y) + (v.z + v.w);
        sq += v.x*v.x + v.y*v.y + v.z*v.z + v.w*v.w;
        __half h[4] = {__float2half(v.x), __float2half(v.y),
                       __float2half(v.z), __float2half(v.w)};
        *(uint2*)(xh + base + (size_t)i * 4) = *(uint2*)h;
    }
    __shared__ float sh1[8], sh2[8];
    int lane = threadIdx.x & 31, w = threadIdx.x >> 5;
    #pragma unroll
    for (int o = 16; o > 0; o >>= 1) {
        s += __shfl_xor_sync(0xffffffffu, s, o);
        sq += __shfl_xor_sync(0xffffffffu, sq, o);
    }
    if (lane == 0) { sh1[w] = s; sh2[w] = sq; }
    __syncthreads();
    if (threadIdx.x < 8) {
        s = sh1[threadIdx.x]; sq = sh2[threadIdx.x];
        #pragma unroll
        for (int o = 4; o > 0; o >>= 1) {
            s += __shfl_xor_sync(0xffu, s, o);
            sq += __shfl_xor_sync(0xffu, sq, o);
        }
        if (threadIdx.x == 0) {
            float inv_n = 1.f / (float)n;
            float m = s * inv_n;
            float var = sq * inv_n - m * m;
            mu[blockIdx.x] = m;
            rs[blockIdx.x] = rsqrtf(fmaxf(var, 0.f) + EPSV);
        }
    }
}

// ==================== attention: tensor-core online-softmax ctx ====================
__global__ void ctx_kernel(const __half* __restrict__ kv, size_t strideB, int koff, int voff,
                           float* __restrict__ cpart,
                           float* __restrict__ cmax, float* __restrict__ csum)
{
    int bh = blockIdx.x;
    int slice = blockIdx.y;
    int b = bh / NH, h = bh % NH;
    __shared__ __half ksh[32][72];
    __shared__ __half vsh[32][72];
    __shared__ float scale_s[32];
    const int tid = threadIdx.x, lane = tid & 31, wid = tid >> 5;
    const int d = tid >> 3, j = tid & 7;
    const int mt = wid >> 2, nt = wid & 3;
    const __half* kp = kv + (size_t)b*strideB + (size_t)(koff + h*32 + d)*TT + slice*CT + j*8;
    const __half* vp = kv + (size_t)b*strideB + (size_t)(voff + h*32 + d)*TT + slice*CT + j*8;

    const unsigned ksb = s2u(ksh), vsb = s2u(vsh);
    const unsigned aaddr = ksb + (mt*16 + (lane & 15)) * 144 + (lane >> 4) * 16;
    const unsigned baddr = vsb + (nt*8 + (lane & 7)) * 144 + ((lane >> 3) & 1) * 16;

    float mold = -1e30f, ssum = 0.f;
    float c[4] = {0.f, 0.f, 0.f, 0.f};

    uint4 kr = *(const uint4*)kp;
    uint4 vr = *(const uint4*)vp;

    for (int tc = 0; tc < CT; tc += 64) {
        float kf[8];
        float lmax = -1e30f;
        const __half2* kh = (const __half2*)&kr;
        #pragma unroll
        for (int q = 0; q < 4; q++) {
            float2 f = __half22float2(kh[q]);
            kf[2*q] = f.x; kf[2*q+1] = f.y;
            lmax = fmaxf(lmax, fmaxf(f.x, f.y));
        }
        #pragma unroll
        for (int o = 4; o > 0; o >>= 1)
            lmax = fmaxf(lmax, __shfl_xor_sync(0xffffffffu, lmax, o, 8));
        float mnew = fmaxf(mold, lmax);
        float scale = expf(mold - mnew);
        mold = mnew;
        __half eh[8];
        float psum = 0.f;
        #pragma unroll
        for (int q = 0; q < 8; q++) {
            float e = expf(kf[q] - mnew);
            eh[q] = __float2half(e);
            psum += e;
        }
        #pragma unroll
        for (int o = 4; o > 0; o >>= 1)
            psum += __shfl_xor_sync(0xffffffffu, psum, o, 8);
        ssum = ssum * scale + psum;

        __syncthreads();
        *(uint4*)&ksh[d][j*8] = *(uint4*)eh;
        *(uint4*)&vsh[d][j*8] = vr;
        if (j == 0) scale_s[d] = scale;
        __syncthreads();

        if (tc + 64 < CT) {
            kr = *(const uint4*)(kp + tc + 64);
            vr = *(const uint4*)(vp + tc + 64);
        }

        float s0 = scale_s[mt*16 + (lane >> 2)];
        float s1 = scale_s[mt*16 + (lane >> 2) + 8];
        c[0] *= s0; c[1] *= s0; c[2] *= s1; c[3] *= s1;
        #pragma unroll
        for (int ks = 0; ks < 4; ks++) {
            unsigned a[4], bfr[2];
            LDSM4(a, aaddr + ks * 32);
            LDSM2(bfr, baddr + ks * 32);
            mma_f16(c, a, bfr);
        }
    }

    int row0 = mt*16 + (lane >> 2);
    int col = nt*8 + (lane & 3) * 2;
    float* cp = cpart + (size_t)slice*65536 + (size_t)bh*1024;
    cp[row0*32 + col]       = c[0];
    cp[row0*32 + col + 1]   = c[1];
    cp[(row0+8)*32 + col]   = c[2];
    cp[(row0+8)*32 + col+1] = c[3];
    if (j == 0) {
        cmax[slice*2048 + bh*32 + d] = mold;
        csum[slice*2048 + bh*32 + d] = ssum;
    }
}

__global__ void ctx_reduce_kernel(const float* __restrict__ cpart,
                                  const float* __restrict__ cmax,
                                  const float* __restrict__ csum,
                                  float* __restrict__ ctx)
{
    int i = blockIdx.x * 256 + threadIdx.x;
    int bh = i >> 10, d = (i & 1023) >> 5;
    float M = -1e30f;
    #pragma unroll
    for (int sl = 0; sl < CSL; sl++) M = fmaxf(M, cmax[sl*2048 + bh*32 + d]);
    float tot = 0.f, v = 0.f;
    #pragma unroll
    for (int sl = 0; sl < CSL; sl++) {
        float w = expf(cmax[sl*2048 + bh*32 + d] - M);
        tot += csum[sl*2048 + bh*32 + d] * w;
        v   += cpart[(size_t)sl*65536 + i] * w;
    }
    ctx[i] = v / tot;
}

__global__ void attn_out_kernel(const __half* __restrict__ q, size_t strideB, int qoff,
                                const float* __restrict__ ctx,
                                __half* __restrict__ o, size_t oStrideB)
{
    int bh = blockIdx.x;
    int b = bh / NH, h = bh % NH;
    int t = blockIdx.y * 256 + threadIdx.x;
    __shared__ float cs[32][32];
    for (int i = threadIdx.x; i < 1024; i += 256)
        cs[i >> 5][i & 31] = ctx[(size_t)bh*1024 + i];
    __syncthreads();
    const __half* qp = q + (size_t)b*strideB + (size_t)(qoff + h*32)*TT + t;
    float p[32];
    float mx = -1e30f;
    #pragma unroll
    for (int d = 0; d < 32; d++) { p[d] = __half2float(qp[(size_t)d*TT]); mx = fmaxf(mx, p[d]); }
    float s = 0.f;
    #pragma unroll
    for (int d = 0; d < 32; d++) { p[d] = expf(p[d] - mx); s += p[d]; }
    float inv = 0.17677669529663687f / s;
    #pragma unroll
    for (int d = 0; d < 32; d++) p[d] *= inv;
    float accv[32];
    #pragma unroll
    for (int e = 0; e < 32; e++) accv[e] = 0.f;
    #pragma unroll
    for (int d = 0; d < 32; d++) {
        float pd = p[d];
        #pragma unroll
        for (int e4 = 0; e4 < 8; e4++) {
            float4 cv = *(const float4*)&cs[d][e4*4];
            accv[e4*4+0] += cv.x * pd;
            accv[e4*4+1] += cv.y * pd;
            accv[e4*4+2] += cv.z * pd;
            accv[e4*4+3] += cv.w * pd;
        }
    }
    __half* op = o + (size_t)b*oStrideB + (size_t)(h*32)*TT + t;
    #pragma unroll
    for (int e = 0; e < 32; e++) op[(size_t)e*TT] = __float2half(accv[e]);
}

// y = gn(v_fp16)*g + b + r ; r from fp32 (rf) or fp16 (rh); writes fp16 y + fp16 yh + partials
__global__ void gn_add_kernel(const __half* __restrict__ v,
                              const float* __restrict__ gamma, const float* __restrict__ beta,
                              const float* __restrict__ mu, const float* __restrict__ rs,
                              const float* __restrict__ rf, const __half* __restrict__ rh,
                              __half* __restrict__ y, __half* __restrict__ yh,
                              float2* __restrict__ part)
{
    size_t i = ((size_t)blockIdx.x * 256 + threadIdx.x) * 4;
    int c = (int)((i / TT) % DIMC);
    int b = (int)(i / ((size_t)DIMC * TT));
    int grp = c >> 3;
    float rr = rs[b*32 + grp], m = mu[b*32 + grp];
    float sc = gamma[c] * rr;
    float sh = beta[c] - m * sc;
    uint2 hv = *(const uint2*)(v + i);
    float2 f0 = __half22float2(((const __half2*)&hv)[0]);
    float2 f1 = __half22float2(((const __half2*)&hv)[1]);
    float4 rv;
    if (rf) {
        rv = *(const float4*)(rf + i);
    } else {
        uint2 rv16 = *(const uint2*)(rh + i);
        float2 r0 = __half22float2(((const __half2*)&rv16)[0]);
        float2 r1 = __half22float2(((const __half2*)&rv16)[1]);
        rv = make_float4(r0.x, r0.y, r1.x, r1.y);
    }
    float4 o;
    o.x = f0.x * sc + sh + rv.x;
    o.y = f0.y * sc + sh + rv.y;
    o.z = f1.x * sc + sh + rv.z;
    o.w = f1.y * sc + sh + rv.w;
    __half h[4] = {__float2half(o.x), __float2half(o.y), __float2half(o.z), __float2half(o.w)};
    *(uint2*)(y + i) = *(uint2*)h;
    *(uint2*)(yh + i) = *(uint2*)h;

    float s  = (o.x + o.y) + (o.z + o.w);
    float sq = o.x*o.x + o.y*o.y + o.z*o.z + o.w*o.w;
    __shared__ float sh1[8], sh2[8];
    int lane = threadIdx.x & 31, w = threadIdx.x >> 5;
    #pragma unroll
    for (int o2 = 16; o2 > 0; o2 >>= 1) {
        s  += __shfl_xor_sync(0xffffffffu, s,  o2);
        sq += __shfl_xor_sync(0xffffffffu, sq, o2);
    }
    if (lane == 0) { sh1[w] = s; sh2[w] = sq; }
    __syncthreads();
    if (threadIdx.x < 8) {
        s = sh1[threadIdx.x]; sq = sh2[threadIdx.x];
        #pragma unroll
        for (int o2 = 4; o2 > 0; o2 >>= 1) {
            s  += __shfl_xor_sync(0xffu, s,  o2);
            sq += __shfl_xor_sync(0xffu, sq, o2);
        }
        if (threadIdx.x == 0) part[blockIdx.x] = make_float2(s, sq);
    }
}

__global__ void gn_reduce_kernel(const float2* __restrict__ part,
                                 float* __restrict__ mu, float* __restrict__ rs)
{
    int g = blockIdx.x;
    int t = threadIdx.x;
    float2 p = part[g * 64 + t];
    float s = p.x, sq = p.y;
    #pragma unroll
    for (int o = 16; o > 0; o >>= 1) {
        s  += __shfl_xor_sync(0xffffffffu, s,  o);
        sq += __shfl_xor_sync(0xffffffffu, sq, o);
    }
    __shared__ float a[2], bsh[2];
    if ((t & 31) == 0) { a[t >> 5] = s; bsh[t >> 5] = sq; }
    __syncthreads();
    if (t == 0) {
        s = a[0] + a[1]; sq = bsh[0] + bsh[1];
        const float inv_n = 1.f / 65536.f;
        float m = s * inv_n;
        float var = sq * inv_n - m * m;
        mu[g] = m;
        rs[g] = rsqrtf(fmaxf(var, 0.f) + EPSV);
    }
}

// ==================== host orchestration ====================
extern "C" void kernel_launch(void* const* d_in, const int* in_sizes, int n_in,
                              void* d_out, int out_size)
{
    const float* x     = (const float*)d_in[0];
    const float* c     = (const float*)d_in[1];
    const float* W_qkv = (const float*)d_in[2];
    const float* W_so  = (const float*)d_in[3];
    const float* b_so  = (const float*)d_in[4];
    const float* sa_g  = (const float*)d_in[5];
    const float* sa_b  = (const float*)d_in[6];
    const float* W_cq  = (const float*)d_in[7];
    const float* W_ckv = (const float*)d_in[8];
    const float* W_co  = (const float*)d_in[9];
    const float* b_co  = (const float*)d_in[10];
    const float* ca_g  = (const float*)d_in[11];
    const float* ca_b  = (const float*)d_in[12];
    const float* W_m1  = (const float*)d_in[13];
    const float* b_m1  = (const float*)d_in[14];
    const float* W_m2  = (const float*)d_in[15];
    const float* b_m2  = (const float*)d_in[16];
    const float* nm_g  = (const float*)d_in[17];
    const float* nm_b  = (const float*)d_in[18];
    const float* nm1_g = (const float*)d_in[19];
    const float* nm1_b = (const float*)d_in[20];
    const float* nm2_g = (const float*)d_in[21];
    const float* nm2_b = (const float*)d_in[22];
    const float* nm3_g = (const float*)d_in[23];
    const float* nm3_b = (const float*)d_in[24];
    float* out = (float*)d_out;

    float *beff, *mu, *rs, *ctx, *ctxp, *cmax, *csum;
    float2* part;
    __half *xb, *w16, *h1, *h2, *bigh;
    cudaGetSymbolAddress((void**)&beff, g_beff);
    cudaGetSymbolAddress((void**)&mu,   g_mu);
    cudaGetSymbolAddress((void**)&rs,   g_rs);
    cudaGetSymbolAddress((void**)&ctx,  g_ctx);
    cudaGetSymbolAddress((void**)&ctxp, g_ctxp);
    cudaGetSymbolAddress((void**)&cmax, g_cmax);
    cudaGetSymbolAddress((void**)&csum, g_csum);
    cudaGetSymbolAddress((void**)&part, g_part);
    cudaGetSymbolAddress((void**)&xb,   g_xh);
    cudaGetSymbolAddress((void**)&w16,  g_w16);
    cudaGetSymbolAddress((void**)&h1,   g_h1);
    cudaGetSymbolAddress((void**)&h2,   g_h2);
    cudaGetSymbolAddress((void**)&bigh, g_bigh);

    static bool attr_set = false;
    if (!attr_set) {
        cudaFuncSetAttribute(mm_kernel, cudaFuncAttributeMaxDynamicSharedMemorySize, SMEM_MM);
        attr_set = true;
    }

    const size_t XT = (size_t)DIMC * TT;

    // ================= Phase 1: self linear attention =================
    gn_stats_conv_kernel<<<BQ*32, 256>>>(x, h1, 8, mu, rs);
    wprep_kernel<<<dim3(24, BQ), 256>>>(W_qkv, nm_g, nm_b, mu, rs, nullptr, w16, beff, 768, 256);
    mm_kernel<<<dim3(6, 64, BQ), 256, SMEM_MM>>>(w16, (size_t)768*256, beff, 1,
                                                 h1, XT, nullptr, bigh, (size_t)768*TT,
                                                 nullptr, 0, nullptr, 768, 256, 0);
    ctx_kernel<<<dim3(64, CSL), 256>>>(bigh, (size_t)768*TT, 256, 512, ctxp, cmax, csum);
    ctx_reduce_kernel<<<256, 256>>>(ctxp, cmax, csum, ctx);
    attn_out_kernel<<<dim3(64, 32), 256>>>(bigh, (size_t)768*TT, 0, ctx, h1, XT);
    wprep_kernel<<<dim3(8, 1), 256>>>(W_so, nullptr, nullptr, nullptr, nullptr, b_so,
                                      w16, beff, 256, 256);
    mm_kernel<<<dim3(2, 64, BQ), 256, SMEM_MM>>>(w16, 0, beff, 0,
                                                 h1, XT, nullptr, bigh, XT,
                                                 nullptr, 0, part, 256, 256, 0);
    gn_reduce_kernel<<<256, 64>>>(part, mu, rs);                          // so stats
    gn_add_kernel<<<16384, 256>>>(bigh, sa_g, sa_b, mu, rs, x, nullptr, xb, h1, part);
    gn_reduce_kernel<<<256, 64>>>(part, mu, rs);                          // xb stats (nm1)

    // ================= Phase 2: cross linear attention =================
    wprep_kernel<<<dim3(8, BQ), 256>>>(W_cq, nm1_g, nm1_b, mu, rs, nullptr, w16, beff, 256, 256);
    mm_kernel<<<dim3(2, 64, BQ), 256, SMEM_MM>>>(w16, (size_t)256*256, beff, 1,
                                                 h1, XT, nullptr, h2, XT,
                                                 nullptr, 0, nullptr, 256, 256, 0);
    gn_stats_conv_kernel<<<BQ*32, 256>>>(c, h1, 16, mu, rs);
    wprep_kernel<<<dim3(16, BQ), 256>>>(W_ckv, nm3_g, nm3_b, mu, rs, nullptr, w16, beff, 512, 512);
    mm_kernel<<<dim3(4, 64, BQ), 256, SMEM_MM>>>(w16, (size_t)512*512, beff, 1,
                                                 h1, (size_t)512*TT, nullptr, bigh, (size_t)512*TT,
                                                 nullptr, 0, nullptr, 512, 512, 0);
    ctx_kernel<<<dim3(64, CSL), 256>>>(bigh, (size_t)512*TT, 0, 256, ctxp, cmax, csum);
    ctx_reduce_kernel<<<256, 256>>>(ctxp, cmax, csum, ctx);
    attn_out_kernel<<<dim3(64, 32), 256>>>(h2, XT, 0, ctx, h1, XT);
    wprep_kernel<<<dim3(8, 1), 256>>>(W_co, nullptr, nullptr, nullptr, nullptr, b_co,
                                      w16, beff, 256, 256);
    mm_kernel<<<dim3(2, 64, BQ), 256, SMEM_MM>>>(w16, 0, beff, 0,
                                                 h1, XT, nullptr, bigh, XT,
                                                 nullptr, 0, part, 256, 256, 0);
    gn_reduce_kernel<<<256, 64>>>(part, mu, rs);                          // co stats
    gn_add_kernel<<<16384, 256>>>(bigh, ca_g, ca_b, mu, rs, nullptr, xb, xb, h1, part);
    gn_reduce_kernel<<<256, 64>>>(part, mu, rs);                          // xb stats (nm2)

    // ================= Phase 3: SiLU MLP =================
    wprep_kernel<<<dim3(20, BQ), 256>>>(W_m1, nm2_g, nm2_b, mu, rs, b_m1, w16, beff, 640, 256);
    mm_kernel<<<dim3(5, 64, BQ), 256, SMEM_MM>>>(w16, (size_t)640*256, beff, 1,
                                                 h1, XT, nullptr, h2, (size_t)640*TT,
                                                 nullptr, 0, nullptr, 640, 256, 1 /*silu*/);
    wprep_kernel<<<dim3(8, 1), 256>>>(W_m2, nullptr, nullptr, nullptr, nullptr, b_m2,
                                      w16, beff, 256, 640);
    mm_kernel<<<dim3(2, 64, BQ), 256, SMEM_MM>>>(w16, 0, beff, 0,
                                                 h2, (size_t)640*TT, out, nullptr, XT,
                                                 xb, XT, nullptr, 256, 640, 2 /*residual*/);
}